// round 11
// baseline (speedup 1.0000x reference)
#include <cuda_runtime.h>
#include <cuda_bf16.h>
#include <cstdint>

#define BATCH 16
#define TSEQ 512
#define NH 16
#define DK 64
#define DM 1024
#define D3 3072
#define RR 1023  // 2T-1

// ---------------------------------------------------------------------------
// Scratch (allocation-free: device globals)
// ---------------------------------------------------------------------------
__device__ float g_Q[BATCH*NH*TSEQ*DK];
__device__ float g_V[BATCH*NH*TSEQ*DK];

// K and P stored directly as bf16 hi/lo (written by projection epilogues)
__device__ __nv_bfloat16 g_Kh[BATCH*NH*TSEQ*DK];
__device__ __nv_bfloat16 g_Kl[BATCH*NH*TSEQ*DK];
__device__ __nv_bfloat16 g_Ph[NH*RR*DK];
__device__ __nv_bfloat16 g_Pl[NH*RR*DK];

// bf16 hi/lo split operands for projection GEMMs
__device__ __nv_bfloat16 g_Ah[BATCH*TSEQ*DM];
__device__ __nv_bfloat16 g_Al[BATCH*TSEQ*DM];
__device__ __nv_bfloat16 g_Wh[D3*DM];      // qvk_w transposed: [3072][1024]
__device__ __nv_bfloat16 g_Wl[D3*DM];
__device__ __nv_bfloat16 g_pAh[1024*DM];   // pos padded to 1024 rows
__device__ __nv_bfloat16 g_pAl[1024*DM];
__device__ __nv_bfloat16 g_pWh[DM*DM];     // pos_w transposed
__device__ __nv_bfloat16 g_pWl[DM*DM];

// V^T bf16 hi/lo [bh][d][s]
__device__ __nv_bfloat16 g_Vth[(size_t)BATCH*NH*DK*TSEQ];
__device__ __nv_bfloat16 g_Vtl[(size_t)BATCH*NH*DK*TSEQ];

// ---------------------------------------------------------------------------
// helpers
// ---------------------------------------------------------------------------
__device__ __forceinline__ uint32_t smem_u32(const void* p) {
  uint32_t a;
  asm("{ .reg .u64 t; cvta.to.shared.u64 t, %1; cvt.u32.u64 %0, t; }" : "=r"(a) : "l"(p));
  return a;
}
__device__ __forceinline__ void cp16(uint32_t dst, const void* src) {
  asm volatile("cp.async.cg.shared.global [%0], [%1], 16;" :: "r"(dst), "l"(src));
}
__device__ __forceinline__ void cp16z(uint32_t dst, const void* src, int nbytes) {
  asm volatile("cp.async.cg.shared.global [%0], [%1], 16, %2;"
               :: "r"(dst), "l"(src), "r"(nbytes));
}
__device__ __forceinline__ void cp_commit() {
  asm volatile("cp.async.commit_group;" ::: "memory");
}
__device__ __forceinline__ void ldm4(uint32_t& r0, uint32_t& r1, uint32_t& r2,
                                     uint32_t& r3, uint32_t a) {
  asm volatile("ldmatrix.sync.aligned.m8n8.x4.shared.b16 {%0,%1,%2,%3}, [%4];"
               : "=r"(r0), "=r"(r1), "=r"(r2), "=r"(r3) : "r"(a));
}
__device__ __forceinline__ void mma_bf16(float* c, const uint32_t* a,
                                         uint32_t b0, uint32_t b1) {
  asm volatile(
      "mma.sync.aligned.m16n8k16.row.col.f32.bf16.bf16.f32 "
      "{%0,%1,%2,%3}, {%4,%5,%6,%7}, {%8,%9}, {%0,%1,%2,%3};"
      : "+f"(c[0]), "+f"(c[1]), "+f"(c[2]), "+f"(c[3])
      : "r"(a[0]), "r"(a[1]), "r"(a[2]), "r"(a[3]), "r"(b0), "r"(b1));
}
__device__ __forceinline__ uint32_t pack_bf2(float a, float b) {
  __nv_bfloat16 ha = __float2bfloat16(a), hb = __float2bfloat16(b);
  uint16_t ua = *(uint16_t*)&ha, ub = *(uint16_t*)&hb;
  return (uint32_t)ua | ((uint32_t)ub << 16);
}
__device__ __forceinline__ float bf_res(float v) {
  return v - __bfloat162float(__float2bfloat16(v));
}

// ---------------------------------------------------------------------------
// Merged prep: all 4 split/tsplit jobs in ONE launch.
// ---------------------------------------------------------------------------
__global__ void __launch_bounds__(256) prep_kernel(
    const float* __restrict__ x, const float* __restrict__ qvk_w,
    const float* __restrict__ pos, const float* __restrict__ pos_w) {
  __shared__ float t[32][33];
  const int bid = blockIdx.x;
  const int tid = threadIdx.x;
  if (bid < 2048) {  // split x
    const int n = BATCH * TSEQ * DM;
    for (int i = bid * 256 + tid; i < n; i += 2048 * 256) {
      float v = x[i];
      __nv_bfloat16 h = __float2bfloat16(v);
      g_Ah[i] = h;
      g_Al[i] = __float2bfloat16(v - __bfloat162float(h));
    }
  } else if (bid < 5120) {  // tsplit qvk_w: R=1024 C=3072
    const int r = bid - 2048;
    const int c0 = (r % 96) * 32, r0 = (r / 96) * 32;
    const int tx = tid & 31, ty = tid >> 5;
#pragma unroll
    for (int i = 0; i < 4; i++)
      t[ty + i * 8][tx] = qvk_w[(size_t)(r0 + ty + i * 8) * D3 + c0 + tx];
    __syncthreads();
#pragma unroll
    for (int i = 0; i < 4; i++) {
      float v = t[tx][ty + i * 8];
      __nv_bfloat16 h = __float2bfloat16(v);
      size_t o = (size_t)(c0 + ty + i * 8) * DM + r0 + tx;
      g_Wh[o] = h;
      g_Wl[o] = __float2bfloat16(v - __bfloat162float(h));
    }
  } else if (bid < 5376) {  // split pos (pad to 1024 rows)
    const int r = bid - 5120;
    const int n = RR * DM, ntot = 1024 * DM;
    for (int i = r * 256 + tid; i < ntot; i += 256 * 256) {
      float v = (i < n) ? pos[i] : 0.f;
      __nv_bfloat16 h = __float2bfloat16(v);
      g_pAh[i] = h;
      g_pAl[i] = __float2bfloat16(v - __bfloat162float(h));
    }
  } else {  // tsplit pos_w: R=1024 C=1024
    const int r = bid - 5376;
    const int c0 = (r % 32) * 32, r0 = (r / 32) * 32;
    const int tx = tid & 31, ty = tid >> 5;
#pragma unroll
    for (int i = 0; i < 4; i++)
      t[ty + i * 8][tx] = pos_w[(size_t)(r0 + ty + i * 8) * DM + c0 + tx];
    __syncthreads();
#pragma unroll
    for (int i = 0; i < 4; i++) {
      float v = t[tx][ty + i * 8];
      __nv_bfloat16 h = __float2bfloat16(v);
      size_t o = (size_t)(c0 + ty + i * 8) * DM + r0 + tx;
      g_pWh[o] = h;
      g_pWl[o] = __float2bfloat16(v - __bfloat162float(h));
    }
  }
}

// ---------------------------------------------------------------------------
// Merged projection GEMMs (QKV + pos), tile 128x256, 512 threads (16 warps).
// ---------------------------------------------------------------------------
#define PBUF 98304
#define OFF_AH 0
#define OFF_AL 16384
#define OFF_BH 32768
#define OFF_BL 65536
#define GSMEM (2 * PBUF)  // 196608

__global__ void __launch_bounds__(512, 1) mma_gemm_all(const float* __restrict__ bias) {
  extern __shared__ char smem[];
  const uint32_t sb = smem_u32(smem);
  const int tid = threadIdx.x;
  const int wid = tid >> 5, lane = tid & 31;
  const int bid = blockIdx.x;
  const bool qkv = bid < 768;
  int n0, m0;
  const __nv_bfloat16 *Ah, *Al, *Bh, *Bl;
  if (qkv) {
    n0 = (bid % 12) * 256; m0 = (bid / 12) * 128;
    Ah = g_Ah; Al = g_Al; Bh = g_Wh; Bl = g_Wl;
  } else {
    const int r = bid - 768;
    n0 = (r % 4) * 256; m0 = (r / 4) * 128;
    Ah = g_pAh; Al = g_pAl; Bh = g_pWh; Bl = g_pWl;
  }
  const int wm = wid & 3;
  const int wn = wid >> 2;

  const int gr = tid >> 3;
  const int gc = tid & 7;
  const uint32_t gsw = (uint32_t)((gc * 16) ^ ((gr & 7) << 4));

  const int l7 = lane & 7;
  const uint32_t xa = (uint32_t)(l7 << 4);
  const int rowA0 = wm * 32 + l7 + (((lane >> 3) & 1) << 3);
  const uint32_t kadd_a = (uint32_t)(((lane >> 4) & 1) << 4);
  const int rowB0 = wn * 64 + l7 + (((lane >> 4) & 1) << 3);
  const uint32_t kadd_b = (uint32_t)(((lane >> 3) & 1) << 4);

  float acc[2][8][4];
#pragma unroll
  for (int mt = 0; mt < 2; mt++)
#pragma unroll
    for (int nt = 0; nt < 8; nt++)
#pragma unroll
      for (int i = 0; i < 4; i++) acc[mt][nt][i] = 0.f;

  auto load_chunk = [&](int kc, int buf) {
    const int k0 = kc * 64;
    const uint32_t base = sb + buf * PBUF;
#pragma unroll
    for (int it = 0; it < 2; it++) {
      const int r = gr + it * 64;
      const uint32_t sw = (uint32_t)(r * 128) + gsw;
      const size_t asrc = (size_t)(m0 + r) * DM + k0 + gc * 8;
      cp16(base + OFF_AH + sw, Ah + asrc);
      cp16(base + OFF_AL + sw, Al + asrc);
    }
#pragma unroll
    for (int it = 0; it < 4; it++) {
      const int r = gr + it * 64;
      const uint32_t sw = (uint32_t)(r * 128) + gsw;
      const size_t bsrc = (size_t)(n0 + r) * DM + k0 + gc * 8;
      cp16(base + OFF_BH + sw, Bh + bsrc);
      cp16(base + OFF_BL + sw, Bl + bsrc);
    }
    cp_commit();
  };

  load_chunk(0, 0);

  for (int kc = 0; kc < 16; kc++) {
    if (kc + 1 < 16) {
      load_chunk(kc + 1, (kc + 1) & 1);
      asm volatile("cp.async.wait_group 1;" ::: "memory");
    } else {
      asm volatile("cp.async.wait_group 0;" ::: "memory");
    }
    __syncthreads();

    const uint32_t bb = sb + (kc & 1) * PBUF;
#pragma unroll
    for (int ks = 0; ks < 4; ks++) {
      const uint32_t kba = (uint32_t)(ks * 32);
      uint32_t ah[2][4], al[2][4];
#pragma unroll
      for (int mt = 0; mt < 2; mt++) {
        const uint32_t aoff = (uint32_t)((rowA0 + mt * 16) * 128) + ((kba + kadd_a) ^ xa);
        ldm4(ah[mt][0], ah[mt][1], ah[mt][2], ah[mt][3], bb + OFF_AH + aoff);
        ldm4(al[mt][0], al[mt][1], al[mt][2], al[mt][3], bb + OFF_AL + aoff);
      }
#pragma unroll
      for (int np = 0; np < 4; np++) {
        const uint32_t boff = (uint32_t)((rowB0 + np * 16) * 128) + ((kba + kadd_b) ^ xa);
        uint32_t bh[4], bl[4];
        ldm4(bh[0], bh[1], bh[2], bh[3], bb + OFF_BH + boff);
        ldm4(bl[0], bl[1], bl[2], bl[3], bb + OFF_BL + boff);
#pragma unroll
        for (int mt = 0; mt < 2; mt++) {
          mma_bf16(acc[mt][2 * np + 0], ah[mt], bh[0], bh[1]);
          mma_bf16(acc[mt][2 * np + 1], ah[mt], bh[2], bh[3]);
          mma_bf16(acc[mt][2 * np + 0], ah[mt], bl[0], bl[1]);
          mma_bf16(acc[mt][2 * np + 1], ah[mt], bl[2], bl[3]);
          mma_bf16(acc[mt][2 * np + 0], al[mt], bh[0], bh[1]);
          mma_bf16(acc[mt][2 * np + 1], al[mt], bh[2], bh[3]);
        }
      }
    }
    __syncthreads();
  }

  const int mrow = m0 + wm * 32 + (lane >> 2);
#pragma unroll
  for (int mt = 0; mt < 2; mt++) {
#pragma unroll
    for (int half = 0; half < 2; half++) {
      const int m = mrow + mt * 16 + half * 8;
#pragma unroll
      for (int nt = 0; nt < 8; nt++) {
        const int n = n0 + wn * 64 + nt * 8 + (lane & 3) * 2;
        float2 o;
        o.x = acc[mt][nt][half * 2 + 0];
        o.y = acc[mt][nt][half * 2 + 1];
        if (qkv) {
          o.x += bias[n];
          o.y += bias[n + 1];
          const int b = m >> 9, t = m & 511;
          const int sec = n >> 10;
          const int h = (n >> 6) & 15;
          const int d = n & 63;
          const size_t idx = ((size_t)(b * NH + h) * TSEQ + t) * DK + d;
          if (sec == 0) {
            *(float2*)(g_Q + idx) = o;
          } else if (sec == 1) {
            *(uint32_t*)&g_Kh[idx] = pack_bf2(o.x, o.y);
            *(uint32_t*)&g_Kl[idx] = pack_bf2(bf_res(o.x), bf_res(o.y));
          } else {
            *(float2*)(g_V + idx) = o;
          }
        } else {
          if (m < RR) {
            const int h = n >> 6;
            const int d = n & 63;
            const size_t idx = ((size_t)h * RR + m) * DK + d;
            *(uint32_t*)&g_Ph[idx] = pack_bf2(o.x, o.y);
            *(uint32_t*)&g_Pl[idx] = pack_bf2(bf_res(o.x), bf_res(o.y));
          }
        }
      }
    }
  }
}

// ---------------------------------------------------------------------------
// Scores (+ merged vtsplit tail): grid (4, 8, 320).
// ---------------------------------------------------------------------------
#define SC_QUH 0
#define SC_QUL 8192
#define SC_QVH 16384
#define SC_QVL 24576
#define SC_KH  32768
#define SC_KL  49152
#define SC_PH  65536
#define SC_PL  90112
#define SC_SMEM 114688
#define SC_BDW 196

__global__ void __launch_bounds__(256, 2) scores_mma(
    const float* __restrict__ pu, const float* __restrict__ pv,
    float* __restrict__ wout) {
  extern __shared__ char smem[];
  const uint32_t sb = smem_u32(smem);
  const int tid = threadIdx.x;

  if (blockIdx.z >= 256) {
    // ---- vtsplit job
    float (*t)[65] = (float(*)[65])smem;
    const int job = (blockIdx.z - 256) * 32 + blockIdx.y * 4 + blockIdx.x;
    const int vbh = job >> 3;
    const int vs0 = (job & 7) * 64;
    const float* vbase = g_V + (size_t)vbh * TSEQ * DK;
    for (int i = tid; i < 4096; i += 256) {
      const int sl = i >> 6, d = i & 63;
      t[sl][d] = vbase[(size_t)(vs0 + sl) * DK + d];
    }
    __syncthreads();
    for (int i = tid; i < 2048; i += 256) {
      const int d = i >> 5, sl = (i & 31) * 2;
      const float v0 = t[sl][d], v1 = t[sl + 1][d];
      const size_t o = ((size_t)vbh * DK + d) * TSEQ + vs0 + sl;
      *(uint32_t*)&g_Vth[o] = pack_bf2(v0, v1);
      *(uint32_t*)&g_Vtl[o] = pack_bf2(bf_res(v0), bf_res(v1));
    }
    return;
  }

  float* BDs = (float*)smem;  // aliased after mma phase
  const int wid = tid >> 5, lane = tid & 31;
  const int s0 = blockIdx.x * 128;
  const int t0 = blockIdx.y * 64;
  const int bh = blockIdx.z, h = bh & 15;
  const int relbase = s0 - t0 + 448;

  // ---- cp.async K tiles (128 rows x 128B, hi+lo)
  {
    const __nv_bfloat16* Kh = g_Kh + ((size_t)bh * TSEQ + s0) * DK;
    const __nv_bfloat16* Kl = g_Kl + ((size_t)bh * TSEQ + s0) * DK;
#pragma unroll
    for (int it = 0; it < 4; it++) {
      const int idx = tid + it * 256;
      const int row = idx >> 3, ch = idx & 7;
      const uint32_t sw = (uint32_t)(row * 128) + ((uint32_t)(ch * 16) ^ ((uint32_t)(row & 7) << 4));
      cp16(sb + SC_KH + sw, Kh + row * DK + ch * 8);
      cp16(sb + SC_KL + sw, Kl + row * DK + ch * 8);
    }
  }
  // ---- cp.async P band (192 rows x 128B, hi+lo), zero-fill out of range
  {
    const __nv_bfloat16* Ph = g_Ph + (size_t)h * RR * DK;
    const __nv_bfloat16* Pl = g_Pl + (size_t)h * RR * DK;
#pragma unroll
    for (int it = 0; it < 6; it++) {
      const int idx = tid + it * 256;
      const int row = idx >> 3, ch = idx & 7;
      const int r = relbase + row;
      const int rc = r < 0 ? 0 : (r >= RR ? RR - 1 : r);
      const int ok = (r >= 0 && r < RR) ? 16 : 0;
      const uint32_t sw = (uint32_t)(row * 128) + ((uint32_t)(ch * 16) ^ ((uint32_t)(row & 7) << 4));
      cp16z(sb + SC_PH + sw, Ph + (size_t)rc * DK + ch * 8, ok);
      cp16z(sb + SC_PL + sw, Pl + (size_t)rc * DK + ch * 8, ok);
    }
  }
  cp_commit();

  // ---- Q fill: fp32 + posu/posv, convert to bf16 hi/lo (overlaps cp.async)
  {
    const int frow = tid >> 4;
    const int c4 = (tid & 15) * 4;
    const uint32_t cb = (uint32_t)(c4 * 2);
    const float4 pu4 = *(const float4*)(pu + h * 64 + c4);
    const float4 pv4 = *(const float4*)(pv + h * 64 + c4);
    const float* qb = g_Q + ((size_t)bh * TSEQ + t0) * DK;
#pragma unroll
    for (int it = 0; it < 4; it++) {
      const int row = frow + it * 16;
      const float4 q = *(const float4*)(qb + (size_t)row * DK + c4);
      const uint32_t sw = (uint32_t)(row * 128) + (cb ^ ((uint32_t)(row & 7) << 4));
      float ux = q.x + pu4.x, uy = q.y + pu4.y, uz = q.z + pu4.z, uw = q.w + pu4.w;
      float vx = q.x + pv4.x, vy = q.y + pv4.y, vz = q.z + pv4.z, vw = q.w + pv4.w;
      uint2 hh, ll;
      hh.x = pack_bf2(ux, uy); hh.y = pack_bf2(uz, uw);
      ll.x = pack_bf2(bf_res(ux), bf_res(uy));
      ll.y = pack_bf2(bf_res(uz), bf_res(uw));
      *(uint2*)(smem + SC_QUH + sw) = hh;
      *(uint2*)(smem + SC_QUL + sw) = ll;
      hh.x = pack_bf2(vx, vy); hh.y = pack_bf2(vz, vw);
      ll.x = pack_bf2(bf_res(vx), bf_res(vy));
      ll.y = pack_bf2(bf_res(vz), bf_res(vw));
      *(uint2*)(smem + SC_QVH + sw) = hh;
      *(uint2*)(smem + SC_QVL + sw) = ll;
    }
  }
  asm volatile("cp.async.wait_group 0;" ::: "memory");
  __syncthreads();

  // ---- mma: 8 warps = 4 (t) x 2 (s/band)
  const int wm = wid & 3;
  const int wn = wid >> 2;
  const int l7 = lane & 7;
  const uint32_t xa = (uint32_t)(l7 << 4);
  const int rowA = wm * 16 + l7 + (((lane >> 3) & 1) << 3);
  const uint32_t kadd_a = (uint32_t)(((lane >> 4) & 1) << 4);
  const int rbB = l7 + (((lane >> 4) & 1) << 3);
  const uint32_t kadd_b = (uint32_t)(((lane >> 3) & 1) << 4);

  float ac[8][4], bd[12][4];
#pragma unroll
  for (int nt = 0; nt < 8; nt++)
#pragma unroll
    for (int i = 0; i < 4; i++) ac[nt][i] = 0.f;
#pragma unroll
  for (int nt = 0; nt < 12; nt++)
#pragma unroll
    for (int i = 0; i < 4; i++) bd[nt][i] = 0.f;

#pragma unroll
  for (int ks = 0; ks < 4; ks++) {
    const uint32_t kba = (uint32_t)(ks * 32);
    const uint32_t aoff = (uint32_t)(rowA * 128) + ((kba + kadd_a) ^ xa);
    uint32_t quh[4], qul[4], qvh[4], qvl[4];
    ldm4(quh[0], quh[1], quh[2], quh[3], sb + SC_QUH + aoff);
    ldm4(qul[0], qul[1], qul[2], qul[3], sb + SC_QUL + aoff);
    ldm4(qvh[0], qvh[1], qvh[2], qvh[3], sb + SC_QVH + aoff);
    ldm4(qvl[0], qvl[1], qvl[2], qvl[3], sb + SC_QVL + aoff);
#pragma unroll
    for (int np = 0; np < 4; np++) {
      const int rowB = wn * 64 + np * 16 + rbB;
      const uint32_t boff = (uint32_t)(rowB * 128) + ((kba + kadd_b) ^ xa);
      uint32_t kh[4], kl[4];
      ldm4(kh[0], kh[1], kh[2], kh[3], sb + SC_KH + boff);
      ldm4(kl[0], kl[1], kl[2], kl[3], sb + SC_KL + boff);
      mma_bf16(ac[2 * np + 0], quh, kh[0], kh[1]);
      mma_bf16(ac[2 * np + 1], quh, kh[2], kh[3]);
      mma_bf16(ac[2 * np + 0], quh, kl[0], kl[1]);
      mma_bf16(ac[2 * np + 1], quh, kl[2], kl[3]);
      mma_bf16(ac[2 * np + 0], qul, kh[0], kh[1]);
      mma_bf16(ac[2 * np + 1], qul, kh[2], kh[3]);
    }
#pragma unroll
    for (int np = 0; np < 6; np++) {
      const int rowB = wn * 96 + np * 16 + rbB;
      const uint32_t boff = (uint32_t)(rowB * 128) + ((kba + kadd_b) ^ xa);
      uint32_t ph[4], pl[4];
      ldm4(ph[0], ph[1], ph[2], ph[3], sb + SC_PH + boff);
      ldm4(pl[0], pl[1], pl[2], pl[3], sb + SC_PL + boff);
      mma_bf16(bd[2 * np + 0], qvh, ph[0], ph[1]);
      mma_bf16(bd[2 * np + 1], qvh, ph[2], ph[3]);
      mma_bf16(bd[2 * np + 0], qvh, pl[0], pl[1]);
      mma_bf16(bd[2 * np + 1], qvh, pl[2], pl[3]);
      mma_bf16(bd[2 * np + 0], qvl, ph[0], ph[1]);
      mma_bf16(bd[2 * np + 1], qvl, ph[2], ph[3]);
    }
  }
  __syncthreads();  // operand smem dead; safe to alias with BDs

  // ---- BD -> smem (stride 196 floats)
  const int r0w = wm * 16 + (lane >> 2);
#pragma unroll
  for (int nt = 0; nt < 12; nt++) {
    const int col = wn * 96 + nt * 8 + (lane & 3) * 2;
    *(float2*)&BDs[r0w * SC_BDW + col] = make_float2(bd[nt][0], bd[nt][1]);
    *(float2*)&BDs[(r0w + 8) * SC_BDW + col] = make_float2(bd[nt][2], bd[nt][3]);
  }
  __syncthreads();

  // ---- epilogue: out = (AC + shifted BD) / 8
  float* wbase = wout + ((size_t)bh * TSEQ + t0) * TSEQ + s0;
#pragma unroll
  for (int nt = 0; nt < 8; nt++) {
    const int col = wn * 64 + nt * 8 + (lane & 3) * 2;
#pragma unroll
    for (int half = 0; half < 2; half++) {
      const int row = r0w + half * 8;
      const int bdi = row * SC_BDW + col - row + 63;
      float2 o;
      o.x = (ac[nt][half * 2 + 0] + BDs[bdi]) * 0.125f;
      o.y = (ac[nt][half * 2 + 1] + BDs[bdi + 1]) * 0.125f;
      *(float2*)(wbase + (size_t)row * TSEQ + col) = o;
    }
  }
}

// ---------------------------------------------------------------------------
// Fused softmax + context, occupancy-safe (104KB smem, 2 CTAs/SM):
// per CTA (t-tile 32, bh): cp.async raw 32x512 -> smem, 8-warp softmax,
// write normalized weights, then 8 s-chunks: convert W tile + mma vs V^T.
// ---------------------------------------------------------------------------
#define SX_RAW 0        // 32 x 512 f32 = 65536
#define SX_WH  65536    // 4096
#define SX_WL  69632    // 4096
#define SX_V   73728    // 2 bufs x (hi 8192 + lo 8192) = 32768
#define SX_SMEM 106496

__global__ void __launch_bounds__(256, 2) smctx_kernel(
    float* __restrict__ wts, float* __restrict__ ctx) {
  extern __shared__ char smem[];
  float* RAW = (float*)smem;
  const uint32_t sb = smem_u32(smem);
  const int tid = threadIdx.x;
  const int wid = tid >> 5, lane = tid & 31;
  const int t0 = blockIdx.x * 32;
  const int bh = blockIdx.y;
  const int b = bh >> 4, h = bh & 15;
  float* wbase = wts + ((size_t)bh * TSEQ + t0) * TSEQ;
  const __nv_bfloat16* Vh = g_Vth + (size_t)bh * DK * TSEQ;
  const __nv_bfloat16* Vl = g_Vtl + (size_t)bh * DK * TSEQ;

  auto load_v = [&](int kc, int buf) {
    const int k0 = kc * 64;
    const uint32_t vb = sb + SX_V + (uint32_t)(buf * 16384);
#pragma unroll
    for (int it = 0; it < 2; it++) {
      const int idx = tid + it * 256;
      const int row = idx >> 3, ch = idx & 7;
      const uint32_t sw = (uint32_t)(row * 128) + ((uint32_t)(ch * 16) ^ ((uint32_t)(row & 7) << 4));
      cp16(vb + sw, Vh + (size_t)row * TSEQ + k0 + ch * 8);
      cp16(vb + 8192 + sw, Vl + (size_t)row * TSEQ + k0 + ch * 8);
    }
  };

  // Phase A: raw scores 32x512 (f32) + V chunk 0
#pragma unroll
  for (int it = 0; it < 16; it++) {
    const int idx = tid + it * 256;
    const int r = idx >> 7, seg = idx & 127;
    cp16(sb + SX_RAW + (uint32_t)(r * 2048 + seg * 16),
         wbase + (size_t)r * TSEQ + seg * 4);
  }
  load_v(0, 0);
  cp_commit();
  asm volatile("cp.async.wait_group 0;" ::: "memory");
  __syncthreads();

  // Phase B: softmax (each warp: 4 rows, strided)
  for (int r = wid; r < 32; r += 8) {
    float* row = &RAW[r * 512];
    float vals[16];
    float m = -1e30f;
#pragma unroll
    for (int k = 0; k < 16; k++) { vals[k] = row[lane + 32 * k]; m = fmaxf(m, vals[k]); }
#pragma unroll
    for (int off = 16; off > 0; off >>= 1)
      m = fmaxf(m, __shfl_xor_sync(0xffffffffu, m, off));
    float s = 0.f;
#pragma unroll
    for (int k = 0; k < 16; k++) { vals[k] = __expf(vals[k] - m); s += vals[k]; }
#pragma unroll
    for (int off = 16; off > 0; off >>= 1)
      s += __shfl_xor_sync(0xffffffffu, s, off);
    const float inv = 1.0f / s;
#pragma unroll
    for (int k = 0; k < 16; k++) row[lane + 32 * k] = vals[k] * inv;
  }
  __syncthreads();

  // write normalized weights (output)
#pragma unroll
  for (int it = 0; it < 16; it++) {
    const int idx = tid + it * 256;
    const int r = idx >> 7, c4 = (idx & 127) * 4;
    *(float4*)(wbase + (size_t)r * TSEQ + c4) = *(float4*)&RAW[r * 512 + c4];
  }

  // Phase C: ctx = W @ V^T, 8 chunks of s=64
  const int wm = wid & 1;   // 16 t-rows each
  const int wn = wid >> 1;  // 16 d-cols each (0..3)
  const int l7 = lane & 7;
  const uint32_t xa = (uint32_t)(l7 << 4);
  const int rowA = wm * 16 + l7 + (((lane >> 3) & 1) << 3);
  const uint32_t kadd_a = (uint32_t)(((lane >> 4) & 1) << 4);
  const int rowB = wn * 16 + l7 + (((lane >> 4) & 1) << 3);
  const uint32_t kadd_b = (uint32_t)(((lane >> 3) & 1) << 4);

  float acc[2][4];
#pragma unroll
  for (int nt = 0; nt < 2; nt++)
#pragma unroll
    for (int i = 0; i < 4; i++) acc[nt][i] = 0.f;

  for (int kc = 0; kc < 8; kc++) {
    if (kc > 0) asm volatile("cp.async.wait_group 0;" ::: "memory");
    __syncthreads();  // prev mma done with WH/WL; V chunk visible

    // convert W tile (32 x 64) f32 -> bf16 hi/lo swizzled
#pragma unroll
    for (int it = 0; it < 2; it++) {
      const int idx = tid + it * 256;
      const int r = idx >> 4, q = idx & 15;
      const float4 wv = *(const float4*)&RAW[r * 512 + kc * 64 + q * 4];
      const uint32_t sw = (uint32_t)(r * 128) + ((uint32_t)(q * 8) ^ ((uint32_t)(r & 7) << 4));
      uint2 hh, ll;
      hh.x = pack_bf2(wv.x, wv.y); hh.y = pack_bf2(wv.z, wv.w);
      ll.x = pack_bf2(bf_res(wv.x), bf_res(wv.y));
      ll.y = pack_bf2(bf_res(wv.z), bf_res(wv.w));
      *(uint2*)(smem + SX_WH + sw) = hh;
      *(uint2*)(smem + SX_WL + sw) = ll;
    }
    __syncthreads();

    if (kc + 1 < 8) { load_v(kc + 1, (kc + 1) & 1); cp_commit(); }

    const uint32_t vb = sb + SX_V + (uint32_t)((kc & 1) * 16384);
#pragma unroll
    for (int ks = 0; ks < 4; ks++) {
      const uint32_t kba = (uint32_t)(ks * 32);
      const uint32_t aoff = (uint32_t)(rowA * 128) + ((kba + kadd_a) ^ xa);
      uint32_t ah[4], al[4];
      ldm4(ah[0], ah[1], ah[2], ah[3], sb + SX_WH + aoff);
      ldm4(al[0], al[1], al[2], al[3], sb + SX_WL + aoff);
      const uint32_t boff = (uint32_t)(rowB * 128) + ((kba + kadd_b) ^ xa);
      uint32_t vhh[4], vll[4];
      ldm4(vhh[0], vhh[1], vhh[2], vhh[3], vb + boff);
      ldm4(vll[0], vll[1], vll[2], vll[3], vb + 8192 + boff);
      mma_bf16(acc[0], ah, vhh[0], vhh[1]);
      mma_bf16(acc[1], ah, vhh[2], vhh[3]);
      mma_bf16(acc[0], ah, vll[0], vll[1]);
      mma_bf16(acc[1], ah, vll[2], vll[3]);
      mma_bf16(acc[0], al, vhh[0], vhh[1]);
      mma_bf16(acc[1], al, vhh[2], vhh[3]);
    }
  }

  // epilogue
  const int mrow = t0 + wm * 16 + (lane >> 2);
#pragma unroll
  for (int half = 0; half < 2; half++) {
    const int t = mrow + half * 8;
#pragma unroll
    for (int nt = 0; nt < 2; nt++) {
      const int d = wn * 16 + nt * 8 + (lane & 3) * 2;
      float2 o;
      o.x = acc[nt][half * 2 + 0];
      o.y = acc[nt][half * 2 + 1];
      *(float2*)(ctx + ((size_t)b * TSEQ + t) * DM + h * DK + d) = o;
    }
  }
}

// ---------------------------------------------------------------------------
// Launch
// ---------------------------------------------------------------------------
extern "C" void kernel_launch(void* const* d_in, const int* in_sizes, int n_in,
                              void* d_out, int out_size) {
  const float* x     = (const float*)d_in[0];
  const float* pos   = (const float*)d_in[2];
  const float* qvk_w = (const float*)d_in[3];
  const float* qvk_b = (const float*)d_in[4];
  const float* pos_w = (const float*)d_in[5];
  const float* posu  = (const float*)d_in[6];
  const float* posv  = (const float*)d_in[7];

  float* ctx = (float*)d_out;
  float* wts = (float*)d_out + (size_t)BATCH * TSEQ * DM;

  // 0) merged prep (all bf16 hi/lo splits)
  prep_kernel<<<6400, 256>>>(x, qvk_w, pos, pos_w);

  // 1) merged projection GEMMs, tile 128x256 (QKV 768 + pos 32 tiles)
  cudaFuncSetAttribute(mma_gemm_all, cudaFuncAttributeMaxDynamicSharedMemorySize,
                       GSMEM);
  mma_gemm_all<<<800, 512, GSMEM>>>(qvk_b);

  // 2) scores (+ merged vtsplit tail) -> weights region
  cudaFuncSetAttribute(scores_mma, cudaFuncAttributeMaxDynamicSharedMemorySize,
                       SC_SMEM);
  scores_mma<<<dim3(4, 8, 320), 256, SC_SMEM>>>(posu, posv, wts);

  // 3+4) fused softmax + context (2 CTAs/SM)
  cudaFuncSetAttribute(smctx_kernel, cudaFuncAttributeMaxDynamicSharedMemorySize,
                       SX_SMEM);
  smctx_kernel<<<dim3(TSEQ / 32, BATCH * NH), 256, SX_SMEM>>>(wts, ctx);
}

// round 12
// speedup vs baseline: 1.0162x; 1.0162x over previous
#include <cuda_runtime.h>
#include <cuda_bf16.h>
#include <cstdint>

#define BATCH 16
#define TSEQ 512
#define NH 16
#define DK 64
#define DM 1024
#define D3 3072
#define RR 1023  // 2T-1

// ---------------------------------------------------------------------------
// Scratch (allocation-free: device globals)
// ---------------------------------------------------------------------------
__device__ float g_Q[BATCH*NH*TSEQ*DK];
__device__ float g_V[BATCH*NH*TSEQ*DK];

// K and P stored directly as bf16 hi/lo (written by projection epilogues)
__device__ __nv_bfloat16 g_Kh[BATCH*NH*TSEQ*DK];
__device__ __nv_bfloat16 g_Kl[BATCH*NH*TSEQ*DK];
__device__ __nv_bfloat16 g_Ph[NH*RR*DK];
__device__ __nv_bfloat16 g_Pl[NH*RR*DK];

// bf16 hi/lo split operands for projection GEMMs
__device__ __nv_bfloat16 g_Ah[BATCH*TSEQ*DM];
__device__ __nv_bfloat16 g_Al[BATCH*TSEQ*DM];
__device__ __nv_bfloat16 g_Wh[D3*DM];      // qvk_w transposed: [3072][1024]
__device__ __nv_bfloat16 g_Wl[D3*DM];
__device__ __nv_bfloat16 g_pAh[1024*DM];   // pos padded to 1024 rows
__device__ __nv_bfloat16 g_pAl[1024*DM];
__device__ __nv_bfloat16 g_pWh[DM*DM];     // pos_w transposed
__device__ __nv_bfloat16 g_pWl[DM*DM];

// V^T bf16 hi/lo [bh][d][s]
__device__ __nv_bfloat16 g_Vth[(size_t)BATCH*NH*DK*TSEQ];
__device__ __nv_bfloat16 g_Vtl[(size_t)BATCH*NH*DK*TSEQ];

// ---------------------------------------------------------------------------
// helpers
// ---------------------------------------------------------------------------
__device__ __forceinline__ uint32_t smem_u32(const void* p) {
  uint32_t a;
  asm("{ .reg .u64 t; cvta.to.shared.u64 t, %1; cvt.u32.u64 %0, t; }" : "=r"(a) : "l"(p));
  return a;
}
__device__ __forceinline__ void cp16(uint32_t dst, const void* src) {
  asm volatile("cp.async.cg.shared.global [%0], [%1], 16;" :: "r"(dst), "l"(src));
}
__device__ __forceinline__ void cp16z(uint32_t dst, const void* src, int nbytes) {
  asm volatile("cp.async.cg.shared.global [%0], [%1], 16, %2;"
               :: "r"(dst), "l"(src), "r"(nbytes));
}
__device__ __forceinline__ void cp_commit() {
  asm volatile("cp.async.commit_group;" ::: "memory");
}
__device__ __forceinline__ void ldm4(uint32_t& r0, uint32_t& r1, uint32_t& r2,
                                     uint32_t& r3, uint32_t a) {
  asm volatile("ldmatrix.sync.aligned.m8n8.x4.shared.b16 {%0,%1,%2,%3}, [%4];"
               : "=r"(r0), "=r"(r1), "=r"(r2), "=r"(r3) : "r"(a));
}
__device__ __forceinline__ void mma_bf16(float* c, const uint32_t* a,
                                         uint32_t b0, uint32_t b1) {
  asm volatile(
      "mma.sync.aligned.m16n8k16.row.col.f32.bf16.bf16.f32 "
      "{%0,%1,%2,%3}, {%4,%5,%6,%7}, {%8,%9}, {%0,%1,%2,%3};"
      : "+f"(c[0]), "+f"(c[1]), "+f"(c[2]), "+f"(c[3])
      : "r"(a[0]), "r"(a[1]), "r"(a[2]), "r"(a[3]), "r"(b0), "r"(b1));
}
__device__ __forceinline__ uint32_t pack_bf2(float a, float b) {
  __nv_bfloat16 ha = __float2bfloat16(a), hb = __float2bfloat16(b);
  uint16_t ua = *(uint16_t*)&ha, ub = *(uint16_t*)&hb;
  return (uint32_t)ua | ((uint32_t)ub << 16);
}
__device__ __forceinline__ float bf_res(float v) {
  return v - __bfloat162float(__float2bfloat16(v));
}

// ---------------------------------------------------------------------------
// Merged prep: all 4 split/tsplit jobs in ONE launch.
// ---------------------------------------------------------------------------
__global__ void __launch_bounds__(256) prep_kernel(
    const float* __restrict__ x, const float* __restrict__ qvk_w,
    const float* __restrict__ pos, const float* __restrict__ pos_w) {
  __shared__ float t[32][33];
  const int bid = blockIdx.x;
  const int tid = threadIdx.x;
  if (bid < 2048) {  // split x
    const int n = BATCH * TSEQ * DM;
    for (int i = bid * 256 + tid; i < n; i += 2048 * 256) {
      float v = x[i];
      __nv_bfloat16 h = __float2bfloat16(v);
      g_Ah[i] = h;
      g_Al[i] = __float2bfloat16(v - __bfloat162float(h));
    }
  } else if (bid < 5120) {  // tsplit qvk_w: R=1024 C=3072
    const int r = bid - 2048;
    const int c0 = (r % 96) * 32, r0 = (r / 96) * 32;
    const int tx = tid & 31, ty = tid >> 5;
#pragma unroll
    for (int i = 0; i < 4; i++)
      t[ty + i * 8][tx] = qvk_w[(size_t)(r0 + ty + i * 8) * D3 + c0 + tx];
    __syncthreads();
#pragma unroll
    for (int i = 0; i < 4; i++) {
      float v = t[tx][ty + i * 8];
      __nv_bfloat16 h = __float2bfloat16(v);
      size_t o = (size_t)(c0 + ty + i * 8) * DM + r0 + tx;
      g_Wh[o] = h;
      g_Wl[o] = __float2bfloat16(v - __bfloat162float(h));
    }
  } else if (bid < 5376) {  // split pos (pad to 1024 rows)
    const int r = bid - 5120;
    const int n = RR * DM, ntot = 1024 * DM;
    for (int i = r * 256 + tid; i < ntot; i += 256 * 256) {
      float v = (i < n) ? pos[i] : 0.f;
      __nv_bfloat16 h = __float2bfloat16(v);
      g_pAh[i] = h;
      g_pAl[i] = __float2bfloat16(v - __bfloat162float(h));
    }
  } else {  // tsplit pos_w: R=1024 C=1024
    const int r = bid - 5376;
    const int c0 = (r % 32) * 32, r0 = (r / 32) * 32;
    const int tx = tid & 31, ty = tid >> 5;
#pragma unroll
    for (int i = 0; i < 4; i++)
      t[ty + i * 8][tx] = pos_w[(size_t)(r0 + ty + i * 8) * DM + c0 + tx];
    __syncthreads();
#pragma unroll
    for (int i = 0; i < 4; i++) {
      float v = t[tx][ty + i * 8];
      __nv_bfloat16 h = __float2bfloat16(v);
      size_t o = (size_t)(c0 + ty + i * 8) * DM + r0 + tx;
      g_pWh[o] = h;
      g_pWl[o] = __float2bfloat16(v - __bfloat162float(h));
    }
  }
}

// ---------------------------------------------------------------------------
// Merged projection GEMMs (QKV + pos), tile 128x256, 512 threads (16 warps).
// ---------------------------------------------------------------------------
#define PBUF 98304
#define OFF_AH 0
#define OFF_AL 16384
#define OFF_BH 32768
#define OFF_BL 65536
#define GSMEM (2 * PBUF)  // 196608

__global__ void __launch_bounds__(512, 1) mma_gemm_all(const float* __restrict__ bias) {
  extern __shared__ char smem[];
  const uint32_t sb = smem_u32(smem);
  const int tid = threadIdx.x;
  const int wid = tid >> 5, lane = tid & 31;
  const int bid = blockIdx.x;
  const bool qkv = bid < 768;
  int n0, m0;
  const __nv_bfloat16 *Ah, *Al, *Bh, *Bl;
  if (qkv) {
    n0 = (bid % 12) * 256; m0 = (bid / 12) * 128;
    Ah = g_Ah; Al = g_Al; Bh = g_Wh; Bl = g_Wl;
  } else {
    const int r = bid - 768;
    n0 = (r % 4) * 256; m0 = (r / 4) * 128;
    Ah = g_pAh; Al = g_pAl; Bh = g_pWh; Bl = g_pWl;
  }
  const int wm = wid & 3;
  const int wn = wid >> 2;

  const int gr = tid >> 3;
  const int gc = tid & 7;
  const uint32_t gsw = (uint32_t)((gc * 16) ^ ((gr & 7) << 4));

  const int l7 = lane & 7;
  const uint32_t xa = (uint32_t)(l7 << 4);
  const int rowA0 = wm * 32 + l7 + (((lane >> 3) & 1) << 3);
  const uint32_t kadd_a = (uint32_t)(((lane >> 4) & 1) << 4);
  const int rowB0 = wn * 64 + l7 + (((lane >> 4) & 1) << 3);
  const uint32_t kadd_b = (uint32_t)(((lane >> 3) & 1) << 4);

  float acc[2][8][4];
#pragma unroll
  for (int mt = 0; mt < 2; mt++)
#pragma unroll
    for (int nt = 0; nt < 8; nt++)
#pragma unroll
      for (int i = 0; i < 4; i++) acc[mt][nt][i] = 0.f;

  auto load_chunk = [&](int kc, int buf) {
    const int k0 = kc * 64;
    const uint32_t base = sb + buf * PBUF;
#pragma unroll
    for (int it = 0; it < 2; it++) {
      const int r = gr + it * 64;
      const uint32_t sw = (uint32_t)(r * 128) + gsw;
      const size_t asrc = (size_t)(m0 + r) * DM + k0 + gc * 8;
      cp16(base + OFF_AH + sw, Ah + asrc);
      cp16(base + OFF_AL + sw, Al + asrc);
    }
#pragma unroll
    for (int it = 0; it < 4; it++) {
      const int r = gr + it * 64;
      const uint32_t sw = (uint32_t)(r * 128) + gsw;
      const size_t bsrc = (size_t)(n0 + r) * DM + k0 + gc * 8;
      cp16(base + OFF_BH + sw, Bh + bsrc);
      cp16(base + OFF_BL + sw, Bl + bsrc);
    }
    cp_commit();
  };

  load_chunk(0, 0);

  for (int kc = 0; kc < 16; kc++) {
    if (kc + 1 < 16) {
      load_chunk(kc + 1, (kc + 1) & 1);
      asm volatile("cp.async.wait_group 1;" ::: "memory");
    } else {
      asm volatile("cp.async.wait_group 0;" ::: "memory");
    }
    __syncthreads();

    const uint32_t bb = sb + (kc & 1) * PBUF;
#pragma unroll
    for (int ks = 0; ks < 4; ks++) {
      const uint32_t kba = (uint32_t)(ks * 32);
      uint32_t ah[2][4], al[2][4];
#pragma unroll
      for (int mt = 0; mt < 2; mt++) {
        const uint32_t aoff = (uint32_t)((rowA0 + mt * 16) * 128) + ((kba + kadd_a) ^ xa);
        ldm4(ah[mt][0], ah[mt][1], ah[mt][2], ah[mt][3], bb + OFF_AH + aoff);
        ldm4(al[mt][0], al[mt][1], al[mt][2], al[mt][3], bb + OFF_AL + aoff);
      }
#pragma unroll
      for (int np = 0; np < 4; np++) {
        const uint32_t boff = (uint32_t)((rowB0 + np * 16) * 128) + ((kba + kadd_b) ^ xa);
        uint32_t bh[4], bl[4];
        ldm4(bh[0], bh[1], bh[2], bh[3], bb + OFF_BH + boff);
        ldm4(bl[0], bl[1], bl[2], bl[3], bb + OFF_BL + boff);
#pragma unroll
        for (int mt = 0; mt < 2; mt++) {
          mma_bf16(acc[mt][2 * np + 0], ah[mt], bh[0], bh[1]);
          mma_bf16(acc[mt][2 * np + 1], ah[mt], bh[2], bh[3]);
          mma_bf16(acc[mt][2 * np + 0], ah[mt], bl[0], bl[1]);
          mma_bf16(acc[mt][2 * np + 1], ah[mt], bl[2], bl[3]);
          mma_bf16(acc[mt][2 * np + 0], al[mt], bh[0], bh[1]);
          mma_bf16(acc[mt][2 * np + 1], al[mt], bh[2], bh[3]);
        }
      }
    }
    __syncthreads();
  }

  const int mrow = m0 + wm * 32 + (lane >> 2);
#pragma unroll
  for (int mt = 0; mt < 2; mt++) {
#pragma unroll
    for (int half = 0; half < 2; half++) {
      const int m = mrow + mt * 16 + half * 8;
#pragma unroll
      for (int nt = 0; nt < 8; nt++) {
        const int n = n0 + wn * 64 + nt * 8 + (lane & 3) * 2;
        float2 o;
        o.x = acc[mt][nt][half * 2 + 0];
        o.y = acc[mt][nt][half * 2 + 1];
        if (qkv) {
          o.x += bias[n];
          o.y += bias[n + 1];
          const int b = m >> 9, t = m & 511;
          const int sec = n >> 10;
          const int h = (n >> 6) & 15;
          const int d = n & 63;
          const size_t idx = ((size_t)(b * NH + h) * TSEQ + t) * DK + d;
          if (sec == 0) {
            *(float2*)(g_Q + idx) = o;
          } else if (sec == 1) {
            *(uint32_t*)&g_Kh[idx] = pack_bf2(o.x, o.y);
            *(uint32_t*)&g_Kl[idx] = pack_bf2(bf_res(o.x), bf_res(o.y));
          } else {
            *(float2*)(g_V + idx) = o;
          }
        } else {
          if (m < RR) {
            const int h = n >> 6;
            const int d = n & 63;
            const size_t idx = ((size_t)h * RR + m) * DK + d;
            *(uint32_t*)&g_Ph[idx] = pack_bf2(o.x, o.y);
            *(uint32_t*)&g_Pl[idx] = pack_bf2(bf_res(o.x), bf_res(o.y));
          }
        }
      }
    }
  }
}

// ---------------------------------------------------------------------------
// Scores (+ merged vtsplit tail): grid (4, 8, 320).
// ---------------------------------------------------------------------------
#define SC_QUH 0
#define SC_QUL 8192
#define SC_QVH 16384
#define SC_QVL 24576
#define SC_KH  32768
#define SC_KL  49152
#define SC_PH  65536
#define SC_PL  90112
#define SC_SMEM 114688
#define SC_BDW 196

__global__ void __launch_bounds__(256, 2) scores_mma(
    const float* __restrict__ pu, const float* __restrict__ pv,
    float* __restrict__ wout) {
  extern __shared__ char smem[];
  const uint32_t sb = smem_u32(smem);
  const int tid = threadIdx.x;

  if (blockIdx.z >= 256) {
    // ---- vtsplit job
    float (*t)[65] = (float(*)[65])smem;
    const int job = (blockIdx.z - 256) * 32 + blockIdx.y * 4 + blockIdx.x;
    const int vbh = job >> 3;
    const int vs0 = (job & 7) * 64;
    const float* vbase = g_V + (size_t)vbh * TSEQ * DK;
    for (int i = tid; i < 4096; i += 256) {
      const int sl = i >> 6, d = i & 63;
      t[sl][d] = vbase[(size_t)(vs0 + sl) * DK + d];
    }
    __syncthreads();
    for (int i = tid; i < 2048; i += 256) {
      const int d = i >> 5, sl = (i & 31) * 2;
      const float v0 = t[sl][d], v1 = t[sl + 1][d];
      const size_t o = ((size_t)vbh * DK + d) * TSEQ + vs0 + sl;
      *(uint32_t*)&g_Vth[o] = pack_bf2(v0, v1);
      *(uint32_t*)&g_Vtl[o] = pack_bf2(bf_res(v0), bf_res(v1));
    }
    return;
  }

  float* BDs = (float*)smem;  // aliased after mma phase
  const int wid = tid >> 5, lane = tid & 31;
  const int s0 = blockIdx.x * 128;
  const int t0 = blockIdx.y * 64;
  const int bh = blockIdx.z, h = bh & 15;
  const int relbase = s0 - t0 + 448;

  // ---- cp.async K tiles (128 rows x 128B, hi+lo)
  {
    const __nv_bfloat16* Kh = g_Kh + ((size_t)bh * TSEQ + s0) * DK;
    const __nv_bfloat16* Kl = g_Kl + ((size_t)bh * TSEQ + s0) * DK;
#pragma unroll
    for (int it = 0; it < 4; it++) {
      const int idx = tid + it * 256;
      const int row = idx >> 3, ch = idx & 7;
      const uint32_t sw = (uint32_t)(row * 128) + ((uint32_t)(ch * 16) ^ ((uint32_t)(row & 7) << 4));
      cp16(sb + SC_KH + sw, Kh + row * DK + ch * 8);
      cp16(sb + SC_KL + sw, Kl + row * DK + ch * 8);
    }
  }
  // ---- cp.async P band (192 rows x 128B, hi+lo), zero-fill out of range
  {
    const __nv_bfloat16* Ph = g_Ph + (size_t)h * RR * DK;
    const __nv_bfloat16* Pl = g_Pl + (size_t)h * RR * DK;
#pragma unroll
    for (int it = 0; it < 6; it++) {
      const int idx = tid + it * 256;
      const int row = idx >> 3, ch = idx & 7;
      const int r = relbase + row;
      const int rc = r < 0 ? 0 : (r >= RR ? RR - 1 : r);
      const int ok = (r >= 0 && r < RR) ? 16 : 0;
      const uint32_t sw = (uint32_t)(row * 128) + ((uint32_t)(ch * 16) ^ ((uint32_t)(row & 7) << 4));
      cp16z(sb + SC_PH + sw, Ph + (size_t)rc * DK + ch * 8, ok);
      cp16z(sb + SC_PL + sw, Pl + (size_t)rc * DK + ch * 8, ok);
    }
  }
  cp_commit();

  // ---- Q fill: fp32 + posu/posv, convert to bf16 hi/lo (overlaps cp.async)
  {
    const int frow = tid >> 4;
    const int c4 = (tid & 15) * 4;
    const uint32_t cb = (uint32_t)(c4 * 2);
    const float4 pu4 = *(const float4*)(pu + h * 64 + c4);
    const float4 pv4 = *(const float4*)(pv + h * 64 + c4);
    const float* qb = g_Q + ((size_t)bh * TSEQ + t0) * DK;
#pragma unroll
    for (int it = 0; it < 4; it++) {
      const int row = frow + it * 16;
      const float4 q = *(const float4*)(qb + (size_t)row * DK + c4);
      const uint32_t sw = (uint32_t)(row * 128) + (cb ^ ((uint32_t)(row & 7) << 4));
      float ux = q.x + pu4.x, uy = q.y + pu4.y, uz = q.z + pu4.z, uw = q.w + pu4.w;
      float vx = q.x + pv4.x, vy = q.y + pv4.y, vz = q.z + pv4.z, vw = q.w + pv4.w;
      uint2 hh, ll;
      hh.x = pack_bf2(ux, uy); hh.y = pack_bf2(uz, uw);
      ll.x = pack_bf2(bf_res(ux), bf_res(uy));
      ll.y = pack_bf2(bf_res(uz), bf_res(uw));
      *(uint2*)(smem + SC_QUH + sw) = hh;
      *(uint2*)(smem + SC_QUL + sw) = ll;
      hh.x = pack_bf2(vx, vy); hh.y = pack_bf2(vz, vw);
      ll.x = pack_bf2(bf_res(vx), bf_res(vy));
      ll.y = pack_bf2(bf_res(vz), bf_res(vw));
      *(uint2*)(smem + SC_QVH + sw) = hh;
      *(uint2*)(smem + SC_QVL + sw) = ll;
    }
  }
  asm volatile("cp.async.wait_group 0;" ::: "memory");
  __syncthreads();

  // ---- mma: 8 warps = 4 (t) x 2 (s/band)
  const int wm = wid & 3;
  const int wn = wid >> 2;
  const int l7 = lane & 7;
  const uint32_t xa = (uint32_t)(l7 << 4);
  const int rowA = wm * 16 + l7 + (((lane >> 3) & 1) << 3);
  const uint32_t kadd_a = (uint32_t)(((lane >> 4) & 1) << 4);
  const int rbB = l7 + (((lane >> 4) & 1) << 3);
  const uint32_t kadd_b = (uint32_t)(((lane >> 3) & 1) << 4);

  float ac[8][4], bd[12][4];
#pragma unroll
  for (int nt = 0; nt < 8; nt++)
#pragma unroll
    for (int i = 0; i < 4; i++) ac[nt][i] = 0.f;
#pragma unroll
  for (int nt = 0; nt < 12; nt++)
#pragma unroll
    for (int i = 0; i < 4; i++) bd[nt][i] = 0.f;

#pragma unroll
  for (int ks = 0; ks < 4; ks++) {
    const uint32_t kba = (uint32_t)(ks * 32);
    const uint32_t aoff = (uint32_t)(rowA * 128) + ((kba + kadd_a) ^ xa);
    uint32_t quh[4], qul[4], qvh[4], qvl[4];
    ldm4(quh[0], quh[1], quh[2], quh[3], sb + SC_QUH + aoff);
    ldm4(qul[0], qul[1], qul[2], qul[3], sb + SC_QUL + aoff);
    ldm4(qvh[0], qvh[1], qvh[2], qvh[3], sb + SC_QVH + aoff);
    ldm4(qvl[0], qvl[1], qvl[2], qvl[3], sb + SC_QVL + aoff);
#pragma unroll
    for (int np = 0; np < 4; np++) {
      const int rowB = wn * 64 + np * 16 + rbB;
      const uint32_t boff = (uint32_t)(rowB * 128) + ((kba + kadd_b) ^ xa);
      uint32_t kh[4], kl[4];
      ldm4(kh[0], kh[1], kh[2], kh[3], sb + SC_KH + boff);
      ldm4(kl[0], kl[1], kl[2], kl[3], sb + SC_KL + boff);
      mma_bf16(ac[2 * np + 0], quh, kh[0], kh[1]);
      mma_bf16(ac[2 * np + 1], quh, kh[2], kh[3]);
      mma_bf16(ac[2 * np + 0], quh, kl[0], kl[1]);
      mma_bf16(ac[2 * np + 1], quh, kl[2], kl[3]);
      mma_bf16(ac[2 * np + 0], qul, kh[0], kh[1]);
      mma_bf16(ac[2 * np + 1], qul, kh[2], kh[3]);
    }
#pragma unroll
    for (int np = 0; np < 6; np++) {
      const int rowB = wn * 96 + np * 16 + rbB;
      const uint32_t boff = (uint32_t)(rowB * 128) + ((kba + kadd_b) ^ xa);
      uint32_t ph[4], pl[4];
      ldm4(ph[0], ph[1], ph[2], ph[3], sb + SC_PH + boff);
      ldm4(pl[0], pl[1], pl[2], pl[3], sb + SC_PL + boff);
      mma_bf16(bd[2 * np + 0], qvh, ph[0], ph[1]);
      mma_bf16(bd[2 * np + 1], qvh, ph[2], ph[3]);
      mma_bf16(bd[2 * np + 0], qvh, pl[0], pl[1]);
      mma_bf16(bd[2 * np + 1], qvh, pl[2], pl[3]);
      mma_bf16(bd[2 * np + 0], qvl, ph[0], ph[1]);
      mma_bf16(bd[2 * np + 1], qvl, ph[2], ph[3]);
    }
  }
  __syncthreads();  // operand smem dead; safe to alias with BDs

  // ---- BD -> smem (stride 196 floats)
  const int r0w = wm * 16 + (lane >> 2);
#pragma unroll
  for (int nt = 0; nt < 12; nt++) {
    const int col = wn * 96 + nt * 8 + (lane & 3) * 2;
    *(float2*)&BDs[r0w * SC_BDW + col] = make_float2(bd[nt][0], bd[nt][1]);
    *(float2*)&BDs[(r0w + 8) * SC_BDW + col] = make_float2(bd[nt][2], bd[nt][3]);
  }
  __syncthreads();

  // ---- epilogue: out = (AC + shifted BD) / 8
  float* wbase = wout + ((size_t)bh * TSEQ + t0) * TSEQ + s0;
#pragma unroll
  for (int nt = 0; nt < 8; nt++) {
    const int col = wn * 64 + nt * 8 + (lane & 3) * 2;
#pragma unroll
    for (int half = 0; half < 2; half++) {
      const int row = r0w + half * 8;
      const int bdi = row * SC_BDW + col - row + 63;
      float2 o;
      o.x = (ac[nt][half * 2 + 0] + BDs[bdi]) * 0.125f;
      o.y = (ac[nt][half * 2 + 1] + BDs[bdi + 1]) * 0.125f;
      *(float2*)(wbase + (size_t)row * TSEQ + col) = o;
    }
  }
}

// ---------------------------------------------------------------------------
// Softmax over rows of 512, in place (f32 only). One warp per row.
// ---------------------------------------------------------------------------
__global__ void __launch_bounds__(256) softmax_kernel(float* __restrict__ w) {
  const int gwarp = (blockIdx.x * 256 + threadIdx.x) >> 5;
  const int lane = threadIdx.x & 31;
  float* row = w + (size_t)gwarp * TSEQ;
  float4 v[4];
#pragma unroll
  for (int k = 0; k < 4; k++) v[k] = *(float4*)(row + k * 128 + lane * 4);
  float m = v[0].x;
#pragma unroll
  for (int k = 0; k < 4; k++)
    m = fmaxf(m, fmaxf(fmaxf(v[k].x, v[k].y), fmaxf(v[k].z, v[k].w)));
#pragma unroll
  for (int off = 16; off > 0; off >>= 1)
    m = fmaxf(m, __shfl_xor_sync(0xffffffffu, m, off));
  float s = 0.f;
#pragma unroll
  for (int k = 0; k < 4; k++) {
    v[k].x = __expf(v[k].x - m); s += v[k].x;
    v[k].y = __expf(v[k].y - m); s += v[k].y;
    v[k].z = __expf(v[k].z - m); s += v[k].z;
    v[k].w = __expf(v[k].w - m); s += v[k].w;
  }
#pragma unroll
  for (int off = 16; off > 0; off >>= 1)
    s += __shfl_xor_sync(0xffffffffu, s, off);
  const float inv = 1.0f / s;
#pragma unroll
  for (int k = 0; k < 4; k++) {
    v[k].x *= inv; v[k].y *= inv; v[k].z *= inv; v[k].w *= inv;
    *(float4*)(row + k * 128 + lane * 4) = v[k];
  }
}

// ---------------------------------------------------------------------------
// Context GEMM: ctx[b,t,h*64+d] = sum_s W[bh,t,s] * Vt[bh,d,s]
// W loaded f32 direct-to-register (coalesced LDG), converted to smem bf16.
// ---------------------------------------------------------------------------
#define CT_WH 0        // converted W hi (swizzled), 16KB
#define CT_WL 16384    // converted W lo, 16KB
#define CT_V  32768    // V buffers: +buf*16384; hi at +0 (8KB), lo at +8192
#define CT_SMEM 65536

__global__ void __launch_bounds__(256, 2) ctx_mma(
    const float* __restrict__ wts, float* __restrict__ ctx) {
  extern __shared__ char smem[];
  const uint32_t sb = smem_u32(smem);
  const int tid = threadIdx.x;
  const int wid = tid >> 5, lane = tid & 31;
  const int t0 = blockIdx.x * 128;
  const int bh = blockIdx.y;
  const int b = bh >> 4, h = bh & 15;

  const float* Wf = wts + ((size_t)bh * TSEQ + t0) * TSEQ;
  const __nv_bfloat16* Vh = g_Vth + (size_t)bh * DK * TSEQ;
  const __nv_bfloat16* Vl = g_Vtl + (size_t)bh * DK * TSEQ;

  const int wm = wid & 3;
  const int wn = wid >> 2;
  const int l7 = lane & 7;
  const uint32_t xa = (uint32_t)(l7 << 4);
  const int rowA0 = wm * 32 + l7 + (((lane >> 3) & 1) << 3);
  const uint32_t kadd_a = (uint32_t)(((lane >> 4) & 1) << 4);
  const int rowB0 = wn * 32 + l7 + (((lane >> 4) & 1) << 3);
  const uint32_t kadd_b = (uint32_t)(((lane >> 3) & 1) << 4);

  // per-thread W load mapping: 128 rows x 16 segs (16B) = 2048 items, 8/thread
  const int wrow = tid >> 4;   // base row (stride +16 rows per it... see loop)
  const int wseg = tid & 15;

  float acc[2][4][4];
#pragma unroll
  for (int mt = 0; mt < 2; mt++)
#pragma unroll
    for (int nt = 0; nt < 4; nt++)
#pragma unroll
      for (int i = 0; i < 4; i++) acc[mt][nt][i] = 0.f;

  auto load_v = [&](int kc, int buf) {
    const int k0 = kc * 64;
    const uint32_t vb = sb + CT_V + (uint32_t)(buf * 16384);
#pragma unroll
    for (int it = 0; it < 2; it++) {
      const int idx = tid + it * 256;
      const int row = idx >> 3, ch = idx & 7;
      const uint32_t sw = (uint32_t)(row * 128) + ((uint32_t)(ch * 16) ^ ((uint32_t)(row & 7) << 4));
      cp16(vb + sw, Vh + (size_t)row * TSEQ + k0 + ch * 8);
      cp16(vb + 8192 + sw, Vl + (size_t)row * TSEQ + k0 + ch * 8);
    }
  };

  load_v(0, 0);
  cp_commit();

  for (int kc = 0; kc < 8; kc++) {
    // load W f32 chunk direct to registers (coalesced: 16 threads x 16B per row)
    float4 wreg[8];
#pragma unroll
    for (int it = 0; it < 8; it++) {
      const int r = wrow + it * 16;
      wreg[it] = *(const float4*)(Wf + (size_t)r * TSEQ + kc * 64 + wseg * 4);
    }
    asm volatile("cp.async.wait_group 0;" ::: "memory");
    __syncthreads();  // prev mma done with WH/WL; V chunk visible

    // convert regs -> bf16 hi/lo swizzled smem
#pragma unroll
    for (int it = 0; it < 8; it++) {
      const int r = wrow + it * 16;
      const float4 wv = wreg[it];
      const uint32_t sw = (uint32_t)(r * 128) + ((uint32_t)(wseg * 8) ^ ((uint32_t)(r & 7) << 4));
      uint2 hh, ll;
      hh.x = pack_bf2(wv.x, wv.y); hh.y = pack_bf2(wv.z, wv.w);
      ll.x = pack_bf2(bf_res(wv.x), bf_res(wv.y));
      ll.y = pack_bf2(bf_res(wv.z), bf_res(wv.w));
      *(uint2*)(smem + CT_WH + sw) = hh;
      *(uint2*)(smem + CT_WL + sw) = ll;
    }
    __syncthreads();

    if (kc + 1 < 8) {
      load_v(kc + 1, (kc + 1) & 1);
      cp_commit();
    }

    const uint32_t vb = sb + CT_V + (uint32_t)((kc & 1) * 16384);
#pragma unroll
    for (int ks = 0; ks < 4; ks++) {
      const uint32_t kba = (uint32_t)(ks * 32);
      uint32_t ah[2][4], al[2][4];
#pragma unroll
      for (int mt = 0; mt < 2; mt++) {
        const uint32_t aoff = (uint32_t)((rowA0 + mt * 16) * 128) + ((kba + kadd_a) ^ xa);
        ldm4(ah[mt][0], ah[mt][1], ah[mt][2], ah[mt][3], sb + CT_WH + aoff);
        ldm4(al[mt][0], al[mt][1], al[mt][2], al[mt][3], sb + CT_WL + aoff);
      }
#pragma unroll
      for (int np = 0; np < 2; np++) {
        const uint32_t boff = (uint32_t)((rowB0 + np * 16) * 128) + ((kba + kadd_b) ^ xa);
        uint32_t vhh[4], vll[4];
        ldm4(vhh[0], vhh[1], vhh[2], vhh[3], vb + boff);
        ldm4(vll[0], vll[1], vll[2], vll[3], vb + 8192 + boff);
#pragma unroll
        for (int mt = 0; mt < 2; mt++) {
          mma_bf16(acc[mt][2 * np + 0], ah[mt], vhh[0], vhh[1]);
          mma_bf16(acc[mt][2 * np + 1], ah[mt], vhh[2], vhh[3]);
          mma_bf16(acc[mt][2 * np + 0], ah[mt], vll[0], vll[1]);
          mma_bf16(acc[mt][2 * np + 1], ah[mt], vll[2], vll[3]);
          mma_bf16(acc[mt][2 * np + 0], al[mt], vhh[0], vhh[1]);
          mma_bf16(acc[mt][2 * np + 1], al[mt], vhh[2], vhh[3]);
        }
      }
    }
  }

  const int mrow = t0 + wm * 32 + (lane >> 2);
#pragma unroll
  for (int mt = 0; mt < 2; mt++) {
#pragma unroll
    for (int half = 0; half < 2; half++) {
      const int t = mrow + mt * 16 + half * 8;
#pragma unroll
      for (int nt = 0; nt < 4; nt++) {
        const int d = wn * 32 + nt * 8 + (lane & 3) * 2;
        float2 o;
        o.x = acc[mt][nt][half * 2 + 0];
        o.y = acc[mt][nt][half * 2 + 1];
        *(float2*)(ctx + ((size_t)b * TSEQ + t) * DM + h * DK + d) = o;
      }
    }
  }
}

// ---------------------------------------------------------------------------
// Launch
// ---------------------------------------------------------------------------
extern "C" void kernel_launch(void* const* d_in, const int* in_sizes, int n_in,
                              void* d_out, int out_size) {
  const float* x     = (const float*)d_in[0];
  const float* pos   = (const float*)d_in[2];
  const float* qvk_w = (const float*)d_in[3];
  const float* qvk_b = (const float*)d_in[4];
  const float* pos_w = (const float*)d_in[5];
  const float* posu  = (const float*)d_in[6];
  const float* posv  = (const float*)d_in[7];

  float* ctx = (float*)d_out;
  float* wts = (float*)d_out + (size_t)BATCH * TSEQ * DM;

  // 0) merged prep (all bf16 hi/lo splits)
  prep_kernel<<<6400, 256>>>(x, qvk_w, pos, pos_w);

  // 1) merged projection GEMMs, tile 128x256 (QKV 768 + pos 32 tiles)
  cudaFuncSetAttribute(mma_gemm_all, cudaFuncAttributeMaxDynamicSharedMemorySize,
                       GSMEM);
  mma_gemm_all<<<800, 512, GSMEM>>>(qvk_b);

  // 2) scores (+ merged vtsplit tail) -> weights region
  cudaFuncSetAttribute(scores_mma, cudaFuncAttributeMaxDynamicSharedMemorySize,
                       SC_SMEM);
  scores_mma<<<dim3(4, 8, 320), 256, SC_SMEM>>>(posu, posv, wts);

  // 3) softmax in place (f32 only)
  softmax_kernel<<<(BATCH * NH * TSEQ) / 8, 256>>>(wts);

  // 4) context = W @ V (W f32 direct-LDG + in-register conversion)
  cudaFuncSetAttribute(ctx_mma, cudaFuncAttributeMaxDynamicSharedMemorySize,
                       CT_SMEM);
  ctx_mma<<<dim3(TSEQ / 128, BATCH * NH), 256, CT_SMEM>>>(wts, ctx);
}

// round 13
// speedup vs baseline: 1.0543x; 1.0375x over previous
#include <cuda_runtime.h>
#include <cuda_bf16.h>
#include <cstdint>

#define BATCH 16
#define TSEQ 512
#define NH 16
#define DK 64
#define DM 1024
#define D3 3072
#define RR 1023  // 2T-1

// ---------------------------------------------------------------------------
// Scratch (allocation-free: device globals)
// ---------------------------------------------------------------------------
__device__ float g_Q[BATCH*NH*TSEQ*DK];
__device__ float g_V[BATCH*NH*TSEQ*DK];

// K and P stored directly as bf16 hi/lo (written by projection epilogues)
__device__ __nv_bfloat16 g_Kh[BATCH*NH*TSEQ*DK];
__device__ __nv_bfloat16 g_Kl[BATCH*NH*TSEQ*DK];
__device__ __nv_bfloat16 g_Ph[NH*RR*DK];
__device__ __nv_bfloat16 g_Pl[NH*RR*DK];

// bf16 hi/lo split operands for projection GEMMs
__device__ __nv_bfloat16 g_Ah[BATCH*TSEQ*DM];
__device__ __nv_bfloat16 g_Al[BATCH*TSEQ*DM];
__device__ __nv_bfloat16 g_Wh[D3*DM];      // qvk_w transposed: [3072][1024]
__device__ __nv_bfloat16 g_Wl[D3*DM];
__device__ __nv_bfloat16 g_pAh[1024*DM];   // pos padded to 1024 rows
__device__ __nv_bfloat16 g_pAl[1024*DM];
__device__ __nv_bfloat16 g_pWh[DM*DM];     // pos_w transposed
__device__ __nv_bfloat16 g_pWl[DM*DM];

// V^T bf16 hi/lo [bh][d][s]
__device__ __nv_bfloat16 g_Vth[(size_t)BATCH*NH*DK*TSEQ];
__device__ __nv_bfloat16 g_Vtl[(size_t)BATCH*NH*DK*TSEQ];

// ---------------------------------------------------------------------------
// helpers
// ---------------------------------------------------------------------------
__device__ __forceinline__ uint32_t smem_u32(const void* p) {
  uint32_t a;
  asm("{ .reg .u64 t; cvta.to.shared.u64 t, %1; cvt.u32.u64 %0, t; }" : "=r"(a) : "l"(p));
  return a;
}
__device__ __forceinline__ void cp16(uint32_t dst, const void* src) {
  asm volatile("cp.async.cg.shared.global [%0], [%1], 16;" :: "r"(dst), "l"(src));
}
__device__ __forceinline__ void cp16z(uint32_t dst, const void* src, int nbytes) {
  asm volatile("cp.async.cg.shared.global [%0], [%1], 16, %2;"
               :: "r"(dst), "l"(src), "r"(nbytes));
}
__device__ __forceinline__ void cp_commit() {
  asm volatile("cp.async.commit_group;" ::: "memory");
}
__device__ __forceinline__ void ldm4(uint32_t& r0, uint32_t& r1, uint32_t& r2,
                                     uint32_t& r3, uint32_t a) {
  asm volatile("ldmatrix.sync.aligned.m8n8.x4.shared.b16 {%0,%1,%2,%3}, [%4];"
               : "=r"(r0), "=r"(r1), "=r"(r2), "=r"(r3) : "r"(a));
}
__device__ __forceinline__ void mma_bf16(float* c, const uint32_t* a,
                                         uint32_t b0, uint32_t b1) {
  asm volatile(
      "mma.sync.aligned.m16n8k16.row.col.f32.bf16.bf16.f32 "
      "{%0,%1,%2,%3}, {%4,%5,%6,%7}, {%8,%9}, {%0,%1,%2,%3};"
      : "+f"(c[0]), "+f"(c[1]), "+f"(c[2]), "+f"(c[3])
      : "r"(a[0]), "r"(a[1]), "r"(a[2]), "r"(a[3]), "r"(b0), "r"(b1));
}
__device__ __forceinline__ uint32_t pack_bf2(float a, float b) {
  __nv_bfloat16 ha = __float2bfloat16(a), hb = __float2bfloat16(b);
  uint16_t ua = *(uint16_t*)&ha, ub = *(uint16_t*)&hb;
  return (uint32_t)ua | ((uint32_t)ub << 16);
}
__device__ __forceinline__ float bf_res(float v) {
  return v - __bfloat162float(__float2bfloat16(v));
}

// ---------------------------------------------------------------------------
// Merged prep: all 4 split/tsplit jobs in ONE launch.
// ---------------------------------------------------------------------------
__global__ void __launch_bounds__(256) prep_kernel(
    const float* __restrict__ x, const float* __restrict__ qvk_w,
    const float* __restrict__ pos, const float* __restrict__ pos_w) {
  __shared__ float t[32][33];
  const int bid = blockIdx.x;
  const int tid = threadIdx.x;
  if (bid < 2048) {  // split x
    const int n = BATCH * TSEQ * DM;
    for (int i = bid * 256 + tid; i < n; i += 2048 * 256) {
      float v = x[i];
      __nv_bfloat16 h = __float2bfloat16(v);
      g_Ah[i] = h;
      g_Al[i] = __float2bfloat16(v - __bfloat162float(h));
    }
  } else if (bid < 5120) {  // tsplit qvk_w: R=1024 C=3072
    const int r = bid - 2048;
    const int c0 = (r % 96) * 32, r0 = (r / 96) * 32;
    const int tx = tid & 31, ty = tid >> 5;
#pragma unroll
    for (int i = 0; i < 4; i++)
      t[ty + i * 8][tx] = qvk_w[(size_t)(r0 + ty + i * 8) * D3 + c0 + tx];
    __syncthreads();
#pragma unroll
    for (int i = 0; i < 4; i++) {
      float v = t[tx][ty + i * 8];
      __nv_bfloat16 h = __float2bfloat16(v);
      size_t o = (size_t)(c0 + ty + i * 8) * DM + r0 + tx;
      g_Wh[o] = h;
      g_Wl[o] = __float2bfloat16(v - __bfloat162float(h));
    }
  } else if (bid < 5376) {  // split pos (pad to 1024 rows)
    const int r = bid - 5120;
    const int n = RR * DM, ntot = 1024 * DM;
    for (int i = r * 256 + tid; i < ntot; i += 256 * 256) {
      float v = (i < n) ? pos[i] : 0.f;
      __nv_bfloat16 h = __float2bfloat16(v);
      g_pAh[i] = h;
      g_pAl[i] = __float2bfloat16(v - __bfloat162float(h));
    }
  } else {  // tsplit pos_w: R=1024 C=1024
    const int r = bid - 5376;
    const int c0 = (r % 32) * 32, r0 = (r / 32) * 32;
    const int tx = tid & 31, ty = tid >> 5;
#pragma unroll
    for (int i = 0; i < 4; i++)
      t[ty + i * 8][tx] = pos_w[(size_t)(r0 + ty + i * 8) * DM + c0 + tx];
    __syncthreads();
#pragma unroll
    for (int i = 0; i < 4; i++) {
      float v = t[tx][ty + i * 8];
      __nv_bfloat16 h = __float2bfloat16(v);
      size_t o = (size_t)(c0 + ty + i * 8) * DM + r0 + tx;
      g_pWh[o] = h;
      g_pWl[o] = __float2bfloat16(v - __bfloat162float(h));
    }
  }
}

// ---------------------------------------------------------------------------
// Merged projection GEMMs (QKV + pos), tile 128x256, 512 threads (16 warps).
// ---------------------------------------------------------------------------
#define PBUF 98304
#define OFF_AH 0
#define OFF_AL 16384
#define OFF_BH 32768
#define OFF_BL 65536
#define GSMEM (2 * PBUF)  // 196608

__global__ void __launch_bounds__(512, 1) mma_gemm_all(const float* __restrict__ bias) {
  extern __shared__ char smem[];
  const uint32_t sb = smem_u32(smem);
  const int tid = threadIdx.x;
  const int wid = tid >> 5, lane = tid & 31;
  const int bid = blockIdx.x;
  const bool qkv = bid < 768;
  int n0, m0;
  const __nv_bfloat16 *Ah, *Al, *Bh, *Bl;
  if (qkv) {
    n0 = (bid % 12) * 256; m0 = (bid / 12) * 128;
    Ah = g_Ah; Al = g_Al; Bh = g_Wh; Bl = g_Wl;
  } else {
    const int r = bid - 768;
    n0 = (r % 4) * 256; m0 = (r / 4) * 128;
    Ah = g_pAh; Al = g_pAl; Bh = g_pWh; Bl = g_pWl;
  }
  const int wm = wid & 3;
  const int wn = wid >> 2;

  const int gr = tid >> 3;
  const int gc = tid & 7;
  const uint32_t gsw = (uint32_t)((gc * 16) ^ ((gr & 7) << 4));

  const int l7 = lane & 7;
  const uint32_t xa = (uint32_t)(l7 << 4);
  const int rowA0 = wm * 32 + l7 + (((lane >> 3) & 1) << 3);
  const uint32_t kadd_a = (uint32_t)(((lane >> 4) & 1) << 4);
  const int rowB0 = wn * 64 + l7 + (((lane >> 4) & 1) << 3);
  const uint32_t kadd_b = (uint32_t)(((lane >> 3) & 1) << 4);

  float acc[2][8][4];
#pragma unroll
  for (int mt = 0; mt < 2; mt++)
#pragma unroll
    for (int nt = 0; nt < 8; nt++)
#pragma unroll
      for (int i = 0; i < 4; i++) acc[mt][nt][i] = 0.f;

  auto load_chunk = [&](int kc, int buf) {
    const int k0 = kc * 64;
    const uint32_t base = sb + buf * PBUF;
#pragma unroll
    for (int it = 0; it < 2; it++) {
      const int r = gr + it * 64;
      const uint32_t sw = (uint32_t)(r * 128) + gsw;
      const size_t asrc = (size_t)(m0 + r) * DM + k0 + gc * 8;
      cp16(base + OFF_AH + sw, Ah + asrc);
      cp16(base + OFF_AL + sw, Al + asrc);
    }
#pragma unroll
    for (int it = 0; it < 4; it++) {
      const int r = gr + it * 64;
      const uint32_t sw = (uint32_t)(r * 128) + gsw;
      const size_t bsrc = (size_t)(n0 + r) * DM + k0 + gc * 8;
      cp16(base + OFF_BH + sw, Bh + bsrc);
      cp16(base + OFF_BL + sw, Bl + bsrc);
    }
    cp_commit();
  };

  load_chunk(0, 0);

  for (int kc = 0; kc < 16; kc++) {
    if (kc + 1 < 16) {
      load_chunk(kc + 1, (kc + 1) & 1);
      asm volatile("cp.async.wait_group 1;" ::: "memory");
    } else {
      asm volatile("cp.async.wait_group 0;" ::: "memory");
    }
    __syncthreads();

    const uint32_t bb = sb + (kc & 1) * PBUF;
#pragma unroll
    for (int ks = 0; ks < 4; ks++) {
      const uint32_t kba = (uint32_t)(ks * 32);
      uint32_t ah[2][4], al[2][4];
#pragma unroll
      for (int mt = 0; mt < 2; mt++) {
        const uint32_t aoff = (uint32_t)((rowA0 + mt * 16) * 128) + ((kba + kadd_a) ^ xa);
        ldm4(ah[mt][0], ah[mt][1], ah[mt][2], ah[mt][3], bb + OFF_AH + aoff);
        ldm4(al[mt][0], al[mt][1], al[mt][2], al[mt][3], bb + OFF_AL + aoff);
      }
#pragma unroll
      for (int np = 0; np < 4; np++) {
        const uint32_t boff = (uint32_t)((rowB0 + np * 16) * 128) + ((kba + kadd_b) ^ xa);
        uint32_t bh[4], bl[4];
        ldm4(bh[0], bh[1], bh[2], bh[3], bb + OFF_BH + boff);
        ldm4(bl[0], bl[1], bl[2], bl[3], bb + OFF_BL + boff);
#pragma unroll
        for (int mt = 0; mt < 2; mt++) {
          mma_bf16(acc[mt][2 * np + 0], ah[mt], bh[0], bh[1]);
          mma_bf16(acc[mt][2 * np + 1], ah[mt], bh[2], bh[3]);
          mma_bf16(acc[mt][2 * np + 0], ah[mt], bl[0], bl[1]);
          mma_bf16(acc[mt][2 * np + 1], ah[mt], bl[2], bl[3]);
          mma_bf16(acc[mt][2 * np + 0], al[mt], bh[0], bh[1]);
          mma_bf16(acc[mt][2 * np + 1], al[mt], bh[2], bh[3]);
        }
      }
    }
    __syncthreads();
  }

  const int mrow = m0 + wm * 32 + (lane >> 2);
#pragma unroll
  for (int mt = 0; mt < 2; mt++) {
#pragma unroll
    for (int half = 0; half < 2; half++) {
      const int m = mrow + mt * 16 + half * 8;
#pragma unroll
      for (int nt = 0; nt < 8; nt++) {
        const int n = n0 + wn * 64 + nt * 8 + (lane & 3) * 2;
        float2 o;
        o.x = acc[mt][nt][half * 2 + 0];
        o.y = acc[mt][nt][half * 2 + 1];
        if (qkv) {
          o.x += bias[n];
          o.y += bias[n + 1];
          const int b = m >> 9, t = m & 511;
          const int sec = n >> 10;
          const int h = (n >> 6) & 15;
          const int d = n & 63;
          const size_t idx = ((size_t)(b * NH + h) * TSEQ + t) * DK + d;
          if (sec == 0) {
            *(float2*)(g_Q + idx) = o;
          } else if (sec == 1) {
            *(uint32_t*)&g_Kh[idx] = pack_bf2(o.x, o.y);
            *(uint32_t*)&g_Kl[idx] = pack_bf2(bf_res(o.x), bf_res(o.y));
          } else {
            *(float2*)(g_V + idx) = o;
          }
        } else {
          if (m < RR) {
            const int h = n >> 6;
            const int d = n & 63;
            const size_t idx = ((size_t)h * RR + m) * DK + d;
            *(uint32_t*)&g_Ph[idx] = pack_bf2(o.x, o.y);
            *(uint32_t*)&g_Pl[idx] = pack_bf2(bf_res(o.x), bf_res(o.y));
          }
        }
      }
    }
  }
}

// ---------------------------------------------------------------------------
// Scores (+ merged vtsplit tail): grid (4, 8, 320).
// ---------------------------------------------------------------------------
#define SC_QUH 0
#define SC_QUL 8192
#define SC_QVH 16384
#define SC_QVL 24576
#define SC_KH  32768
#define SC_KL  49152
#define SC_PH  65536
#define SC_PL  90112
#define SC_SMEM 114688
#define SC_BDW 196

__global__ void __launch_bounds__(256, 2) scores_mma(
    const float* __restrict__ pu, const float* __restrict__ pv,
    float* __restrict__ wout) {
  extern __shared__ char smem[];
  const uint32_t sb = smem_u32(smem);
  const int tid = threadIdx.x;

  if (blockIdx.z >= 256) {
    // ---- vtsplit job
    float (*t)[65] = (float(*)[65])smem;
    const int job = (blockIdx.z - 256) * 32 + blockIdx.y * 4 + blockIdx.x;
    const int vbh = job >> 3;
    const int vs0 = (job & 7) * 64;
    const float* vbase = g_V + (size_t)vbh * TSEQ * DK;
    for (int i = tid; i < 4096; i += 256) {
      const int sl = i >> 6, d = i & 63;
      t[sl][d] = vbase[(size_t)(vs0 + sl) * DK + d];
    }
    __syncthreads();
    for (int i = tid; i < 2048; i += 256) {
      const int d = i >> 5, sl = (i & 31) * 2;
      const float v0 = t[sl][d], v1 = t[sl + 1][d];
      const size_t o = ((size_t)vbh * DK + d) * TSEQ + vs0 + sl;
      *(uint32_t*)&g_Vth[o] = pack_bf2(v0, v1);
      *(uint32_t*)&g_Vtl[o] = pack_bf2(bf_res(v0), bf_res(v1));
    }
    return;
  }

  float* BDs = (float*)smem;  // aliased after mma phase
  const int wid = tid >> 5, lane = tid & 31;
  const int s0 = blockIdx.x * 128;
  const int t0 = blockIdx.y * 64;
  const int bh = blockIdx.z, h = bh & 15;
  const int relbase = s0 - t0 + 448;

  // ---- cp.async K tiles (128 rows x 128B, hi+lo)
  {
    const __nv_bfloat16* Kh = g_Kh + ((size_t)bh * TSEQ + s0) * DK;
    const __nv_bfloat16* Kl = g_Kl + ((size_t)bh * TSEQ + s0) * DK;
#pragma unroll
    for (int it = 0; it < 4; it++) {
      const int idx = tid + it * 256;
      const int row = idx >> 3, ch = idx & 7;
      const uint32_t sw = (uint32_t)(row * 128) + ((uint32_t)(ch * 16) ^ ((uint32_t)(row & 7) << 4));
      cp16(sb + SC_KH + sw, Kh + row * DK + ch * 8);
      cp16(sb + SC_KL + sw, Kl + row * DK + ch * 8);
    }
  }
  // ---- cp.async P band (192 rows x 128B, hi+lo), zero-fill out of range
  {
    const __nv_bfloat16* Ph = g_Ph + (size_t)h * RR * DK;
    const __nv_bfloat16* Pl = g_Pl + (size_t)h * RR * DK;
#pragma unroll
    for (int it = 0; it < 6; it++) {
      const int idx = tid + it * 256;
      const int row = idx >> 3, ch = idx & 7;
      const int r = relbase + row;
      const int rc = r < 0 ? 0 : (r >= RR ? RR - 1 : r);
      const int ok = (r >= 0 && r < RR) ? 16 : 0;
      const uint32_t sw = (uint32_t)(row * 128) + ((uint32_t)(ch * 16) ^ ((uint32_t)(row & 7) << 4));
      cp16z(sb + SC_PH + sw, Ph + (size_t)rc * DK + ch * 8, ok);
      cp16z(sb + SC_PL + sw, Pl + (size_t)rc * DK + ch * 8, ok);
    }
  }
  cp_commit();

  // ---- Q fill: fp32 + posu/posv, convert to bf16 hi/lo (overlaps cp.async)
  {
    const int frow = tid >> 4;
    const int c4 = (tid & 15) * 4;
    const uint32_t cb = (uint32_t)(c4 * 2);
    const float4 pu4 = *(const float4*)(pu + h * 64 + c4);
    const float4 pv4 = *(const float4*)(pv + h * 64 + c4);
    const float* qb = g_Q + ((size_t)bh * TSEQ + t0) * DK;
#pragma unroll
    for (int it = 0; it < 4; it++) {
      const int row = frow + it * 16;
      const float4 q = *(const float4*)(qb + (size_t)row * DK + c4);
      const uint32_t sw = (uint32_t)(row * 128) + (cb ^ ((uint32_t)(row & 7) << 4));
      float ux = q.x + pu4.x, uy = q.y + pu4.y, uz = q.z + pu4.z, uw = q.w + pu4.w;
      float vx = q.x + pv4.x, vy = q.y + pv4.y, vz = q.z + pv4.z, vw = q.w + pv4.w;
      uint2 hh, ll;
      hh.x = pack_bf2(ux, uy); hh.y = pack_bf2(uz, uw);
      ll.x = pack_bf2(bf_res(ux), bf_res(uy));
      ll.y = pack_bf2(bf_res(uz), bf_res(uw));
      *(uint2*)(smem + SC_QUH + sw) = hh;
      *(uint2*)(smem + SC_QUL + sw) = ll;
      hh.x = pack_bf2(vx, vy); hh.y = pack_bf2(vz, vw);
      ll.x = pack_bf2(bf_res(vx), bf_res(vy));
      ll.y = pack_bf2(bf_res(vz), bf_res(vw));
      *(uint2*)(smem + SC_QVH + sw) = hh;
      *(uint2*)(smem + SC_QVL + sw) = ll;
    }
  }
  asm volatile("cp.async.wait_group 0;" ::: "memory");
  __syncthreads();

  // ---- mma: 8 warps = 4 (t) x 2 (s/band)
  const int wm = wid & 3;
  const int wn = wid >> 2;
  const int l7 = lane & 7;
  const uint32_t xa = (uint32_t)(l7 << 4);
  const int rowA = wm * 16 + l7 + (((lane >> 3) & 1) << 3);
  const uint32_t kadd_a = (uint32_t)(((lane >> 4) & 1) << 4);
  const int rbB = l7 + (((lane >> 4) & 1) << 3);
  const uint32_t kadd_b = (uint32_t)(((lane >> 3) & 1) << 4);

  float ac[8][4], bd[12][4];
#pragma unroll
  for (int nt = 0; nt < 8; nt++)
#pragma unroll
    for (int i = 0; i < 4; i++) ac[nt][i] = 0.f;
#pragma unroll
  for (int nt = 0; nt < 12; nt++)
#pragma unroll
    for (int i = 0; i < 4; i++) bd[nt][i] = 0.f;

#pragma unroll
  for (int ks = 0; ks < 4; ks++) {
    const uint32_t kba = (uint32_t)(ks * 32);
    const uint32_t aoff = (uint32_t)(rowA * 128) + ((kba + kadd_a) ^ xa);
    uint32_t quh[4], qul[4], qvh[4], qvl[4];
    ldm4(quh[0], quh[1], quh[2], quh[3], sb + SC_QUH + aoff);
    ldm4(qul[0], qul[1], qul[2], qul[3], sb + SC_QUL + aoff);
    ldm4(qvh[0], qvh[1], qvh[2], qvh[3], sb + SC_QVH + aoff);
    ldm4(qvl[0], qvl[1], qvl[2], qvl[3], sb + SC_QVL + aoff);
#pragma unroll
    for (int np = 0; np < 4; np++) {
      const int rowB = wn * 64 + np * 16 + rbB;
      const uint32_t boff = (uint32_t)(rowB * 128) + ((kba + kadd_b) ^ xa);
      uint32_t kh[4], kl[4];
      ldm4(kh[0], kh[1], kh[2], kh[3], sb + SC_KH + boff);
      ldm4(kl[0], kl[1], kl[2], kl[3], sb + SC_KL + boff);
      mma_bf16(ac[2 * np + 0], quh, kh[0], kh[1]);
      mma_bf16(ac[2 * np + 1], quh, kh[2], kh[3]);
      mma_bf16(ac[2 * np + 0], quh, kl[0], kl[1]);
      mma_bf16(ac[2 * np + 1], quh, kl[2], kl[3]);
      mma_bf16(ac[2 * np + 0], qul, kh[0], kh[1]);
      mma_bf16(ac[2 * np + 1], qul, kh[2], kh[3]);
    }
#pragma unroll
    for (int np = 0; np < 6; np++) {
      const int rowB = wn * 96 + np * 16 + rbB;
      const uint32_t boff = (uint32_t)(rowB * 128) + ((kba + kadd_b) ^ xa);
      uint32_t ph[4], pl[4];
      ldm4(ph[0], ph[1], ph[2], ph[3], sb + SC_PH + boff);
      ldm4(pl[0], pl[1], pl[2], pl[3], sb + SC_PL + boff);
      mma_bf16(bd[2 * np + 0], qvh, ph[0], ph[1]);
      mma_bf16(bd[2 * np + 1], qvh, ph[2], ph[3]);
      mma_bf16(bd[2 * np + 0], qvh, pl[0], pl[1]);
      mma_bf16(bd[2 * np + 1], qvh, pl[2], pl[3]);
      mma_bf16(bd[2 * np + 0], qvl, ph[0], ph[1]);
      mma_bf16(bd[2 * np + 1], qvl, ph[2], ph[3]);
    }
  }
  __syncthreads();  // operand smem dead; safe to alias with BDs

  // ---- BD -> smem (stride 196 floats)
  const int r0w = wm * 16 + (lane >> 2);
#pragma unroll
  for (int nt = 0; nt < 12; nt++) {
    const int col = wn * 96 + nt * 8 + (lane & 3) * 2;
    *(float2*)&BDs[r0w * SC_BDW + col] = make_float2(bd[nt][0], bd[nt][1]);
    *(float2*)&BDs[(r0w + 8) * SC_BDW + col] = make_float2(bd[nt][2], bd[nt][3]);
  }
  __syncthreads();

  // ---- epilogue: out = (AC + shifted BD) / 8
  float* wbase = wout + ((size_t)bh * TSEQ + t0) * TSEQ + s0;
#pragma unroll
  for (int nt = 0; nt < 8; nt++) {
    const int col = wn * 64 + nt * 8 + (lane & 3) * 2;
#pragma unroll
    for (int half = 0; half < 2; half++) {
      const int row = r0w + half * 8;
      const int bdi = row * SC_BDW + col - row + 63;
      float2 o;
      o.x = (ac[nt][half * 2 + 0] + BDs[bdi]) * 0.125f;
      o.y = (ac[nt][half * 2 + 1] + BDs[bdi + 1]) * 0.125f;
      *(float2*)(wbase + (size_t)row * TSEQ + col) = o;
    }
  }
}

// ---------------------------------------------------------------------------
// Softmax over rows of 512, in place (f32 only). One warp per row.
// ---------------------------------------------------------------------------
__global__ void __launch_bounds__(256) softmax_kernel(float* __restrict__ w) {
  const int gwarp = (blockIdx.x * 256 + threadIdx.x) >> 5;
  const int lane = threadIdx.x & 31;
  float* row = w + (size_t)gwarp * TSEQ;
  float4 v[4];
#pragma unroll
  for (int k = 0; k < 4; k++) v[k] = *(float4*)(row + k * 128 + lane * 4);
  float m = v[0].x;
#pragma unroll
  for (int k = 0; k < 4; k++)
    m = fmaxf(m, fmaxf(fmaxf(v[k].x, v[k].y), fmaxf(v[k].z, v[k].w)));
#pragma unroll
  for (int off = 16; off > 0; off >>= 1)
    m = fmaxf(m, __shfl_xor_sync(0xffffffffu, m, off));
  float s = 0.f;
#pragma unroll
  for (int k = 0; k < 4; k++) {
    v[k].x = __expf(v[k].x - m); s += v[k].x;
    v[k].y = __expf(v[k].y - m); s += v[k].y;
    v[k].z = __expf(v[k].z - m); s += v[k].z;
    v[k].w = __expf(v[k].w - m); s += v[k].w;
  }
#pragma unroll
  for (int off = 16; off > 0; off >>= 1)
    s += __shfl_xor_sync(0xffffffffu, s, off);
  const float inv = 1.0f / s;
#pragma unroll
  for (int k = 0; k < 4; k++) {
    v[k].x *= inv; v[k].y *= inv; v[k].z *= inv; v[k].w *= inv;
    *(float4*)(row + k * 128 + lane * 4) = v[k];
  }
}

// ---------------------------------------------------------------------------
// Context GEMM: ctx[b,t,h*64+d] = sum_s W[bh,t,s] * Vt[bh,d,s]
// W staged via cp.async (f32), converted in-kernel to bf16 hi/lo.
// V prefetch issued early (dead double-buffer slot) to overlap conversion.
// ---------------------------------------------------------------------------
#define CT_WF 0        // 128 x 64 f32 staging (linear, 256B rows), 32KB
#define CT_WH 32768    // converted W hi (swizzled), 16KB
#define CT_WL 49152    // converted W lo, 16KB
#define CT_V  65536    // V buffers: +buf*16384; hi at +0 (8KB), lo at +8192
#define CT_SMEM 98304

__global__ void __launch_bounds__(256, 2) ctx_mma(
    const float* __restrict__ wts, float* __restrict__ ctx) {
  extern __shared__ char smem[];
  const uint32_t sb = smem_u32(smem);
  const int tid = threadIdx.x;
  const int wid = tid >> 5, lane = tid & 31;
  const int t0 = blockIdx.x * 128;
  const int bh = blockIdx.y;
  const int b = bh >> 4, h = bh & 15;

  const float* Wf = wts + ((size_t)bh * TSEQ + t0) * TSEQ;
  const __nv_bfloat16* Vh = g_Vth + (size_t)bh * DK * TSEQ;
  const __nv_bfloat16* Vl = g_Vtl + (size_t)bh * DK * TSEQ;

  const int wm = wid & 3;
  const int wn = wid >> 2;
  const int l7 = lane & 7;
  const uint32_t xa = (uint32_t)(l7 << 4);
  const int rowA0 = wm * 32 + l7 + (((lane >> 3) & 1) << 3);
  const uint32_t kadd_a = (uint32_t)(((lane >> 4) & 1) << 4);
  const int rowB0 = wn * 32 + l7 + (((lane >> 4) & 1) << 3);
  const uint32_t kadd_b = (uint32_t)(((lane >> 3) & 1) << 4);

  float acc[2][4][4];
#pragma unroll
  for (int mt = 0; mt < 2; mt++)
#pragma unroll
    for (int nt = 0; nt < 4; nt++)
#pragma unroll
      for (int i = 0; i < 4; i++) acc[mt][nt][i] = 0.f;

  auto load_wf = [&](int kc) {
    const int k0 = kc * 64;
#pragma unroll
    for (int it = 0; it < 8; it++) {
      const int idx = tid + it * 256;
      const int row = idx >> 4, seg = idx & 15;
      cp16(sb + CT_WF + (uint32_t)(row * 256 + seg * 16),
           Wf + (size_t)row * TSEQ + k0 + seg * 4);
    }
  };
  auto load_v = [&](int kc, int buf) {
    const int k0 = kc * 64;
    const uint32_t vb = sb + CT_V + (uint32_t)(buf * 16384);
#pragma unroll
    for (int it = 0; it < 2; it++) {
      const int idx = tid + it * 256;
      const int row = idx >> 3, ch = idx & 7;
      const uint32_t sw = (uint32_t)(row * 128) + ((uint32_t)(ch * 16) ^ ((uint32_t)(row & 7) << 4));
      cp16(vb + sw, Vh + (size_t)row * TSEQ + k0 + ch * 8);
      cp16(vb + 8192 + sw, Vl + (size_t)row * TSEQ + k0 + ch * 8);
    }
  };

  load_wf(0);
  load_v(0, 0);
  cp_commit();

  for (int kc = 0; kc < 8; kc++) {
    asm volatile("cp.async.wait_group 0;" ::: "memory");
    __syncthreads();  // staging + V ready; prev mma done with WH/WL

    // early V prefetch: destination buffer (kc+1)&1 is dead since iter kc-1
    if (kc + 1 < 8) {
      load_v(kc + 1, (kc + 1) & 1);
      cp_commit();
    }

    // convert W f32 -> bf16 hi/lo swizzled (2048 float4)
#pragma unroll
    for (int it = 0; it < 8; it++) {
      const int idx = tid + it * 256;
      const int r = idx >> 4, q = idx & 15;
      const float4 wv = *(const float4*)(smem + CT_WF + r * 256 + q * 16);
      const uint32_t sw = (uint32_t)(r * 128) + ((uint32_t)(q * 8) ^ ((uint32_t)(r & 7) << 4));
      uint2 hh, ll;
      hh.x = pack_bf2(wv.x, wv.y); hh.y = pack_bf2(wv.z, wv.w);
      ll.x = pack_bf2(bf_res(wv.x), bf_res(wv.y));
      ll.y = pack_bf2(bf_res(wv.z), bf_res(wv.w));
      *(uint2*)(smem + CT_WH + sw) = hh;
      *(uint2*)(smem + CT_WL + sw) = ll;
    }
    __syncthreads();

    // W staging prefetch (CT_WF free after conversion barrier)
    if (kc + 1 < 8) {
      load_wf(kc + 1);
      cp_commit();
    }

    const uint32_t vb = sb + CT_V + (uint32_t)((kc & 1) * 16384);
#pragma unroll
    for (int ks = 0; ks < 4; ks++) {
      const uint32_t kba = (uint32_t)(ks * 32);
      uint32_t ah[2][4], al[2][4];
#pragma unroll
      for (int mt = 0; mt < 2; mt++) {
        const uint32_t aoff = (uint32_t)((rowA0 + mt * 16) * 128) + ((kba + kadd_a) ^ xa);
        ldm4(ah[mt][0], ah[mt][1], ah[mt][2], ah[mt][3], sb + CT_WH + aoff);
        ldm4(al[mt][0], al[mt][1], al[mt][2], al[mt][3], sb + CT_WL + aoff);
      }
#pragma unroll
      for (int np = 0; np < 2; np++) {
        const uint32_t boff = (uint32_t)((rowB0 + np * 16) * 128) + ((kba + kadd_b) ^ xa);
        uint32_t vhh[4], vll[4];
        ldm4(vhh[0], vhh[1], vhh[2], vhh[3], vb + boff);
        ldm4(vll[0], vll[1], vll[2], vll[3], vb + 8192 + boff);
#pragma unroll
        for (int mt = 0; mt < 2; mt++) {
          mma_bf16(acc[mt][2 * np + 0], ah[mt], vhh[0], vhh[1]);
          mma_bf16(acc[mt][2 * np + 1], ah[mt], vhh[2], vhh[3]);
          mma_bf16(acc[mt][2 * np + 0], ah[mt], vll[0], vll[1]);
          mma_bf16(acc[mt][2 * np + 1], ah[mt], vll[2], vll[3]);
          mma_bf16(acc[mt][2 * np + 0], al[mt], vhh[0], vhh[1]);
          mma_bf16(acc[mt][2 * np + 1], al[mt], vhh[2], vhh[3]);
        }
      }
    }
  }

  const int mrow = t0 + wm * 32 + (lane >> 2);
#pragma unroll
  for (int mt = 0; mt < 2; mt++) {
#pragma unroll
    for (int half = 0; half < 2; half++) {
      const int t = mrow + mt * 16 + half * 8;
#pragma unroll
      for (int nt = 0; nt < 4; nt++) {
        const int d = wn * 32 + nt * 8 + (lane & 3) * 2;
        float2 o;
        o.x = acc[mt][nt][half * 2 + 0];
        o.y = acc[mt][nt][half * 2 + 1];
        *(float2*)(ctx + ((size_t)b * TSEQ + t) * DM + h * DK + d) = o;
      }
    }
  }
}

// ---------------------------------------------------------------------------
// Launch
// ---------------------------------------------------------------------------
extern "C" void kernel_launch(void* const* d_in, const int* in_sizes, int n_in,
                              void* d_out, int out_size) {
  const float* x     = (const float*)d_in[0];
  const float* pos   = (const float*)d_in[2];
  const float* qvk_w = (const float*)d_in[3];
  const float* qvk_b = (const float*)d_in[4];
  const float* pos_w = (const float*)d_in[5];
  const float* posu  = (const float*)d_in[6];
  const float* posv  = (const float*)d_in[7];

  float* ctx = (float*)d_out;
  float* wts = (float*)d_out + (size_t)BATCH * TSEQ * DM;

  // 0) merged prep (all bf16 hi/lo splits)
  prep_kernel<<<6400, 256>>>(x, qvk_w, pos, pos_w);

  // 1) merged projection GEMMs, tile 128x256 (QKV 768 + pos 32 tiles)
  cudaFuncSetAttribute(mma_gemm_all, cudaFuncAttributeMaxDynamicSharedMemorySize,
                       GSMEM);
  mma_gemm_all<<<800, 512, GSMEM>>>(qvk_b);

  // 2) scores (+ merged vtsplit tail) -> weights region
  cudaFuncSetAttribute(scores_mma, cudaFuncAttributeMaxDynamicSharedMemorySize,
                       SC_SMEM);
  scores_mma<<<dim3(4, 8, 320), 256, SC_SMEM>>>(posu, posv, wts);

  // 3) softmax in place (f32 only)
  softmax_kernel<<<(BATCH * NH * TSEQ) / 8, 256>>>(wts);

  // 4) context = W @ V (staged W + early V prefetch)
  cudaFuncSetAttribute(ctx_mma, cudaFuncAttributeMaxDynamicSharedMemorySize,
                       CT_SMEM);
  ctx_mma<<<dim3(TSEQ / 128, BATCH * NH), 256, CT_SMEM>>>(wts, ctx);
}

// round 14
// speedup vs baseline: 1.1000x; 1.0434x over previous
#include <cuda_runtime.h>
#include <cuda_bf16.h>
#include <cstdint>

#define BATCH 16
#define TSEQ 512
#define NH 16
#define DK 64
#define DM 1024
#define D3 3072
#define RR 1023  // 2T-1

// ---------------------------------------------------------------------------
// Scratch (allocation-free: device globals)
// ---------------------------------------------------------------------------
__device__ float g_Q[BATCH*NH*TSEQ*DK];
__device__ float g_V[BATCH*NH*TSEQ*DK];

// K and P stored directly as bf16 hi/lo (written by projection epilogues)
__device__ __nv_bfloat16 g_Kh[BATCH*NH*TSEQ*DK];
__device__ __nv_bfloat16 g_Kl[BATCH*NH*TSEQ*DK];
__device__ __nv_bfloat16 g_Ph[NH*RR*DK];
__device__ __nv_bfloat16 g_Pl[NH*RR*DK];

// bf16 hi/lo split operands for projection GEMMs
__device__ __nv_bfloat16 g_Ah[BATCH*TSEQ*DM];
__device__ __nv_bfloat16 g_Al[BATCH*TSEQ*DM];
__device__ __nv_bfloat16 g_Wh[D3*DM];      // qvk_w transposed: [3072][1024]
__device__ __nv_bfloat16 g_Wl[D3*DM];
__device__ __nv_bfloat16 g_pAh[1024*DM];   // pos padded to 1024 rows
__device__ __nv_bfloat16 g_pAl[1024*DM];
__device__ __nv_bfloat16 g_pWh[DM*DM];     // pos_w transposed
__device__ __nv_bfloat16 g_pWl[DM*DM];

// V^T bf16 hi/lo [bh][d][s]
__device__ __nv_bfloat16 g_Vth[(size_t)BATCH*NH*DK*TSEQ];
__device__ __nv_bfloat16 g_Vtl[(size_t)BATCH*NH*DK*TSEQ];

// per-(bh, s-tile, t-row) partial softmax stats: (rowmax, sumexp)
__device__ float2 g_stats[(size_t)BATCH*NH*4*TSEQ];

// ---------------------------------------------------------------------------
// helpers
// ---------------------------------------------------------------------------
__device__ __forceinline__ uint32_t smem_u32(const void* p) {
  uint32_t a;
  asm("{ .reg .u64 t; cvta.to.shared.u64 t, %1; cvt.u32.u64 %0, t; }" : "=r"(a) : "l"(p));
  return a;
}
__device__ __forceinline__ void cp16(uint32_t dst, const void* src) {
  asm volatile("cp.async.cg.shared.global [%0], [%1], 16;" :: "r"(dst), "l"(src));
}
__device__ __forceinline__ void cp16z(uint32_t dst, const void* src, int nbytes) {
  asm volatile("cp.async.cg.shared.global [%0], [%1], 16, %2;"
               :: "r"(dst), "l"(src), "r"(nbytes));
}
__device__ __forceinline__ void cp_commit() {
  asm volatile("cp.async.commit_group;" ::: "memory");
}
__device__ __forceinline__ void ldm4(uint32_t& r0, uint32_t& r1, uint32_t& r2,
                                     uint32_t& r3, uint32_t a) {
  asm volatile("ldmatrix.sync.aligned.m8n8.x4.shared.b16 {%0,%1,%2,%3}, [%4];"
               : "=r"(r0), "=r"(r1), "=r"(r2), "=r"(r3) : "r"(a));
}
__device__ __forceinline__ void mma_bf16(float* c, const uint32_t* a,
                                         uint32_t b0, uint32_t b1) {
  asm volatile(
      "mma.sync.aligned.m16n8k16.row.col.f32.bf16.bf16.f32 "
      "{%0,%1,%2,%3}, {%4,%5,%6,%7}, {%8,%9}, {%0,%1,%2,%3};"
      : "+f"(c[0]), "+f"(c[1]), "+f"(c[2]), "+f"(c[3])
      : "r"(a[0]), "r"(a[1]), "r"(a[2]), "r"(a[3]), "r"(b0), "r"(b1));
}
__device__ __forceinline__ uint32_t pack_bf2(float a, float b) {
  __nv_bfloat16 ha = __float2bfloat16(a), hb = __float2bfloat16(b);
  uint16_t ua = *(uint16_t*)&ha, ub = *(uint16_t*)&hb;
  return (uint32_t)ua | ((uint32_t)ub << 16);
}
__device__ __forceinline__ float bf_res(float v) {
  return v - __bfloat162float(__float2bfloat16(v));
}

// ---------------------------------------------------------------------------
// Merged prep: all 4 split/tsplit jobs in ONE launch.
// ---------------------------------------------------------------------------
__global__ void __launch_bounds__(256) prep_kernel(
    const float* __restrict__ x, const float* __restrict__ qvk_w,
    const float* __restrict__ pos, const float* __restrict__ pos_w) {
  __shared__ float t[32][33];
  const int bid = blockIdx.x;
  const int tid = threadIdx.x;
  if (bid < 2048) {  // split x
    const int n = BATCH * TSEQ * DM;
    for (int i = bid * 256 + tid; i < n; i += 2048 * 256) {
      float v = x[i];
      __nv_bfloat16 h = __float2bfloat16(v);
      g_Ah[i] = h;
      g_Al[i] = __float2bfloat16(v - __bfloat162float(h));
    }
  } else if (bid < 5120) {  // tsplit qvk_w: R=1024 C=3072
    const int r = bid - 2048;
    const int c0 = (r % 96) * 32, r0 = (r / 96) * 32;
    const int tx = tid & 31, ty = tid >> 5;
#pragma unroll
    for (int i = 0; i < 4; i++)
      t[ty + i * 8][tx] = qvk_w[(size_t)(r0 + ty + i * 8) * D3 + c0 + tx];
    __syncthreads();
#pragma unroll
    for (int i = 0; i < 4; i++) {
      float v = t[tx][ty + i * 8];
      __nv_bfloat16 h = __float2bfloat16(v);
      size_t o = (size_t)(c0 + ty + i * 8) * DM + r0 + tx;
      g_Wh[o] = h;
      g_Wl[o] = __float2bfloat16(v - __bfloat162float(h));
    }
  } else if (bid < 5376) {  // split pos (pad to 1024 rows)
    const int r = bid - 5120;
    const int n = RR * DM, ntot = 1024 * DM;
    for (int i = r * 256 + tid; i < ntot; i += 256 * 256) {
      float v = (i < n) ? pos[i] : 0.f;
      __nv_bfloat16 h = __float2bfloat16(v);
      g_pAh[i] = h;
      g_pAl[i] = __float2bfloat16(v - __bfloat162float(h));
    }
  } else {  // tsplit pos_w: R=1024 C=1024
    const int r = bid - 5376;
    const int c0 = (r % 32) * 32, r0 = (r / 32) * 32;
    const int tx = tid & 31, ty = tid >> 5;
#pragma unroll
    for (int i = 0; i < 4; i++)
      t[ty + i * 8][tx] = pos_w[(size_t)(r0 + ty + i * 8) * DM + c0 + tx];
    __syncthreads();
#pragma unroll
    for (int i = 0; i < 4; i++) {
      float v = t[tx][ty + i * 8];
      __nv_bfloat16 h = __float2bfloat16(v);
      size_t o = (size_t)(c0 + ty + i * 8) * DM + r0 + tx;
      g_pWh[o] = h;
      g_pWl[o] = __float2bfloat16(v - __bfloat162float(h));
    }
  }
}

// ---------------------------------------------------------------------------
// Merged projection GEMMs (QKV + pos), tile 128x256, 512 threads (16 warps).
// ---------------------------------------------------------------------------
#define PBUF 98304
#define OFF_AH 0
#define OFF_AL 16384
#define OFF_BH 32768
#define OFF_BL 65536
#define GSMEM (2 * PBUF)  // 196608

__global__ void __launch_bounds__(512, 1) mma_gemm_all(const float* __restrict__ bias) {
  extern __shared__ char smem[];
  const uint32_t sb = smem_u32(smem);
  const int tid = threadIdx.x;
  const int wid = tid >> 5, lane = tid & 31;
  const int bid = blockIdx.x;
  const bool qkv = bid < 768;
  int n0, m0;
  const __nv_bfloat16 *Ah, *Al, *Bh, *Bl;
  if (qkv) {
    n0 = (bid % 12) * 256; m0 = (bid / 12) * 128;
    Ah = g_Ah; Al = g_Al; Bh = g_Wh; Bl = g_Wl;
  } else {
    const int r = bid - 768;
    n0 = (r % 4) * 256; m0 = (r / 4) * 128;
    Ah = g_pAh; Al = g_pAl; Bh = g_pWh; Bl = g_pWl;
  }
  const int wm = wid & 3;
  const int wn = wid >> 2;

  const int gr = tid >> 3;
  const int gc = tid & 7;
  const uint32_t gsw = (uint32_t)((gc * 16) ^ ((gr & 7) << 4));

  const int l7 = lane & 7;
  const uint32_t xa = (uint32_t)(l7 << 4);
  const int rowA0 = wm * 32 + l7 + (((lane >> 3) & 1) << 3);
  const uint32_t kadd_a = (uint32_t)(((lane >> 4) & 1) << 4);
  const int rowB0 = wn * 64 + l7 + (((lane >> 4) & 1) << 3);
  const uint32_t kadd_b = (uint32_t)(((lane >> 3) & 1) << 4);

  float acc[2][8][4];
#pragma unroll
  for (int mt = 0; mt < 2; mt++)
#pragma unroll
    for (int nt = 0; nt < 8; nt++)
#pragma unroll
      for (int i = 0; i < 4; i++) acc[mt][nt][i] = 0.f;

  auto load_chunk = [&](int kc, int buf) {
    const int k0 = kc * 64;
    const uint32_t base = sb + buf * PBUF;
#pragma unroll
    for (int it = 0; it < 2; it++) {
      const int r = gr + it * 64;
      const uint32_t sw = (uint32_t)(r * 128) + gsw;
      const size_t asrc = (size_t)(m0 + r) * DM + k0 + gc * 8;
      cp16(base + OFF_AH + sw, Ah + asrc);
      cp16(base + OFF_AL + sw, Al + asrc);
    }
#pragma unroll
    for (int it = 0; it < 4; it++) {
      const int r = gr + it * 64;
      const uint32_t sw = (uint32_t)(r * 128) + gsw;
      const size_t bsrc = (size_t)(n0 + r) * DM + k0 + gc * 8;
      cp16(base + OFF_BH + sw, Bh + bsrc);
      cp16(base + OFF_BL + sw, Bl + bsrc);
    }
    cp_commit();
  };

  load_chunk(0, 0);

  for (int kc = 0; kc < 16; kc++) {
    if (kc + 1 < 16) {
      load_chunk(kc + 1, (kc + 1) & 1);
      asm volatile("cp.async.wait_group 1;" ::: "memory");
    } else {
      asm volatile("cp.async.wait_group 0;" ::: "memory");
    }
    __syncthreads();

    const uint32_t bb = sb + (kc & 1) * PBUF;
#pragma unroll
    for (int ks = 0; ks < 4; ks++) {
      const uint32_t kba = (uint32_t)(ks * 32);
      uint32_t ah[2][4], al[2][4];
#pragma unroll
      for (int mt = 0; mt < 2; mt++) {
        const uint32_t aoff = (uint32_t)((rowA0 + mt * 16) * 128) + ((kba + kadd_a) ^ xa);
        ldm4(ah[mt][0], ah[mt][1], ah[mt][2], ah[mt][3], bb + OFF_AH + aoff);
        ldm4(al[mt][0], al[mt][1], al[mt][2], al[mt][3], bb + OFF_AL + aoff);
      }
#pragma unroll
      for (int np = 0; np < 4; np++) {
        const uint32_t boff = (uint32_t)((rowB0 + np * 16) * 128) + ((kba + kadd_b) ^ xa);
        uint32_t bh[4], bl[4];
        ldm4(bh[0], bh[1], bh[2], bh[3], bb + OFF_BH + boff);
        ldm4(bl[0], bl[1], bl[2], bl[3], bb + OFF_BL + boff);
#pragma unroll
        for (int mt = 0; mt < 2; mt++) {
          mma_bf16(acc[mt][2 * np + 0], ah[mt], bh[0], bh[1]);
          mma_bf16(acc[mt][2 * np + 1], ah[mt], bh[2], bh[3]);
          mma_bf16(acc[mt][2 * np + 0], ah[mt], bl[0], bl[1]);
          mma_bf16(acc[mt][2 * np + 1], ah[mt], bl[2], bl[3]);
          mma_bf16(acc[mt][2 * np + 0], al[mt], bh[0], bh[1]);
          mma_bf16(acc[mt][2 * np + 1], al[mt], bh[2], bh[3]);
        }
      }
    }
    __syncthreads();
  }

  const int mrow = m0 + wm * 32 + (lane >> 2);
#pragma unroll
  for (int mt = 0; mt < 2; mt++) {
#pragma unroll
    for (int half = 0; half < 2; half++) {
      const int m = mrow + mt * 16 + half * 8;
#pragma unroll
      for (int nt = 0; nt < 8; nt++) {
        const int n = n0 + wn * 64 + nt * 8 + (lane & 3) * 2;
        float2 o;
        o.x = acc[mt][nt][half * 2 + 0];
        o.y = acc[mt][nt][half * 2 + 1];
        if (qkv) {
          o.x += bias[n];
          o.y += bias[n + 1];
          const int b = m >> 9, t = m & 511;
          const int sec = n >> 10;
          const int h = (n >> 6) & 15;
          const int d = n & 63;
          const size_t idx = ((size_t)(b * NH + h) * TSEQ + t) * DK + d;
          if (sec == 0) {
            *(float2*)(g_Q + idx) = o;
          } else if (sec == 1) {
            *(uint32_t*)&g_Kh[idx] = pack_bf2(o.x, o.y);
            *(uint32_t*)&g_Kl[idx] = pack_bf2(bf_res(o.x), bf_res(o.y));
          } else {
            *(float2*)(g_V + idx) = o;
          }
        } else {
          if (m < RR) {
            const int h = n >> 6;
            const int d = n & 63;
            const size_t idx = ((size_t)h * RR + m) * DK + d;
            *(uint32_t*)&g_Ph[idx] = pack_bf2(o.x, o.y);
            *(uint32_t*)&g_Pl[idx] = pack_bf2(bf_res(o.x), bf_res(o.y));
          }
        }
      }
    }
  }
}

// ---------------------------------------------------------------------------
// Scores (+ merged vtsplit tail): grid (4, 8, 320).
// Also emits per-(row, s-tile) partial softmax stats (max, sumexp).
// ---------------------------------------------------------------------------
#define SC_QUH 0
#define SC_QUL 8192
#define SC_QVH 16384
#define SC_QVL 24576
#define SC_KH  32768
#define SC_KL  49152
#define SC_PH  65536
#define SC_PL  90112
#define SC_SMEM 114688
#define SC_BDW 196
#define SC_STATS 53248  // after BDs (64*196*4 = 50176); within operand alias zone

__global__ void __launch_bounds__(256, 2) scores_mma(
    const float* __restrict__ pu, const float* __restrict__ pv,
    float* __restrict__ wout) {
  extern __shared__ char smem[];
  const uint32_t sb = smem_u32(smem);
  const int tid = threadIdx.x;

  if (blockIdx.z >= 256) {
    // ---- vtsplit job
    float (*t)[65] = (float(*)[65])smem;
    const int job = (blockIdx.z - 256) * 32 + blockIdx.y * 4 + blockIdx.x;
    const int vbh = job >> 3;
    const int vs0 = (job & 7) * 64;
    const float* vbase = g_V + (size_t)vbh * TSEQ * DK;
    for (int i = tid; i < 4096; i += 256) {
      const int sl = i >> 6, d = i & 63;
      t[sl][d] = vbase[(size_t)(vs0 + sl) * DK + d];
    }
    __syncthreads();
    for (int i = tid; i < 2048; i += 256) {
      const int d = i >> 5, sl = (i & 31) * 2;
      const float v0 = t[sl][d], v1 = t[sl + 1][d];
      const size_t o = ((size_t)vbh * DK + d) * TSEQ + vs0 + sl;
      *(uint32_t*)&g_Vth[o] = pack_bf2(v0, v1);
      *(uint32_t*)&g_Vtl[o] = pack_bf2(bf_res(v0), bf_res(v1));
    }
    return;
  }

  float* BDs = (float*)smem;                     // aliased after mma phase
  float2* STATS = (float2*)(smem + SC_STATS);    // [64 rows][2 wn]
  const int wid = tid >> 5, lane = tid & 31;
  const int s0 = blockIdx.x * 128;
  const int t0 = blockIdx.y * 64;
  const int bh = blockIdx.z, h = bh & 15;
  const int relbase = s0 - t0 + 448;

  // ---- cp.async K tiles (128 rows x 128B, hi+lo)
  {
    const __nv_bfloat16* Kh = g_Kh + ((size_t)bh * TSEQ + s0) * DK;
    const __nv_bfloat16* Kl = g_Kl + ((size_t)bh * TSEQ + s0) * DK;
#pragma unroll
    for (int it = 0; it < 4; it++) {
      const int idx = tid + it * 256;
      const int row = idx >> 3, ch = idx & 7;
      const uint32_t sw = (uint32_t)(row * 128) + ((uint32_t)(ch * 16) ^ ((uint32_t)(row & 7) << 4));
      cp16(sb + SC_KH + sw, Kh + row * DK + ch * 8);
      cp16(sb + SC_KL + sw, Kl + row * DK + ch * 8);
    }
  }
  // ---- cp.async P band (192 rows x 128B, hi+lo), zero-fill out of range
  {
    const __nv_bfloat16* Ph = g_Ph + (size_t)h * RR * DK;
    const __nv_bfloat16* Pl = g_Pl + (size_t)h * RR * DK;
#pragma unroll
    for (int it = 0; it < 6; it++) {
      const int idx = tid + it * 256;
      const int row = idx >> 3, ch = idx & 7;
      const int r = relbase + row;
      const int rc = r < 0 ? 0 : (r >= RR ? RR - 1 : r);
      const int ok = (r >= 0 && r < RR) ? 16 : 0;
      const uint32_t sw = (uint32_t)(row * 128) + ((uint32_t)(ch * 16) ^ ((uint32_t)(row & 7) << 4));
      cp16z(sb + SC_PH + sw, Ph + (size_t)rc * DK + ch * 8, ok);
      cp16z(sb + SC_PL + sw, Pl + (size_t)rc * DK + ch * 8, ok);
    }
  }
  cp_commit();

  // ---- Q fill: fp32 + posu/posv, convert to bf16 hi/lo (overlaps cp.async)
  {
    const int frow = tid >> 4;
    const int c4 = (tid & 15) * 4;
    const uint32_t cb = (uint32_t)(c4 * 2);
    const float4 pu4 = *(const float4*)(pu + h * 64 + c4);
    const float4 pv4 = *(const float4*)(pv + h * 64 + c4);
    const float* qb = g_Q + ((size_t)bh * TSEQ + t0) * DK;
#pragma unroll
    for (int it = 0; it < 4; it++) {
      const int row = frow + it * 16;
      const float4 q = *(const float4*)(qb + (size_t)row * DK + c4);
      const uint32_t sw = (uint32_t)(row * 128) + (cb ^ ((uint32_t)(row & 7) << 4));
      float ux = q.x + pu4.x, uy = q.y + pu4.y, uz = q.z + pu4.z, uw = q.w + pu4.w;
      float vx = q.x + pv4.x, vy = q.y + pv4.y, vz = q.z + pv4.z, vw = q.w + pv4.w;
      uint2 hh, ll;
      hh.x = pack_bf2(ux, uy); hh.y = pack_bf2(uz, uw);
      ll.x = pack_bf2(bf_res(ux), bf_res(uy));
      ll.y = pack_bf2(bf_res(uz), bf_res(uw));
      *(uint2*)(smem + SC_QUH + sw) = hh;
      *(uint2*)(smem + SC_QUL + sw) = ll;
      hh.x = pack_bf2(vx, vy); hh.y = pack_bf2(vz, vw);
      ll.x = pack_bf2(bf_res(vx), bf_res(vy));
      ll.y = pack_bf2(bf_res(vz), bf_res(vw));
      *(uint2*)(smem + SC_QVH + sw) = hh;
      *(uint2*)(smem + SC_QVL + sw) = ll;
    }
  }
  asm volatile("cp.async.wait_group 0;" ::: "memory");
  __syncthreads();

  // ---- mma: 8 warps = 4 (t) x 2 (s/band)
  const int wm = wid & 3;
  const int wn = wid >> 2;
  const int l7 = lane & 7;
  const uint32_t xa = (uint32_t)(l7 << 4);
  const int rowA = wm * 16 + l7 + (((lane >> 3) & 1) << 3);
  const uint32_t kadd_a = (uint32_t)(((lane >> 4) & 1) << 4);
  const int rbB = l7 + (((lane >> 4) & 1) << 3);
  const uint32_t kadd_b = (uint32_t)(((lane >> 3) & 1) << 4);

  float ac[8][4], bd[12][4];
#pragma unroll
  for (int nt = 0; nt < 8; nt++)
#pragma unroll
    for (int i = 0; i < 4; i++) ac[nt][i] = 0.f;
#pragma unroll
  for (int nt = 0; nt < 12; nt++)
#pragma unroll
    for (int i = 0; i < 4; i++) bd[nt][i] = 0.f;

#pragma unroll
  for (int ks = 0; ks < 4; ks++) {
    const uint32_t kba = (uint32_t)(ks * 32);
    const uint32_t aoff = (uint32_t)(rowA * 128) + ((kba + kadd_a) ^ xa);
    uint32_t quh[4], qul[4], qvh[4], qvl[4];
    ldm4(quh[0], quh[1], quh[2], quh[3], sb + SC_QUH + aoff);
    ldm4(qul[0], qul[1], qul[2], qul[3], sb + SC_QUL + aoff);
    ldm4(qvh[0], qvh[1], qvh[2], qvh[3], sb + SC_QVH + aoff);
    ldm4(qvl[0], qvl[1], qvl[2], qvl[3], sb + SC_QVL + aoff);
#pragma unroll
    for (int np = 0; np < 4; np++) {
      const int rowB = wn * 64 + np * 16 + rbB;
      const uint32_t boff = (uint32_t)(rowB * 128) + ((kba + kadd_b) ^ xa);
      uint32_t kh[4], kl[4];
      ldm4(kh[0], kh[1], kh[2], kh[3], sb + SC_KH + boff);
      ldm4(kl[0], kl[1], kl[2], kl[3], sb + SC_KL + boff);
      mma_bf16(ac[2 * np + 0], quh, kh[0], kh[1]);
      mma_bf16(ac[2 * np + 1], quh, kh[2], kh[3]);
      mma_bf16(ac[2 * np + 0], quh, kl[0], kl[1]);
      mma_bf16(ac[2 * np + 1], quh, kl[2], kl[3]);
      mma_bf16(ac[2 * np + 0], qul, kh[0], kh[1]);
      mma_bf16(ac[2 * np + 1], qul, kh[2], kh[3]);
    }
#pragma unroll
    for (int np = 0; np < 6; np++) {
      const int rowB = wn * 96 + np * 16 + rbB;
      const uint32_t boff = (uint32_t)(rowB * 128) + ((kba + kadd_b) ^ xa);
      uint32_t ph[4], pl[4];
      ldm4(ph[0], ph[1], ph[2], ph[3], sb + SC_PH + boff);
      ldm4(pl[0], pl[1], pl[2], pl[3], sb + SC_PL + boff);
      mma_bf16(bd[2 * np + 0], qvh, ph[0], ph[1]);
      mma_bf16(bd[2 * np + 1], qvh, ph[2], ph[3]);
      mma_bf16(bd[2 * np + 0], qvh, pl[0], pl[1]);
      mma_bf16(bd[2 * np + 1], qvh, pl[2], pl[3]);
      mma_bf16(bd[2 * np + 0], qvl, ph[0], ph[1]);
      mma_bf16(bd[2 * np + 1], qvl, ph[2], ph[3]);
    }
  }
  __syncthreads();  // operand smem dead; safe to alias with BDs/STATS

  // ---- BD -> smem (stride 196 floats)
  const int r0w = wm * 16 + (lane >> 2);
#pragma unroll
  for (int nt = 0; nt < 12; nt++) {
    const int col = wn * 96 + nt * 8 + (lane & 3) * 2;
    *(float2*)&BDs[r0w * SC_BDW + col] = make_float2(bd[nt][0], bd[nt][1]);
    *(float2*)&BDs[(r0w + 8) * SC_BDW + col] = make_float2(bd[nt][2], bd[nt][3]);
  }
  __syncthreads();

  // ---- epilogue: out = (AC + shifted BD) / 8 ; per-row partial (max, sumexp)
  float* wbase = wout + ((size_t)bh * TSEQ + t0) * TSEQ + s0;
#pragma unroll
  for (int half = 0; half < 2; half++) {
    const int row = r0w + half * 8;
    float v[16];
    float mx = -1e30f;
#pragma unroll
    for (int nt = 0; nt < 8; nt++) {
      const int col = wn * 64 + nt * 8 + (lane & 3) * 2;
      const int bdi = row * SC_BDW + col - row + 63;
      v[2 * nt + 0] = (ac[nt][half * 2 + 0] + BDs[bdi]) * 0.125f;
      v[2 * nt + 1] = (ac[nt][half * 2 + 1] + BDs[bdi + 1]) * 0.125f;
      *(float2*)(wbase + (size_t)row * TSEQ + col) =
          make_float2(v[2 * nt + 0], v[2 * nt + 1]);
      mx = fmaxf(mx, fmaxf(v[2 * nt + 0], v[2 * nt + 1]));
    }
    // quad reduce across the 4 lanes sharing this row
    mx = fmaxf(mx, __shfl_xor_sync(0xffffffffu, mx, 1));
    mx = fmaxf(mx, __shfl_xor_sync(0xffffffffu, mx, 2));
    float se = 0.f;
#pragma unroll
    for (int k = 0; k < 16; k++) se += __expf(v[k] - mx);
    se += __shfl_xor_sync(0xffffffffu, se, 1);
    se += __shfl_xor_sync(0xffffffffu, se, 2);
    if ((lane & 3) == 0) STATS[row * 2 + wn] = make_float2(mx, se);
  }
  __syncthreads();

  // merge 2 warp-halves per row, store to global stats
  if (tid < 64) {
    const float2 a = STATS[tid * 2 + 0];
    const float2 b = STATS[tid * 2 + 1];
    const float m = fmaxf(a.x, b.x);
    const float s = a.y * __expf(a.x - m) + b.y * __expf(b.x - m);
    g_stats[((size_t)bh * 4 + blockIdx.x) * TSEQ + t0 + tid] = make_float2(m, s);
  }
}

// ---------------------------------------------------------------------------
// Context GEMM + softmax finalize:
//   merge per-row stats, normalize raw scores on the fly (exp(v-m)/S),
//   write normalized weights (output), and ctx = W @ Vt via bf16x3 mma.
// ---------------------------------------------------------------------------
#define CT_WF 0        // 128 x 64 f32 staging (linear, 256B rows), 32KB
#define CT_WH 32768    // converted W hi (swizzled), 16KB
#define CT_WL 49152    // converted W lo, 16KB
#define CT_V  65536    // V buffers: +buf*16384; hi at +0 (8KB), lo at +8192
#define CT_MS 98304    // m[128], invS[128]
#define CT_SMEM 99328

__global__ void __launch_bounds__(256, 2) ctx_mma(
    float* __restrict__ wts, float* __restrict__ ctx) {
  extern __shared__ char smem[];
  const uint32_t sb = smem_u32(smem);
  const int tid = threadIdx.x;
  const int wid = tid >> 5, lane = tid & 31;
  const int t0 = blockIdx.x * 128;
  const int bh = blockIdx.y;
  const int b = bh >> 4, h = bh & 15;

  float* Wf = wts + ((size_t)bh * TSEQ + t0) * TSEQ;
  const __nv_bfloat16* Vh = g_Vth + (size_t)bh * DK * TSEQ;
  const __nv_bfloat16* Vl = g_Vtl + (size_t)bh * DK * TSEQ;
  float* MS = (float*)(smem + CT_MS);

  const int wm = wid & 3;
  const int wn = wid >> 2;
  const int l7 = lane & 7;
  const uint32_t xa = (uint32_t)(l7 << 4);
  const int rowA0 = wm * 32 + l7 + (((lane >> 3) & 1) << 3);
  const uint32_t kadd_a = (uint32_t)(((lane >> 4) & 1) << 4);
  const int rowB0 = wn * 32 + l7 + (((lane >> 4) & 1) << 3);
  const uint32_t kadd_b = (uint32_t)(((lane >> 3) & 1) << 4);

  float acc[2][4][4];
#pragma unroll
  for (int mt = 0; mt < 2; mt++)
#pragma unroll
    for (int nt = 0; nt < 4; nt++)
#pragma unroll
      for (int i = 0; i < 4; i++) acc[mt][nt][i] = 0.f;

  auto load_wf = [&](int kc) {
    const int k0 = kc * 64;
#pragma unroll
    for (int it = 0; it < 8; it++) {
      const int idx = tid + it * 256;
      const int row = idx >> 4, seg = idx & 15;
      cp16(sb + CT_WF + (uint32_t)(row * 256 + seg * 16),
           Wf + (size_t)row * TSEQ + k0 + seg * 4);
    }
  };
  auto load_v = [&](int kc, int buf) {
    const int k0 = kc * 64;
    const uint32_t vb = sb + CT_V + (uint32_t)(buf * 16384);
#pragma unroll
    for (int it = 0; it < 2; it++) {
      const int idx = tid + it * 256;
      const int row = idx >> 3, ch = idx & 7;
      const uint32_t sw = (uint32_t)(row * 128) + ((uint32_t)(ch * 16) ^ ((uint32_t)(row & 7) << 4));
      cp16(vb + sw, Vh + (size_t)row * TSEQ + k0 + ch * 8);
      cp16(vb + 8192 + sw, Vl + (size_t)row * TSEQ + k0 + ch * 8);
    }
  };

  load_wf(0);
  load_v(0, 0);
  cp_commit();

  // merge per-row softmax stats (4 s-tiles) -> m, 1/S
  if (tid < 128) {
    const int t = t0 + tid;
    const float2 p0 = g_stats[((size_t)bh * 4 + 0) * TSEQ + t];
    const float2 p1 = g_stats[((size_t)bh * 4 + 1) * TSEQ + t];
    const float2 p2 = g_stats[((size_t)bh * 4 + 2) * TSEQ + t];
    const float2 p3 = g_stats[((size_t)bh * 4 + 3) * TSEQ + t];
    const float m = fmaxf(fmaxf(p0.x, p1.x), fmaxf(p2.x, p3.x));
    const float S = p0.y * __expf(p0.x - m) + p1.y * __expf(p1.x - m) +
                    p2.y * __expf(p2.x - m) + p3.y * __expf(p3.x - m);
    MS[tid] = m;
    MS[128 + tid] = 1.0f / S;
  }

  for (int kc = 0; kc < 8; kc++) {
    asm volatile("cp.async.wait_group 0;" ::: "memory");
    __syncthreads();  // staging + V + stats visible; prev mma done with WH/WL

    if (kc + 1 < 8) {
      load_v(kc + 1, (kc + 1) & 1);
      cp_commit();
    }

    // normalize + convert W f32 -> bf16 hi/lo swizzled; write weights output
#pragma unroll
    for (int it = 0; it < 8; it++) {
      const int idx = tid + it * 256;
      const int r = idx >> 4, q = idx & 15;
      float4 wv = *(const float4*)(smem + CT_WF + r * 256 + q * 16);
      const float mr = MS[r], is = MS[128 + r];
      wv.x = __expf(wv.x - mr) * is;
      wv.y = __expf(wv.y - mr) * is;
      wv.z = __expf(wv.z - mr) * is;
      wv.w = __expf(wv.w - mr) * is;
      *(float4*)(Wf + (size_t)r * TSEQ + kc * 64 + q * 4) = wv;
      const uint32_t sw = (uint32_t)(r * 128) + ((uint32_t)(q * 8) ^ ((uint32_t)(r & 7) << 4));
      uint2 hh, ll;
      hh.x = pack_bf2(wv.x, wv.y); hh.y = pack_bf2(wv.z, wv.w);
      ll.x = pack_bf2(bf_res(wv.x), bf_res(wv.y));
      ll.y = pack_bf2(bf_res(wv.z), bf_res(wv.w));
      *(uint2*)(smem + CT_WH + sw) = hh;
      *(uint2*)(smem + CT_WL + sw) = ll;
    }
    __syncthreads();

    if (kc + 1 < 8) {
      load_wf(kc + 1);
      cp_commit();
    }

    const uint32_t vb = sb + CT_V + (uint32_t)((kc & 1) * 16384);
#pragma unroll
    for (int ks = 0; ks < 4; ks++) {
      const uint32_t kba = (uint32_t)(ks * 32);
      uint32_t ah[2][4], al[2][4];
#pragma unroll
      for (int mt = 0; mt < 2; mt++) {
        const uint32_t aoff = (uint32_t)((rowA0 + mt * 16) * 128) + ((kba + kadd_a) ^ xa);
        ldm4(ah[mt][0], ah[mt][1], ah[mt][2], ah[mt][3], sb + CT_WH + aoff);
        ldm4(al[mt][0], al[mt][1], al[mt][2], al[mt][3], sb + CT_WL + aoff);
      }
#pragma unroll
      for (int np = 0; np < 2; np++) {
        const uint32_t boff = (uint32_t)((rowB0 + np * 16) * 128) + ((kba + kadd_b) ^ xa);
        uint32_t vhh[4], vll[4];
        ldm4(vhh[0], vhh[1], vhh[2], vhh[3], vb + boff);
        ldm4(vll[0], vll[1], vll[2], vll[3], vb + 8192 + boff);
#pragma unroll
        for (int mt = 0; mt < 2; mt++) {
          mma_bf16(acc[mt][2 * np + 0], ah[mt], vhh[0], vhh[1]);
          mma_bf16(acc[mt][2 * np + 1], ah[mt], vhh[2], vhh[3]);
          mma_bf16(acc[mt][2 * np + 0], ah[mt], vll[0], vll[1]);
          mma_bf16(acc[mt][2 * np + 1], ah[mt], vll[2], vll[3]);
          mma_bf16(acc[mt][2 * np + 0], al[mt], vhh[0], vhh[1]);
          mma_bf16(acc[mt][2 * np + 1], al[mt], vhh[2], vhh[3]);
        }
      }
    }
  }

  const int mrow = t0 + wm * 32 + (lane >> 2);
#pragma unroll
  for (int mt = 0; mt < 2; mt++) {
#pragma unroll
    for (int half = 0; half < 2; half++) {
      const int t = mrow + mt * 16 + half * 8;
#pragma unroll
      for (int nt = 0; nt < 4; nt++) {
        const int d = wn * 32 + nt * 8 + (lane & 3) * 2;
        float2 o;
        o.x = acc[mt][nt][half * 2 + 0];
        o.y = acc[mt][nt][half * 2 + 1];
        *(float2*)(ctx + ((size_t)b * TSEQ + t) * DM + h * DK + d) = o;
      }
    }
  }
}

// ---------------------------------------------------------------------------
// Launch
// ---------------------------------------------------------------------------
extern "C" void kernel_launch(void* const* d_in, const int* in_sizes, int n_in,
                              void* d_out, int out_size) {
  const float* x     = (const float*)d_in[0];
  const float* pos   = (const float*)d_in[2];
  const float* qvk_w = (const float*)d_in[3];
  const float* qvk_b = (const float*)d_in[4];
  const float* pos_w = (const float*)d_in[5];
  const float* posu  = (const float*)d_in[6];
  const float* posv  = (const float*)d_in[7];

  float* ctx = (float*)d_out;
  float* wts = (float*)d_out + (size_t)BATCH * TSEQ * DM;

  // 0) merged prep (all bf16 hi/lo splits)
  prep_kernel<<<6400, 256>>>(x, qvk_w, pos, pos_w);

  // 1) merged projection GEMMs, tile 128x256 (QKV 768 + pos 32 tiles)
  cudaFuncSetAttribute(mma_gemm_all, cudaFuncAttributeMaxDynamicSharedMemorySize,
                       GSMEM);
  mma_gemm_all<<<800, 512, GSMEM>>>(qvk_b);

  // 2) scores (+ vtsplit + per-row partial softmax stats) -> weights region
  cudaFuncSetAttribute(scores_mma, cudaFuncAttributeMaxDynamicSharedMemorySize,
                       SC_SMEM);
  scores_mma<<<dim3(4, 8, 320), 256, SC_SMEM>>>(posu, posv, wts);

  // 3) context + softmax finalize (normalizes weights in place, writes output)
  cudaFuncSetAttribute(ctx_mma, cudaFuncAttributeMaxDynamicSharedMemorySize,
                       CT_SMEM);
  ctx_mma<<<dim3(TSEQ / 128, BATCH * NH), 256, CT_SMEM>>>(wts, ctx);
}

// round 15
// speedup vs baseline: 1.1005x; 1.0004x over previous
#include <cuda_runtime.h>
#include <cuda_bf16.h>
#include <cstdint>

#define BATCH 16
#define TSEQ 512
#define NH 16
#define DK 64
#define DM 1024
#define D3 3072
#define RR 1023  // 2T-1

// ---------------------------------------------------------------------------
// Scratch (allocation-free: device globals)
// ---------------------------------------------------------------------------
__device__ float g_Q[BATCH*NH*TSEQ*DK];
__device__ float g_V[BATCH*NH*TSEQ*DK];

// K and P stored directly as bf16 hi/lo (written by projection epilogues)
__device__ __nv_bfloat16 g_Kh[BATCH*NH*TSEQ*DK];
__device__ __nv_bfloat16 g_Kl[BATCH*NH*TSEQ*DK];
__device__ __nv_bfloat16 g_Ph[NH*RR*DK];
__device__ __nv_bfloat16 g_Pl[NH*RR*DK];

// bf16 hi/lo split operands for projection GEMMs
__device__ __nv_bfloat16 g_Ah[BATCH*TSEQ*DM];
__device__ __nv_bfloat16 g_Al[BATCH*TSEQ*DM];
__device__ __nv_bfloat16 g_Wh[D3*DM];      // qvk_w transposed: [3072][1024]
__device__ __nv_bfloat16 g_Wl[D3*DM];
__device__ __nv_bfloat16 g_pAh[1024*DM];   // pos padded to 1024 rows
__device__ __nv_bfloat16 g_pAl[1024*DM];
__device__ __nv_bfloat16 g_pWh[DM*DM];     // pos_w transposed
__device__ __nv_bfloat16 g_pWl[DM*DM];

// V^T bf16 hi/lo [bh][d][s]
__device__ __nv_bfloat16 g_Vth[(size_t)BATCH*NH*DK*TSEQ];
__device__ __nv_bfloat16 g_Vtl[(size_t)BATCH*NH*DK*TSEQ];

// per-(bh, s-tile, t-row) partial softmax stats: (rowmax, sumexp)
__device__ float2 g_stats[(size_t)BATCH*NH*4*TSEQ];

// ---------------------------------------------------------------------------
// helpers
// ---------------------------------------------------------------------------
__device__ __forceinline__ uint32_t smem_u32(const void* p) {
  uint32_t a;
  asm("{ .reg .u64 t; cvta.to.shared.u64 t, %1; cvt.u32.u64 %0, t; }" : "=r"(a) : "l"(p));
  return a;
}
__device__ __forceinline__ void cp16(uint32_t dst, const void* src) {
  asm volatile("cp.async.cg.shared.global [%0], [%1], 16;" :: "r"(dst), "l"(src));
}
__device__ __forceinline__ void cp16z(uint32_t dst, const void* src, int nbytes) {
  asm volatile("cp.async.cg.shared.global [%0], [%1], 16, %2;"
               :: "r"(dst), "l"(src), "r"(nbytes));
}
__device__ __forceinline__ void cp_commit() {
  asm volatile("cp.async.commit_group;" ::: "memory");
}
__device__ __forceinline__ void ldm4(uint32_t& r0, uint32_t& r1, uint32_t& r2,
                                     uint32_t& r3, uint32_t a) {
  asm volatile("ldmatrix.sync.aligned.m8n8.x4.shared.b16 {%0,%1,%2,%3}, [%4];"
               : "=r"(r0), "=r"(r1), "=r"(r2), "=r"(r3) : "r"(a));
}
__device__ __forceinline__ void mma_bf16(float* c, const uint32_t* a,
                                         uint32_t b0, uint32_t b1) {
  asm volatile(
      "mma.sync.aligned.m16n8k16.row.col.f32.bf16.bf16.f32 "
      "{%0,%1,%2,%3}, {%4,%5,%6,%7}, {%8,%9}, {%0,%1,%2,%3};"
      : "+f"(c[0]), "+f"(c[1]), "+f"(c[2]), "+f"(c[3])
      : "r"(a[0]), "r"(a[1]), "r"(a[2]), "r"(a[3]), "r"(b0), "r"(b1));
}
__device__ __forceinline__ uint32_t pack_bf2(float a, float b) {
  __nv_bfloat16 ha = __float2bfloat16(a), hb = __float2bfloat16(b);
  uint16_t ua = *(uint16_t*)&ha, ub = *(uint16_t*)&hb;
  return (uint32_t)ua | ((uint32_t)ub << 16);
}
__device__ __forceinline__ float bf_res(float v) {
  return v - __bfloat162float(__float2bfloat16(v));
}

// ---------------------------------------------------------------------------
// Merged prep: all 4 split/tsplit jobs in ONE launch.
// ---------------------------------------------------------------------------
__global__ void __launch_bounds__(256) prep_kernel(
    const float* __restrict__ x, const float* __restrict__ qvk_w,
    const float* __restrict__ pos, const float* __restrict__ pos_w) {
  __shared__ float t[32][33];
  const int bid = blockIdx.x;
  const int tid = threadIdx.x;
  if (bid < 2048) {  // split x
    const int n = BATCH * TSEQ * DM;
    for (int i = bid * 256 + tid; i < n; i += 2048 * 256) {
      float v = x[i];
      __nv_bfloat16 h = __float2bfloat16(v);
      g_Ah[i] = h;
      g_Al[i] = __float2bfloat16(v - __bfloat162float(h));
    }
  } else if (bid < 5120) {  // tsplit qvk_w: R=1024 C=3072
    const int r = bid - 2048;
    const int c0 = (r % 96) * 32, r0 = (r / 96) * 32;
    const int tx = tid & 31, ty = tid >> 5;
#pragma unroll
    for (int i = 0; i < 4; i++)
      t[ty + i * 8][tx] = qvk_w[(size_t)(r0 + ty + i * 8) * D3 + c0 + tx];
    __syncthreads();
#pragma unroll
    for (int i = 0; i < 4; i++) {
      float v = t[tx][ty + i * 8];
      __nv_bfloat16 h = __float2bfloat16(v);
      size_t o = (size_t)(c0 + ty + i * 8) * DM + r0 + tx;
      g_Wh[o] = h;
      g_Wl[o] = __float2bfloat16(v - __bfloat162float(h));
    }
  } else if (bid < 5376) {  // split pos (pad to 1024 rows)
    const int r = bid - 5120;
    const int n = RR * DM, ntot = 1024 * DM;
    for (int i = r * 256 + tid; i < ntot; i += 256 * 256) {
      float v = (i < n) ? pos[i] : 0.f;
      __nv_bfloat16 h = __float2bfloat16(v);
      g_pAh[i] = h;
      g_pAl[i] = __float2bfloat16(v - __bfloat162float(h));
    }
  } else {  // tsplit pos_w: R=1024 C=1024
    const int r = bid - 5376;
    const int c0 = (r % 32) * 32, r0 = (r / 32) * 32;
    const int tx = tid & 31, ty = tid >> 5;
#pragma unroll
    for (int i = 0; i < 4; i++)
      t[ty + i * 8][tx] = pos_w[(size_t)(r0 + ty + i * 8) * DM + c0 + tx];
    __syncthreads();
#pragma unroll
    for (int i = 0; i < 4; i++) {
      float v = t[tx][ty + i * 8];
      __nv_bfloat16 h = __float2bfloat16(v);
      size_t o = (size_t)(c0 + ty + i * 8) * DM + r0 + tx;
      g_pWh[o] = h;
      g_pWl[o] = __float2bfloat16(v - __bfloat162float(h));
    }
  }
}

// ---------------------------------------------------------------------------
// Merged projection GEMMs (QKV + pos), tile 128x256, 512 threads (16 warps).
// ---------------------------------------------------------------------------
#define PBUF 98304
#define OFF_AH 0
#define OFF_AL 16384
#define OFF_BH 32768
#define OFF_BL 65536
#define GSMEM (2 * PBUF)  // 196608

__global__ void __launch_bounds__(512, 1) mma_gemm_all(const float* __restrict__ bias) {
  extern __shared__ char smem[];
  const uint32_t sb = smem_u32(smem);
  const int tid = threadIdx.x;
  const int wid = tid >> 5, lane = tid & 31;
  const int bid = blockIdx.x;
  const bool qkv = bid < 768;
  int n0, m0;
  const __nv_bfloat16 *Ah, *Al, *Bh, *Bl;
  if (qkv) {
    n0 = (bid % 12) * 256; m0 = (bid / 12) * 128;
    Ah = g_Ah; Al = g_Al; Bh = g_Wh; Bl = g_Wl;
  } else {
    const int r = bid - 768;
    n0 = (r % 4) * 256; m0 = (r / 4) * 128;
    Ah = g_pAh; Al = g_pAl; Bh = g_pWh; Bl = g_pWl;
  }
  const int wm = wid & 3;
  const int wn = wid >> 2;

  const int gr = tid >> 3;
  const int gc = tid & 7;
  const uint32_t gsw = (uint32_t)((gc * 16) ^ ((gr & 7) << 4));

  const int l7 = lane & 7;
  const uint32_t xa = (uint32_t)(l7 << 4);
  const int rowA0 = wm * 32 + l7 + (((lane >> 3) & 1) << 3);
  const uint32_t kadd_a = (uint32_t)(((lane >> 4) & 1) << 4);
  const int rowB0 = wn * 64 + l7 + (((lane >> 4) & 1) << 3);
  const uint32_t kadd_b = (uint32_t)(((lane >> 3) & 1) << 4);

  float acc[2][8][4];
#pragma unroll
  for (int mt = 0; mt < 2; mt++)
#pragma unroll
    for (int nt = 0; nt < 8; nt++)
#pragma unroll
      for (int i = 0; i < 4; i++) acc[mt][nt][i] = 0.f;

  auto load_chunk = [&](int kc, int buf) {
    const int k0 = kc * 64;
    const uint32_t base = sb + buf * PBUF;
#pragma unroll
    for (int it = 0; it < 2; it++) {
      const int r = gr + it * 64;
      const uint32_t sw = (uint32_t)(r * 128) + gsw;
      const size_t asrc = (size_t)(m0 + r) * DM + k0 + gc * 8;
      cp16(base + OFF_AH + sw, Ah + asrc);
      cp16(base + OFF_AL + sw, Al + asrc);
    }
#pragma unroll
    for (int it = 0; it < 4; it++) {
      const int r = gr + it * 64;
      const uint32_t sw = (uint32_t)(r * 128) + gsw;
      const size_t bsrc = (size_t)(n0 + r) * DM + k0 + gc * 8;
      cp16(base + OFF_BH + sw, Bh + bsrc);
      cp16(base + OFF_BL + sw, Bl + bsrc);
    }
    cp_commit();
  };

  load_chunk(0, 0);

  for (int kc = 0; kc < 16; kc++) {
    if (kc + 1 < 16) {
      load_chunk(kc + 1, (kc + 1) & 1);
      asm volatile("cp.async.wait_group 1;" ::: "memory");
    } else {
      asm volatile("cp.async.wait_group 0;" ::: "memory");
    }
    __syncthreads();

    const uint32_t bb = sb + (kc & 1) * PBUF;
#pragma unroll
    for (int ks = 0; ks < 4; ks++) {
      const uint32_t kba = (uint32_t)(ks * 32);
      uint32_t ah[2][4], al[2][4];
#pragma unroll
      for (int mt = 0; mt < 2; mt++) {
        const uint32_t aoff = (uint32_t)((rowA0 + mt * 16) * 128) + ((kba + kadd_a) ^ xa);
        ldm4(ah[mt][0], ah[mt][1], ah[mt][2], ah[mt][3], bb + OFF_AH + aoff);
        ldm4(al[mt][0], al[mt][1], al[mt][2], al[mt][3], bb + OFF_AL + aoff);
      }
#pragma unroll
      for (int np = 0; np < 4; np++) {
        const uint32_t boff = (uint32_t)((rowB0 + np * 16) * 128) + ((kba + kadd_b) ^ xa);
        uint32_t bh[4], bl[4];
        ldm4(bh[0], bh[1], bh[2], bh[3], bb + OFF_BH + boff);
        ldm4(bl[0], bl[1], bl[2], bl[3], bb + OFF_BL + boff);
#pragma unroll
        for (int mt = 0; mt < 2; mt++) {
          mma_bf16(acc[mt][2 * np + 0], ah[mt], bh[0], bh[1]);
          mma_bf16(acc[mt][2 * np + 1], ah[mt], bh[2], bh[3]);
          mma_bf16(acc[mt][2 * np + 0], ah[mt], bl[0], bl[1]);
          mma_bf16(acc[mt][2 * np + 1], ah[mt], bl[2], bl[3]);
          mma_bf16(acc[mt][2 * np + 0], al[mt], bh[0], bh[1]);
          mma_bf16(acc[mt][2 * np + 1], al[mt], bh[2], bh[3]);
        }
      }
    }
    __syncthreads();
  }

  const int mrow = m0 + wm * 32 + (lane >> 2);
#pragma unroll
  for (int mt = 0; mt < 2; mt++) {
#pragma unroll
    for (int half = 0; half < 2; half++) {
      const int m = mrow + mt * 16 + half * 8;
#pragma unroll
      for (int nt = 0; nt < 8; nt++) {
        const int n = n0 + wn * 64 + nt * 8 + (lane & 3) * 2;
        float2 o;
        o.x = acc[mt][nt][half * 2 + 0];
        o.y = acc[mt][nt][half * 2 + 1];
        if (qkv) {
          o.x += bias[n];
          o.y += bias[n + 1];
          const int b = m >> 9, t = m & 511;
          const int sec = n >> 10;
          const int h = (n >> 6) & 15;
          const int d = n & 63;
          const size_t idx = ((size_t)(b * NH + h) * TSEQ + t) * DK + d;
          if (sec == 0) {
            *(float2*)(g_Q + idx) = o;
          } else if (sec == 1) {
            *(uint32_t*)&g_Kh[idx] = pack_bf2(o.x, o.y);
            *(uint32_t*)&g_Kl[idx] = pack_bf2(bf_res(o.x), bf_res(o.y));
          } else {
            *(float2*)(g_V + idx) = o;
          }
        } else {
          if (m < RR) {
            const int h = n >> 6;
            const int d = n & 63;
            const size_t idx = ((size_t)h * RR + m) * DK + d;
            *(uint32_t*)&g_Ph[idx] = pack_bf2(o.x, o.y);
            *(uint32_t*)&g_Pl[idx] = pack_bf2(bf_res(o.x), bf_res(o.y));
          }
        }
      }
    }
  }
}

// ---------------------------------------------------------------------------
// Scores (+ merged vtsplit tail): grid (4, 8, 320).
// Also emits per-(row, s-tile) partial softmax stats (max, sumexp).
// ---------------------------------------------------------------------------
#define SC_QUH 0
#define SC_QUL 8192
#define SC_QVH 16384
#define SC_QVL 24576
#define SC_KH  32768
#define SC_KL  49152
#define SC_PH  65536
#define SC_PL  90112
#define SC_SMEM 114688
#define SC_BDW 196
#define SC_STATS 53248  // after BDs (64*196*4 = 50176); within operand alias zone

__global__ void __launch_bounds__(256, 2) scores_mma(
    const float* __restrict__ pu, const float* __restrict__ pv,
    float* __restrict__ wout) {
  extern __shared__ char smem[];
  const uint32_t sb = smem_u32(smem);
  const int tid = threadIdx.x;

  if (blockIdx.z >= 256) {
    // ---- vtsplit job
    float (*t)[65] = (float(*)[65])smem;
    const int job = (blockIdx.z - 256) * 32 + blockIdx.y * 4 + blockIdx.x;
    const int vbh = job >> 3;
    const int vs0 = (job & 7) * 64;
    const float* vbase = g_V + (size_t)vbh * TSEQ * DK;
    for (int i = tid; i < 4096; i += 256) {
      const int sl = i >> 6, d = i & 63;
      t[sl][d] = vbase[(size_t)(vs0 + sl) * DK + d];
    }
    __syncthreads();
    for (int i = tid; i < 2048; i += 256) {
      const int d = i >> 5, sl = (i & 31) * 2;
      const float v0 = t[sl][d], v1 = t[sl + 1][d];
      const size_t o = ((size_t)vbh * DK + d) * TSEQ + vs0 + sl;
      *(uint32_t*)&g_Vth[o] = pack_bf2(v0, v1);
      *(uint32_t*)&g_Vtl[o] = pack_bf2(bf_res(v0), bf_res(v1));
    }
    return;
  }

  float* BDs = (float*)smem;                     // aliased after mma phase
  float2* STATS = (float2*)(smem + SC_STATS);    // [64 rows][2 wn]
  const int wid = tid >> 5, lane = tid & 31;
  const int s0 = blockIdx.x * 128;
  const int t0 = blockIdx.y * 64;
  const int bh = blockIdx.z, h = bh & 15;
  const int relbase = s0 - t0 + 448;

  // ---- cp.async K tiles (128 rows x 128B, hi+lo)
  {
    const __nv_bfloat16* Kh = g_Kh + ((size_t)bh * TSEQ + s0) * DK;
    const __nv_bfloat16* Kl = g_Kl + ((size_t)bh * TSEQ + s0) * DK;
#pragma unroll
    for (int it = 0; it < 4; it++) {
      const int idx = tid + it * 256;
      const int row = idx >> 3, ch = idx & 7;
      const uint32_t sw = (uint32_t)(row * 128) + ((uint32_t)(ch * 16) ^ ((uint32_t)(row & 7) << 4));
      cp16(sb + SC_KH + sw, Kh + row * DK + ch * 8);
      cp16(sb + SC_KL + sw, Kl + row * DK + ch * 8);
    }
  }
  // ---- cp.async P band (192 rows x 128B, hi+lo), zero-fill out of range
  {
    const __nv_bfloat16* Ph = g_Ph + (size_t)h * RR * DK;
    const __nv_bfloat16* Pl = g_Pl + (size_t)h * RR * DK;
#pragma unroll
    for (int it = 0; it < 6; it++) {
      const int idx = tid + it * 256;
      const int row = idx >> 3, ch = idx & 7;
      const int r = relbase + row;
      const int rc = r < 0 ? 0 : (r >= RR ? RR - 1 : r);
      const int ok = (r >= 0 && r < RR) ? 16 : 0;
      const uint32_t sw = (uint32_t)(row * 128) + ((uint32_t)(ch * 16) ^ ((uint32_t)(row & 7) << 4));
      cp16z(sb + SC_PH + sw, Ph + (size_t)rc * DK + ch * 8, ok);
      cp16z(sb + SC_PL + sw, Pl + (size_t)rc * DK + ch * 8, ok);
    }
  }
  cp_commit();

  // ---- Q fill: fp32 + posu/posv, convert to bf16 hi/lo (overlaps cp.async)
  {
    const int frow = tid >> 4;
    const int c4 = (tid & 15) * 4;
    const uint32_t cb = (uint32_t)(c4 * 2);
    const float4 pu4 = *(const float4*)(pu + h * 64 + c4);
    const float4 pv4 = *(const float4*)(pv + h * 64 + c4);
    const float* qb = g_Q + ((size_t)bh * TSEQ + t0) * DK;
#pragma unroll
    for (int it = 0; it < 4; it++) {
      const int row = frow + it * 16;
      const float4 q = *(const float4*)(qb + (size_t)row * DK + c4);
      const uint32_t sw = (uint32_t)(row * 128) + (cb ^ ((uint32_t)(row & 7) << 4));
      float ux = q.x + pu4.x, uy = q.y + pu4.y, uz = q.z + pu4.z, uw = q.w + pu4.w;
      float vx = q.x + pv4.x, vy = q.y + pv4.y, vz = q.z + pv4.z, vw = q.w + pv4.w;
      uint2 hh, ll;
      hh.x = pack_bf2(ux, uy); hh.y = pack_bf2(uz, uw);
      ll.x = pack_bf2(bf_res(ux), bf_res(uy));
      ll.y = pack_bf2(bf_res(uz), bf_res(uw));
      *(uint2*)(smem + SC_QUH + sw) = hh;
      *(uint2*)(smem + SC_QUL + sw) = ll;
      hh.x = pack_bf2(vx, vy); hh.y = pack_bf2(vz, vw);
      ll.x = pack_bf2(bf_res(vx), bf_res(vy));
      ll.y = pack_bf2(bf_res(vz), bf_res(vw));
      *(uint2*)(smem + SC_QVH + sw) = hh;
      *(uint2*)(smem + SC_QVL + sw) = ll;
    }
  }
  asm volatile("cp.async.wait_group 0;" ::: "memory");
  __syncthreads();

  // ---- mma: 8 warps = 4 (t) x 2 (s/band)
  const int wm = wid & 3;
  const int wn = wid >> 2;
  const int l7 = lane & 7;
  const uint32_t xa = (uint32_t)(l7 << 4);
  const int rowA = wm * 16 + l7 + (((lane >> 3) & 1) << 3);
  const uint32_t kadd_a = (uint32_t)(((lane >> 4) & 1) << 4);
  const int rbB = l7 + (((lane >> 4) & 1) << 3);
  const uint32_t kadd_b = (uint32_t)(((lane >> 3) & 1) << 4);

  float ac[8][4], bd[12][4];
#pragma unroll
  for (int nt = 0; nt < 8; nt++)
#pragma unroll
    for (int i = 0; i < 4; i++) ac[nt][i] = 0.f;
#pragma unroll
  for (int nt = 0; nt < 12; nt++)
#pragma unroll
    for (int i = 0; i < 4; i++) bd[nt][i] = 0.f;

#pragma unroll
  for (int ks = 0; ks < 4; ks++) {
    const uint32_t kba = (uint32_t)(ks * 32);
    const uint32_t aoff = (uint32_t)(rowA * 128) + ((kba + kadd_a) ^ xa);
    uint32_t quh[4], qul[4], qvh[4], qvl[4];
    ldm4(quh[0], quh[1], quh[2], quh[3], sb + SC_QUH + aoff);
    ldm4(qul[0], qul[1], qul[2], qul[3], sb + SC_QUL + aoff);
    ldm4(qvh[0], qvh[1], qvh[2], qvh[3], sb + SC_QVH + aoff);
    ldm4(qvl[0], qvl[1], qvl[2], qvl[3], sb + SC_QVL + aoff);
#pragma unroll
    for (int np = 0; np < 4; np++) {
      const int rowB = wn * 64 + np * 16 + rbB;
      const uint32_t boff = (uint32_t)(rowB * 128) + ((kba + kadd_b) ^ xa);
      uint32_t kh[4], kl[4];
      ldm4(kh[0], kh[1], kh[2], kh[3], sb + SC_KH + boff);
      ldm4(kl[0], kl[1], kl[2], kl[3], sb + SC_KL + boff);
      mma_bf16(ac[2 * np + 0], quh, kh[0], kh[1]);
      mma_bf16(ac[2 * np + 1], quh, kh[2], kh[3]);
      mma_bf16(ac[2 * np + 0], quh, kl[0], kl[1]);
      mma_bf16(ac[2 * np + 1], quh, kl[2], kl[3]);
      mma_bf16(ac[2 * np + 0], qul, kh[0], kh[1]);
      mma_bf16(ac[2 * np + 1], qul, kh[2], kh[3]);
    }
#pragma unroll
    for (int np = 0; np < 6; np++) {
      const int rowB = wn * 96 + np * 16 + rbB;
      const uint32_t boff = (uint32_t)(rowB * 128) + ((kba + kadd_b) ^ xa);
      uint32_t ph[4], pl[4];
      ldm4(ph[0], ph[1], ph[2], ph[3], sb + SC_PH + boff);
      ldm4(pl[0], pl[1], pl[2], pl[3], sb + SC_PL + boff);
      mma_bf16(bd[2 * np + 0], qvh, ph[0], ph[1]);
      mma_bf16(bd[2 * np + 1], qvh, ph[2], ph[3]);
      mma_bf16(bd[2 * np + 0], qvh, pl[0], pl[1]);
      mma_bf16(bd[2 * np + 1], qvh, pl[2], pl[3]);
      mma_bf16(bd[2 * np + 0], qvl, ph[0], ph[1]);
      mma_bf16(bd[2 * np + 1], qvl, ph[2], ph[3]);
    }
  }
  __syncthreads();  // operand smem dead; safe to alias with BDs/STATS

  // ---- BD -> smem (stride 196 floats)
  const int r0w = wm * 16 + (lane >> 2);
#pragma unroll
  for (int nt = 0; nt < 12; nt++) {
    const int col = wn * 96 + nt * 8 + (lane & 3) * 2;
    *(float2*)&BDs[r0w * SC_BDW + col] = make_float2(bd[nt][0], bd[nt][1]);
    *(float2*)&BDs[(r0w + 8) * SC_BDW + col] = make_float2(bd[nt][2], bd[nt][3]);
  }
  __syncthreads();

  // ---- epilogue: out = (AC + shifted BD) / 8 ; per-row partial (max, sumexp)
  float* wbase = wout + ((size_t)bh * TSEQ + t0) * TSEQ + s0;
#pragma unroll
  for (int half = 0; half < 2; half++) {
    const int row = r0w + half * 8;
    float v[16];
    float mx = -1e30f;
#pragma unroll
    for (int nt = 0; nt < 8; nt++) {
      const int col = wn * 64 + nt * 8 + (lane & 3) * 2;
      const int bdi = row * SC_BDW + col - row + 63;
      v[2 * nt + 0] = (ac[nt][half * 2 + 0] + BDs[bdi]) * 0.125f;
      v[2 * nt + 1] = (ac[nt][half * 2 + 1] + BDs[bdi + 1]) * 0.125f;
      *(float2*)(wbase + (size_t)row * TSEQ + col) =
          make_float2(v[2 * nt + 0], v[2 * nt + 1]);
      mx = fmaxf(mx, fmaxf(v[2 * nt + 0], v[2 * nt + 1]));
    }
    // quad reduce across the 4 lanes sharing this row
    mx = fmaxf(mx, __shfl_xor_sync(0xffffffffu, mx, 1));
    mx = fmaxf(mx, __shfl_xor_sync(0xffffffffu, mx, 2));
    float se = 0.f;
#pragma unroll
    for (int k = 0; k < 16; k++) se += __expf(v[k] - mx);
    se += __shfl_xor_sync(0xffffffffu, se, 1);
    se += __shfl_xor_sync(0xffffffffu, se, 2);
    if ((lane & 3) == 0) STATS[row * 2 + wn] = make_float2(mx, se);
  }
  __syncthreads();

  // merge 2 warp-halves per row, store to global stats
  if (tid < 64) {
    const float2 a = STATS[tid * 2 + 0];
    const float2 b = STATS[tid * 2 + 1];
    const float m = fmaxf(a.x, b.x);
    const float s = a.y * __expf(a.x - m) + b.y * __expf(b.x - m);
    g_stats[((size_t)bh * 4 + blockIdx.x) * TSEQ + t0 + tid] = make_float2(m, s);
  }
}

// ---------------------------------------------------------------------------
// Context GEMM + softmax finalize:
//   merge per-row stats, normalize raw scores on the fly (exp(v-m)/S),
//   write normalized weights (output), and ctx = W @ Vt via bf16x3 mma.
// W staging drained to registers early so both prefetches overlap convert+mma.
// ---------------------------------------------------------------------------
#define CT_WF 0        // 128 x 64 f32 staging (linear, 256B rows), 32KB
#define CT_WH 32768    // converted W hi (swizzled), 16KB
#define CT_WL 49152    // converted W lo, 16KB
#define CT_V  65536    // V buffers: +buf*16384; hi at +0 (8KB), lo at +8192
#define CT_MS 98304    // m[128], invS[128]
#define CT_SMEM 99328

__global__ void __launch_bounds__(256, 2) ctx_mma(
    float* __restrict__ wts, float* __restrict__ ctx) {
  extern __shared__ char smem[];
  const uint32_t sb = smem_u32(smem);
  const int tid = threadIdx.x;
  const int wid = tid >> 5, lane = tid & 31;
  const int t0 = blockIdx.x * 128;
  const int bh = blockIdx.y;
  const int b = bh >> 4, h = bh & 15;

  float* Wf = wts + ((size_t)bh * TSEQ + t0) * TSEQ;
  const __nv_bfloat16* Vh = g_Vth + (size_t)bh * DK * TSEQ;
  const __nv_bfloat16* Vl = g_Vtl + (size_t)bh * DK * TSEQ;
  float* MS = (float*)(smem + CT_MS);

  const int wm = wid & 3;
  const int wn = wid >> 2;
  const int l7 = lane & 7;
  const uint32_t xa = (uint32_t)(l7 << 4);
  const int rowA0 = wm * 32 + l7 + (((lane >> 3) & 1) << 3);
  const uint32_t kadd_a = (uint32_t)(((lane >> 4) & 1) << 4);
  const int rowB0 = wn * 32 + l7 + (((lane >> 4) & 1) << 3);
  const uint32_t kadd_b = (uint32_t)(((lane >> 3) & 1) << 4);

  const int wrow = tid >> 4;   // staging row group (8 rows per thread, +16 apart)
  const int wseg = tid & 15;

  float acc[2][4][4];
#pragma unroll
  for (int mt = 0; mt < 2; mt++)
#pragma unroll
    for (int nt = 0; nt < 4; nt++)
#pragma unroll
      for (int i = 0; i < 4; i++) acc[mt][nt][i] = 0.f;

  auto load_wf = [&](int kc) {
    const int k0 = kc * 64;
#pragma unroll
    for (int it = 0; it < 8; it++) {
      const int idx = tid + it * 256;
      const int row = idx >> 4, seg = idx & 15;
      cp16(sb + CT_WF + (uint32_t)(row * 256 + seg * 16),
           Wf + (size_t)row * TSEQ + k0 + seg * 4);
    }
  };
  auto load_v = [&](int kc, int buf) {
    const int k0 = kc * 64;
    const uint32_t vb = sb + CT_V + (uint32_t)(buf * 16384);
#pragma unroll
    for (int it = 0; it < 2; it++) {
      const int idx = tid + it * 256;
      const int row = idx >> 3, ch = idx & 7;
      const uint32_t sw = (uint32_t)(row * 128) + ((uint32_t)(ch * 16) ^ ((uint32_t)(row & 7) << 4));
      cp16(vb + sw, Vh + (size_t)row * TSEQ + k0 + ch * 8);
      cp16(vb + 8192 + sw, Vl + (size_t)row * TSEQ + k0 + ch * 8);
    }
  };

  load_wf(0);
  load_v(0, 0);
  cp_commit();

  // merge per-row softmax stats (4 s-tiles) -> m, 1/S
  if (tid < 128) {
    const int t = t0 + tid;
    const float2 p0 = g_stats[((size_t)bh * 4 + 0) * TSEQ + t];
    const float2 p1 = g_stats[((size_t)bh * 4 + 1) * TSEQ + t];
    const float2 p2 = g_stats[((size_t)bh * 4 + 2) * TSEQ + t];
    const float2 p3 = g_stats[((size_t)bh * 4 + 3) * TSEQ + t];
    const float m = fmaxf(fmaxf(p0.x, p1.x), fmaxf(p2.x, p3.x));
    const float S = p0.y * __expf(p0.x - m) + p1.y * __expf(p1.x - m) +
                    p2.y * __expf(p2.x - m) + p3.y * __expf(p3.x - m);
    MS[tid] = m;
    MS[128 + tid] = 1.0f / S;
  }

  for (int kc = 0; kc < 8; kc++) {
    asm volatile("cp.async.wait_group 0;" ::: "memory");
    __syncthreads();  // staging + V + stats visible; prev mma done with WH/WL

    // drain W staging into registers (short LDS), free CT_WF for prefetch
    float4 wreg[8];
#pragma unroll
    for (int it = 0; it < 8; it++) {
      const int r = wrow + it * 16;
      wreg[it] = *(const float4*)(smem + CT_WF + r * 256 + wseg * 16);
    }
    __syncthreads();  // all reads of CT_WF done

    // issue BOTH prefetches now — they overlap convert + mma below
    if (kc + 1 < 8) {
      load_wf(kc + 1);
      load_v(kc + 1, (kc + 1) & 1);
      cp_commit();
    }

    // normalize + convert W from regs -> bf16 hi/lo swizzled; write weights out
#pragma unroll
    for (int it = 0; it < 8; it++) {
      const int r = wrow + it * 16;
      float4 wv = wreg[it];
      const float mr = MS[r], is = MS[128 + r];
      wv.x = __expf(wv.x - mr) * is;
      wv.y = __expf(wv.y - mr) * is;
      wv.z = __expf(wv.z - mr) * is;
      wv.w = __expf(wv.w - mr) * is;
      *(float4*)(Wf + (size_t)r * TSEQ + kc * 64 + wseg * 4) = wv;
      const uint32_t sw = (uint32_t)(r * 128) + ((uint32_t)(wseg * 8) ^ ((uint32_t)(r & 7) << 4));
      uint2 hh, ll;
      hh.x = pack_bf2(wv.x, wv.y); hh.y = pack_bf2(wv.z, wv.w);
      ll.x = pack_bf2(bf_res(wv.x), bf_res(wv.y));
      ll.y = pack_bf2(bf_res(wv.z), bf_res(wv.w));
      *(uint2*)(smem + CT_WH + sw) = hh;
      *(uint2*)(smem + CT_WL + sw) = ll;
    }
    __syncthreads();

    const uint32_t vb = sb + CT_V + (uint32_t)((kc & 1) * 16384);
#pragma unroll
    for (int ks = 0; ks < 4; ks++) {
      const uint32_t kba = (uint32_t)(ks * 32);
      uint32_t ah[2][4], al[2][4];
#pragma unroll
      for (int mt = 0; mt < 2; mt++) {
        const uint32_t aoff = (uint32_t)((rowA0 + mt * 16) * 128) + ((kba + kadd_a) ^ xa);
        ldm4(ah[mt][0], ah[mt][1], ah[mt][2], ah[mt][3], sb + CT_WH + aoff);
        ldm4(al[mt][0], al[mt][1], al[mt][2], al[mt][3], sb + CT_WL + aoff);
      }
#pragma unroll
      for (int np = 0; np < 2; np++) {
        const uint32_t boff = (uint32_t)((rowB0 + np * 16) * 128) + ((kba + kadd_b) ^ xa);
        uint32_t vhh[4], vll[4];
        ldm4(vhh[0], vhh[1], vhh[2], vhh[3], vb + boff);
        ldm4(vll[0], vll[1], vll[2], vll[3], vb + 8192 + boff);
#pragma unroll
        for (int mt = 0; mt < 2; mt++) {
          mma_bf16(acc[mt][2 * np + 0], ah[mt], vhh[0], vhh[1]);
          mma_bf16(acc[mt][2 * np + 1], ah[mt], vhh[2], vhh[3]);
          mma_bf16(acc[mt][2 * np + 0], ah[mt], vll[0], vll[1]);
          mma_bf16(acc[mt][2 * np + 1], ah[mt], vll[2], vll[3]);
          mma_bf16(acc[mt][2 * np + 0], al[mt], vhh[0], vhh[1]);
          mma_bf16(acc[mt][2 * np + 1], al[mt], vhh[2], vhh[3]);
        }
      }
    }
  }

  const int mrow = t0 + wm * 32 + (lane >> 2);
#pragma unroll
  for (int mt = 0; mt < 2; mt++) {
#pragma unroll
    for (int half = 0; half < 2; half++) {
      const int t = mrow + mt * 16 + half * 8;
#pragma unroll
      for (int nt = 0; nt < 4; nt++) {
        const int d = wn * 32 + nt * 8 + (lane & 3) * 2;
        float2 o;
        o.x = acc[mt][nt][half * 2 + 0];
        o.y = acc[mt][nt][half * 2 + 1];
        *(float2*)(ctx + ((size_t)b * TSEQ + t) * DM + h * DK + d) = o;
      }
    }
  }
}

// ---------------------------------------------------------------------------
// Launch
// ---------------------------------------------------------------------------
extern "C" void kernel_launch(void* const* d_in, const int* in_sizes, int n_in,
                              void* d_out, int out_size) {
  const float* x     = (const float*)d_in[0];
  const float* pos   = (const float*)d_in[2];
  const float* qvk_w = (const float*)d_in[3];
  const float* qvk_b = (const float*)d_in[4];
  const float* pos_w = (const float*)d_in[5];
  const float* posu  = (const float*)d_in[6];
  const float* posv  = (const float*)d_in[7];

  float* ctx = (float*)d_out;
  float* wts = (float*)d_out + (size_t)BATCH * TSEQ * DM;

  // 0) merged prep (all bf16 hi/lo splits)
  prep_kernel<<<6400, 256>>>(x, qvk_w, pos, pos_w);

  // 1) merged projection GEMMs, tile 128x256 (QKV 768 + pos 32 tiles)
  cudaFuncSetAttribute(mma_gemm_all, cudaFuncAttributeMaxDynamicSharedMemorySize,
                       GSMEM);
  mma_gemm_all<<<800, 512, GSMEM>>>(qvk_b);

  // 2) scores (+ vtsplit + per-row partial softmax stats) -> weights region
  cudaFuncSetAttribute(scores_mma, cudaFuncAttributeMaxDynamicSharedMemorySize,
                       SC_SMEM);
  scores_mma<<<dim3(4, 8, 320), 256, SC_SMEM>>>(posu, posv, wts);

  // 3) context + softmax finalize (normalizes weights in place, writes output)
  cudaFuncSetAttribute(ctx_mma, cudaFuncAttributeMaxDynamicSharedMemorySize,
                       CT_SMEM);
  ctx_mma<<<dim3(TSEQ / 128, BATCH * NH), 256, CT_SMEM>>>(wts, ctx);
}

// round 16
// speedup vs baseline: 1.1174x; 1.0154x over previous
#include <cuda_runtime.h>
#include <cuda_bf16.h>
#include <cstdint>

#define BATCH 16
#define TSEQ 512
#define NH 16
#define DK 64
#define DM 1024
#define D3 3072
#define RR 1023  // 2T-1

// ---------------------------------------------------------------------------
// Scratch (allocation-free: device globals)
// ---------------------------------------------------------------------------
__device__ float g_Q[BATCH*NH*TSEQ*DK];
__device__ float g_V[BATCH*NH*TSEQ*DK];

// K and P stored directly as bf16 hi/lo (written by projection epilogues)
__device__ __nv_bfloat16 g_Kh[BATCH*NH*TSEQ*DK];
__device__ __nv_bfloat16 g_Kl[BATCH*NH*TSEQ*DK];
__device__ __nv_bfloat16 g_Ph[NH*RR*DK];
__device__ __nv_bfloat16 g_Pl[NH*RR*DK];

// bf16 hi/lo split operands for projection GEMMs
__device__ __nv_bfloat16 g_Ah[BATCH*TSEQ*DM];
__device__ __nv_bfloat16 g_Al[BATCH*TSEQ*DM];
__device__ __nv_bfloat16 g_Wh[D3*DM];      // qvk_w transposed: [3072][1024]
__device__ __nv_bfloat16 g_Wl[D3*DM];
__device__ __nv_bfloat16 g_pAh[1024*DM];   // pos padded to 1024 rows
__device__ __nv_bfloat16 g_pAl[1024*DM];
__device__ __nv_bfloat16 g_pWh[DM*DM];     // pos_w transposed
__device__ __nv_bfloat16 g_pWl[DM*DM];

// V^T bf16 hi/lo [bh][d][s]
__device__ __nv_bfloat16 g_Vth[(size_t)BATCH*NH*DK*TSEQ];
__device__ __nv_bfloat16 g_Vtl[(size_t)BATCH*NH*DK*TSEQ];

// per-(bh, s-tile, t-row) partial softmax stats: (rowmax, sumexp)
__device__ float2 g_stats[(size_t)BATCH*NH*4*TSEQ];

// ---------------------------------------------------------------------------
// helpers
// ---------------------------------------------------------------------------
__device__ __forceinline__ uint32_t smem_u32(const void* p) {
  uint32_t a;
  asm("{ .reg .u64 t; cvta.to.shared.u64 t, %1; cvt.u32.u64 %0, t; }" : "=r"(a) : "l"(p));
  return a;
}
__device__ __forceinline__ void cp16(uint32_t dst, const void* src) {
  asm volatile("cp.async.cg.shared.global [%0], [%1], 16;" :: "r"(dst), "l"(src));
}
__device__ __forceinline__ void cp16z(uint32_t dst, const void* src, int nbytes) {
  asm volatile("cp.async.cg.shared.global [%0], [%1], 16, %2;"
               :: "r"(dst), "l"(src), "r"(nbytes));
}
__device__ __forceinline__ void cp_commit() {
  asm volatile("cp.async.commit_group;" ::: "memory");
}
__device__ __forceinline__ void ldm4(uint32_t& r0, uint32_t& r1, uint32_t& r2,
                                     uint32_t& r3, uint32_t a) {
  asm volatile("ldmatrix.sync.aligned.m8n8.x4.shared.b16 {%0,%1,%2,%3}, [%4];"
               : "=r"(r0), "=r"(r1), "=r"(r2), "=r"(r3) : "r"(a));
}
__device__ __forceinline__ void mma_bf16(float* c, const uint32_t* a,
                                         uint32_t b0, uint32_t b1) {
  asm volatile(
      "mma.sync.aligned.m16n8k16.row.col.f32.bf16.bf16.f32 "
      "{%0,%1,%2,%3}, {%4,%5,%6,%7}, {%8,%9}, {%0,%1,%2,%3};"
      : "+f"(c[0]), "+f"(c[1]), "+f"(c[2]), "+f"(c[3])
      : "r"(a[0]), "r"(a[1]), "r"(a[2]), "r"(a[3]), "r"(b0), "r"(b1));
}
__device__ __forceinline__ uint32_t pack_bf2(float a, float b) {
  __nv_bfloat16 ha = __float2bfloat16(a), hb = __float2bfloat16(b);
  uint16_t ua = *(uint16_t*)&ha, ub = *(uint16_t*)&hb;
  return (uint32_t)ua | ((uint32_t)ub << 16);
}
__device__ __forceinline__ float bf_res(float v) {
  return v - __bfloat162float(__float2bfloat16(v));
}

// ---------------------------------------------------------------------------
// Merged prep: all 4 split/tsplit jobs in ONE launch.
// ---------------------------------------------------------------------------
__global__ void __launch_bounds__(256) prep_kernel(
    const float* __restrict__ x, const float* __restrict__ qvk_w,
    const float* __restrict__ pos, const float* __restrict__ pos_w) {
  __shared__ float t[32][33];
  const int bid = blockIdx.x;
  const int tid = threadIdx.x;
  if (bid < 2048) {  // split x
    const int n = BATCH * TSEQ * DM;
    for (int i = bid * 256 + tid; i < n; i += 2048 * 256) {
      float v = x[i];
      __nv_bfloat16 h = __float2bfloat16(v);
      g_Ah[i] = h;
      g_Al[i] = __float2bfloat16(v - __bfloat162float(h));
    }
  } else if (bid < 5120) {  // tsplit qvk_w: R=1024 C=3072
    const int r = bid - 2048;
    const int c0 = (r % 96) * 32, r0 = (r / 96) * 32;
    const int tx = tid & 31, ty = tid >> 5;
#pragma unroll
    for (int i = 0; i < 4; i++)
      t[ty + i * 8][tx] = qvk_w[(size_t)(r0 + ty + i * 8) * D3 + c0 + tx];
    __syncthreads();
#pragma unroll
    for (int i = 0; i < 4; i++) {
      float v = t[tx][ty + i * 8];
      __nv_bfloat16 h = __float2bfloat16(v);
      size_t o = (size_t)(c0 + ty + i * 8) * DM + r0 + tx;
      g_Wh[o] = h;
      g_Wl[o] = __float2bfloat16(v - __bfloat162float(h));
    }
  } else if (bid < 5376) {  // split pos (pad to 1024 rows)
    const int r = bid - 5120;
    const int n = RR * DM, ntot = 1024 * DM;
    for (int i = r * 256 + tid; i < ntot; i += 256 * 256) {
      float v = (i < n) ? pos[i] : 0.f;
      __nv_bfloat16 h = __float2bfloat16(v);
      g_pAh[i] = h;
      g_pAl[i] = __float2bfloat16(v - __bfloat162float(h));
    }
  } else {  // tsplit pos_w: R=1024 C=1024
    const int r = bid - 5376;
    const int c0 = (r % 32) * 32, r0 = (r / 32) * 32;
    const int tx = tid & 31, ty = tid >> 5;
#pragma unroll
    for (int i = 0; i < 4; i++)
      t[ty + i * 8][tx] = pos_w[(size_t)(r0 + ty + i * 8) * DM + c0 + tx];
    __syncthreads();
#pragma unroll
    for (int i = 0; i < 4; i++) {
      float v = t[tx][ty + i * 8];
      __nv_bfloat16 h = __float2bfloat16(v);
      size_t o = (size_t)(c0 + ty + i * 8) * DM + r0 + tx;
      g_pWh[o] = h;
      g_pWl[o] = __float2bfloat16(v - __bfloat162float(h));
    }
  }
}

// ---------------------------------------------------------------------------
// Merged projection GEMMs (QKV + pos), tile 128x256, 512 threads (16 warps).
// ---------------------------------------------------------------------------
#define PBUF 98304
#define OFF_AH 0
#define OFF_AL 16384
#define OFF_BH 32768
#define OFF_BL 65536
#define GSMEM (2 * PBUF)  // 196608

__global__ void __launch_bounds__(512, 1) mma_gemm_all(const float* __restrict__ bias) {
  extern __shared__ char smem[];
  const uint32_t sb = smem_u32(smem);
  const int tid = threadIdx.x;
  const int wid = tid >> 5, lane = tid & 31;
  const int bid = blockIdx.x;
  const bool qkv = bid < 768;
  int n0, m0;
  const __nv_bfloat16 *Ah, *Al, *Bh, *Bl;
  if (qkv) {
    n0 = (bid % 12) * 256; m0 = (bid / 12) * 128;
    Ah = g_Ah; Al = g_Al; Bh = g_Wh; Bl = g_Wl;
  } else {
    const int r = bid - 768;
    n0 = (r % 4) * 256; m0 = (r / 4) * 128;
    Ah = g_pAh; Al = g_pAl; Bh = g_pWh; Bl = g_pWl;
  }
  const int wm = wid & 3;
  const int wn = wid >> 2;

  const int gr = tid >> 3;
  const int gc = tid & 7;
  const uint32_t gsw = (uint32_t)((gc * 16) ^ ((gr & 7) << 4));

  const int l7 = lane & 7;
  const uint32_t xa = (uint32_t)(l7 << 4);
  const int rowA0 = wm * 32 + l7 + (((lane >> 3) & 1) << 3);
  const uint32_t kadd_a = (uint32_t)(((lane >> 4) & 1) << 4);
  const int rowB0 = wn * 64 + l7 + (((lane >> 4) & 1) << 3);
  const uint32_t kadd_b = (uint32_t)(((lane >> 3) & 1) << 4);

  float acc[2][8][4];
#pragma unroll
  for (int mt = 0; mt < 2; mt++)
#pragma unroll
    for (int nt = 0; nt < 8; nt++)
#pragma unroll
      for (int i = 0; i < 4; i++) acc[mt][nt][i] = 0.f;

  auto load_chunk = [&](int kc, int buf) {
    const int k0 = kc * 64;
    const uint32_t base = sb + buf * PBUF;
#pragma unroll
    for (int it = 0; it < 2; it++) {
      const int r = gr + it * 64;
      const uint32_t sw = (uint32_t)(r * 128) + gsw;
      const size_t asrc = (size_t)(m0 + r) * DM + k0 + gc * 8;
      cp16(base + OFF_AH + sw, Ah + asrc);
      cp16(base + OFF_AL + sw, Al + asrc);
    }
#pragma unroll
    for (int it = 0; it < 4; it++) {
      const int r = gr + it * 64;
      const uint32_t sw = (uint32_t)(r * 128) + gsw;
      const size_t bsrc = (size_t)(n0 + r) * DM + k0 + gc * 8;
      cp16(base + OFF_BH + sw, Bh + bsrc);
      cp16(base + OFF_BL + sw, Bl + bsrc);
    }
    cp_commit();
  };

  load_chunk(0, 0);

  for (int kc = 0; kc < 16; kc++) {
    if (kc + 1 < 16) {
      load_chunk(kc + 1, (kc + 1) & 1);
      asm volatile("cp.async.wait_group 1;" ::: "memory");
    } else {
      asm volatile("cp.async.wait_group 0;" ::: "memory");
    }
    __syncthreads();

    const uint32_t bb = sb + (kc & 1) * PBUF;
#pragma unroll
    for (int ks = 0; ks < 4; ks++) {
      const uint32_t kba = (uint32_t)(ks * 32);
      uint32_t ah[2][4], al[2][4];
#pragma unroll
      for (int mt = 0; mt < 2; mt++) {
        const uint32_t aoff = (uint32_t)((rowA0 + mt * 16) * 128) + ((kba + kadd_a) ^ xa);
        ldm4(ah[mt][0], ah[mt][1], ah[mt][2], ah[mt][3], bb + OFF_AH + aoff);
        ldm4(al[mt][0], al[mt][1], al[mt][2], al[mt][3], bb + OFF_AL + aoff);
      }
#pragma unroll
      for (int np = 0; np < 4; np++) {
        const uint32_t boff = (uint32_t)((rowB0 + np * 16) * 128) + ((kba + kadd_b) ^ xa);
        uint32_t bh[4], bl[4];
        ldm4(bh[0], bh[1], bh[2], bh[3], bb + OFF_BH + boff);
        ldm4(bl[0], bl[1], bl[2], bl[3], bb + OFF_BL + boff);
#pragma unroll
        for (int mt = 0; mt < 2; mt++) {
          mma_bf16(acc[mt][2 * np + 0], ah[mt], bh[0], bh[1]);
          mma_bf16(acc[mt][2 * np + 1], ah[mt], bh[2], bh[3]);
          mma_bf16(acc[mt][2 * np + 0], ah[mt], bl[0], bl[1]);
          mma_bf16(acc[mt][2 * np + 1], ah[mt], bl[2], bl[3]);
          mma_bf16(acc[mt][2 * np + 0], al[mt], bh[0], bh[1]);
          mma_bf16(acc[mt][2 * np + 1], al[mt], bh[2], bh[3]);
        }
      }
    }
    __syncthreads();
  }

  const int mrow = m0 + wm * 32 + (lane >> 2);
#pragma unroll
  for (int mt = 0; mt < 2; mt++) {
#pragma unroll
    for (int half = 0; half < 2; half++) {
      const int m = mrow + mt * 16 + half * 8;
#pragma unroll
      for (int nt = 0; nt < 8; nt++) {
        const int n = n0 + wn * 64 + nt * 8 + (lane & 3) * 2;
        float2 o;
        o.x = acc[mt][nt][half * 2 + 0];
        o.y = acc[mt][nt][half * 2 + 1];
        if (qkv) {
          o.x += bias[n];
          o.y += bias[n + 1];
          const int b = m >> 9, t = m & 511;
          const int sec = n >> 10;
          const int h = (n >> 6) & 15;
          const int d = n & 63;
          const size_t idx = ((size_t)(b * NH + h) * TSEQ + t) * DK + d;
          if (sec == 0) {
            *(float2*)(g_Q + idx) = o;
          } else if (sec == 1) {
            *(uint32_t*)&g_Kh[idx] = pack_bf2(o.x, o.y);
            *(uint32_t*)&g_Kl[idx] = pack_bf2(bf_res(o.x), bf_res(o.y));
          } else {
            *(float2*)(g_V + idx) = o;
          }
        } else {
          if (m < RR) {
            const int h = n >> 6;
            const int d = n & 63;
            const size_t idx = ((size_t)h * RR + m) * DK + d;
            *(uint32_t*)&g_Ph[idx] = pack_bf2(o.x, o.y);
            *(uint32_t*)&g_Pl[idx] = pack_bf2(bf_res(o.x), bf_res(o.y));
          }
        }
      }
    }
  }
}

// ---------------------------------------------------------------------------
// Scores (+ merged vtsplit tail): grid (4, 8, 320).
// Also emits per-(row, s-tile) partial softmax stats (max, sumexp).
// ---------------------------------------------------------------------------
#define SC_QUH 0
#define SC_QUL 8192
#define SC_QVH 16384
#define SC_QVL 24576
#define SC_KH  32768
#define SC_KL  49152
#define SC_PH  65536
#define SC_PL  90112
#define SC_SMEM 114688
#define SC_BDW 196
#define SC_STATS 53248  // after BDs (64*196*4 = 50176); within operand alias zone

__global__ void __launch_bounds__(256, 2) scores_mma(
    const float* __restrict__ pu, const float* __restrict__ pv,
    float* __restrict__ wout) {
  extern __shared__ char smem[];
  const uint32_t sb = smem_u32(smem);
  const int tid = threadIdx.x;

  if (blockIdx.z >= 256) {
    // ---- vtsplit job
    float (*t)[65] = (float(*)[65])smem;
    const int job = (blockIdx.z - 256) * 32 + blockIdx.y * 4 + blockIdx.x;
    const int vbh = job >> 3;
    const int vs0 = (job & 7) * 64;
    const float* vbase = g_V + (size_t)vbh * TSEQ * DK;
    for (int i = tid; i < 4096; i += 256) {
      const int sl = i >> 6, d = i & 63;
      t[sl][d] = vbase[(size_t)(vs0 + sl) * DK + d];
    }
    __syncthreads();
    for (int i = tid; i < 2048; i += 256) {
      const int d = i >> 5, sl = (i & 31) * 2;
      const float v0 = t[sl][d], v1 = t[sl + 1][d];
      const size_t o = ((size_t)vbh * DK + d) * TSEQ + vs0 + sl;
      *(uint32_t*)&g_Vth[o] = pack_bf2(v0, v1);
      *(uint32_t*)&g_Vtl[o] = pack_bf2(bf_res(v0), bf_res(v1));
    }
    return;
  }

  float* BDs = (float*)smem;                     // aliased after mma phase
  float2* STATS = (float2*)(smem + SC_STATS);    // [64 rows][2 wn]
  const int wid = tid >> 5, lane = tid & 31;
  const int s0 = blockIdx.x * 128;
  const int t0 = blockIdx.y * 64;
  const int bh = blockIdx.z, h = bh & 15;
  const int relbase = s0 - t0 + 448;

  // ---- cp.async K tiles (128 rows x 128B, hi+lo)
  {
    const __nv_bfloat16* Kh = g_Kh + ((size_t)bh * TSEQ + s0) * DK;
    const __nv_bfloat16* Kl = g_Kl + ((size_t)bh * TSEQ + s0) * DK;
#pragma unroll
    for (int it = 0; it < 4; it++) {
      const int idx = tid + it * 256;
      const int row = idx >> 3, ch = idx & 7;
      const uint32_t sw = (uint32_t)(row * 128) + ((uint32_t)(ch * 16) ^ ((uint32_t)(row & 7) << 4));
      cp16(sb + SC_KH + sw, Kh + row * DK + ch * 8);
      cp16(sb + SC_KL + sw, Kl + row * DK + ch * 8);
    }
  }
  // ---- cp.async P band (192 rows x 128B, hi+lo), zero-fill out of range
  {
    const __nv_bfloat16* Ph = g_Ph + (size_t)h * RR * DK;
    const __nv_bfloat16* Pl = g_Pl + (size_t)h * RR * DK;
#pragma unroll
    for (int it = 0; it < 6; it++) {
      const int idx = tid + it * 256;
      const int row = idx >> 3, ch = idx & 7;
      const int r = relbase + row;
      const int rc = r < 0 ? 0 : (r >= RR ? RR - 1 : r);
      const int ok = (r >= 0 && r < RR) ? 16 : 0;
      const uint32_t sw = (uint32_t)(row * 128) + ((uint32_t)(ch * 16) ^ ((uint32_t)(row & 7) << 4));
      cp16z(sb + SC_PH + sw, Ph + (size_t)rc * DK + ch * 8, ok);
      cp16z(sb + SC_PL + sw, Pl + (size_t)rc * DK + ch * 8, ok);
    }
  }
  cp_commit();

  // ---- Q fill: fp32 + posu/posv, convert to bf16 hi/lo (overlaps cp.async)
  {
    const int frow = tid >> 4;
    const int c4 = (tid & 15) * 4;
    const uint32_t cb = (uint32_t)(c4 * 2);
    const float4 pu4 = *(const float4*)(pu + h * 64 + c4);
    const float4 pv4 = *(const float4*)(pv + h * 64 + c4);
    const float* qb = g_Q + ((size_t)bh * TSEQ + t0) * DK;
#pragma unroll
    for (int it = 0; it < 4; it++) {
      const int row = frow + it * 16;
      const float4 q = *(const float4*)(qb + (size_t)row * DK + c4);
      const uint32_t sw = (uint32_t)(row * 128) + (cb ^ ((uint32_t)(row & 7) << 4));
      float ux = q.x + pu4.x, uy = q.y + pu4.y, uz = q.z + pu4.z, uw = q.w + pu4.w;
      float vx = q.x + pv4.x, vy = q.y + pv4.y, vz = q.z + pv4.z, vw = q.w + pv4.w;
      uint2 hh, ll;
      hh.x = pack_bf2(ux, uy); hh.y = pack_bf2(uz, uw);
      ll.x = pack_bf2(bf_res(ux), bf_res(uy));
      ll.y = pack_bf2(bf_res(uz), bf_res(uw));
      *(uint2*)(smem + SC_QUH + sw) = hh;
      *(uint2*)(smem + SC_QUL + sw) = ll;
      hh.x = pack_bf2(vx, vy); hh.y = pack_bf2(vz, vw);
      ll.x = pack_bf2(bf_res(vx), bf_res(vy));
      ll.y = pack_bf2(bf_res(vz), bf_res(vw));
      *(uint2*)(smem + SC_QVH + sw) = hh;
      *(uint2*)(smem + SC_QVL + sw) = ll;
    }
  }
  asm volatile("cp.async.wait_group 0;" ::: "memory");
  __syncthreads();

  // ---- mma: 8 warps = 4 (t) x 2 (s/band)
  const int wm = wid & 3;
  const int wn = wid >> 2;
  const int l7 = lane & 7;
  const uint32_t xa = (uint32_t)(l7 << 4);
  const int rowA = wm * 16 + l7 + (((lane >> 3) & 1) << 3);
  const uint32_t kadd_a = (uint32_t)(((lane >> 4) & 1) << 4);
  const int rbB = l7 + (((lane >> 4) & 1) << 3);
  const uint32_t kadd_b = (uint32_t)(((lane >> 3) & 1) << 4);

  float ac[8][4], bd[12][4];
#pragma unroll
  for (int nt = 0; nt < 8; nt++)
#pragma unroll
    for (int i = 0; i < 4; i++) ac[nt][i] = 0.f;
#pragma unroll
  for (int nt = 0; nt < 12; nt++)
#pragma unroll
    for (int i = 0; i < 4; i++) bd[nt][i] = 0.f;

#pragma unroll
  for (int ks = 0; ks < 4; ks++) {
    const uint32_t kba = (uint32_t)(ks * 32);
    const uint32_t aoff = (uint32_t)(rowA * 128) + ((kba + kadd_a) ^ xa);
    uint32_t quh[4], qul[4], qvh[4], qvl[4];
    ldm4(quh[0], quh[1], quh[2], quh[3], sb + SC_QUH + aoff);
    ldm4(qul[0], qul[1], qul[2], qul[3], sb + SC_QUL + aoff);
    ldm4(qvh[0], qvh[1], qvh[2], qvh[3], sb + SC_QVH + aoff);
    ldm4(qvl[0], qvl[1], qvl[2], qvl[3], sb + SC_QVL + aoff);
#pragma unroll
    for (int np = 0; np < 4; np++) {
      const int rowB = wn * 64 + np * 16 + rbB;
      const uint32_t boff = (uint32_t)(rowB * 128) + ((kba + kadd_b) ^ xa);
      uint32_t kh[4], kl[4];
      ldm4(kh[0], kh[1], kh[2], kh[3], sb + SC_KH + boff);
      ldm4(kl[0], kl[1], kl[2], kl[3], sb + SC_KL + boff);
      mma_bf16(ac[2 * np + 0], quh, kh[0], kh[1]);
      mma_bf16(ac[2 * np + 1], quh, kh[2], kh[3]);
      mma_bf16(ac[2 * np + 0], quh, kl[0], kl[1]);
      mma_bf16(ac[2 * np + 1], quh, kl[2], kl[3]);
      mma_bf16(ac[2 * np + 0], qul, kh[0], kh[1]);
      mma_bf16(ac[2 * np + 1], qul, kh[2], kh[3]);
    }
#pragma unroll
    for (int np = 0; np < 6; np++) {
      const int rowB = wn * 96 + np * 16 + rbB;
      const uint32_t boff = (uint32_t)(rowB * 128) + ((kba + kadd_b) ^ xa);
      uint32_t ph[4], pl[4];
      ldm4(ph[0], ph[1], ph[2], ph[3], sb + SC_PH + boff);
      ldm4(pl[0], pl[1], pl[2], pl[3], sb + SC_PL + boff);
      mma_bf16(bd[2 * np + 0], qvh, ph[0], ph[1]);
      mma_bf16(bd[2 * np + 1], qvh, ph[2], ph[3]);
      mma_bf16(bd[2 * np + 0], qvh, pl[0], pl[1]);
      mma_bf16(bd[2 * np + 1], qvh, pl[2], pl[3]);
      mma_bf16(bd[2 * np + 0], qvl, ph[0], ph[1]);
      mma_bf16(bd[2 * np + 1], qvl, ph[2], ph[3]);
    }
  }
  __syncthreads();  // operand smem dead; safe to alias with BDs/STATS

  // ---- BD -> smem (stride 196 floats)
  const int r0w = wm * 16 + (lane >> 2);
#pragma unroll
  for (int nt = 0; nt < 12; nt++) {
    const int col = wn * 96 + nt * 8 + (lane & 3) * 2;
    *(float2*)&BDs[r0w * SC_BDW + col] = make_float2(bd[nt][0], bd[nt][1]);
    *(float2*)&BDs[(r0w + 8) * SC_BDW + col] = make_float2(bd[nt][2], bd[nt][3]);
  }
  __syncthreads();

  // ---- epilogue: out = (AC + shifted BD) / 8 ; per-row partial (max, sumexp)
  float* wbase = wout + ((size_t)bh * TSEQ + t0) * TSEQ + s0;
#pragma unroll
  for (int half = 0; half < 2; half++) {
    const int row = r0w + half * 8;
    float v[16];
    float mx = -1e30f;
#pragma unroll
    for (int nt = 0; nt < 8; nt++) {
      const int col = wn * 64 + nt * 8 + (lane & 3) * 2;
      const int bdi = row * SC_BDW + col - row + 63;
      v[2 * nt + 0] = (ac[nt][half * 2 + 0] + BDs[bdi]) * 0.125f;
      v[2 * nt + 1] = (ac[nt][half * 2 + 1] + BDs[bdi + 1]) * 0.125f;
      *(float2*)(wbase + (size_t)row * TSEQ + col) =
          make_float2(v[2 * nt + 0], v[2 * nt + 1]);
      mx = fmaxf(mx, fmaxf(v[2 * nt + 0], v[2 * nt + 1]));
    }
    // quad reduce across the 4 lanes sharing this row
    mx = fmaxf(mx, __shfl_xor_sync(0xffffffffu, mx, 1));
    mx = fmaxf(mx, __shfl_xor_sync(0xffffffffu, mx, 2));
    float se = 0.f;
#pragma unroll
    for (int k = 0; k < 16; k++) se += __expf(v[k] - mx);
    se += __shfl_xor_sync(0xffffffffu, se, 1);
    se += __shfl_xor_sync(0xffffffffu, se, 2);
    if ((lane & 3) == 0) STATS[row * 2 + wn] = make_float2(mx, se);
  }
  __syncthreads();

  // merge 2 warp-halves per row, store to global stats
  if (tid < 64) {
    const float2 a = STATS[tid * 2 + 0];
    const float2 b = STATS[tid * 2 + 1];
    const float m = fmaxf(a.x, b.x);
    const float s = a.y * __expf(a.x - m) + b.y * __expf(b.x - m);
    g_stats[((size_t)bh * 4 + blockIdx.x) * TSEQ + t0 + tid] = make_float2(m, s);
  }
}

// ---------------------------------------------------------------------------
// Context GEMM + softmax finalize, t-tile 64 (3 CTAs/SM):
//   merge per-row stats, normalize raw scores on the fly (exp(v-m)/S),
//   write normalized weights (output), and ctx = W @ Vt via bf16x3 mma.
// ---------------------------------------------------------------------------
#define CT_WF 0        // 64 x 64 f32 staging (linear, 256B rows), 16KB
#define CT_WH 16384    // converted W hi (swizzled), 8KB
#define CT_WL 24576    // converted W lo, 8KB
#define CT_V  32768    // V buffers: +buf*16384; hi at +0 (8KB), lo at +8192
#define CT_MS 65536    // m[64], invS[64]
#define CT_SMEM 66048

__global__ void __launch_bounds__(256, 3) ctx_mma(
    float* __restrict__ wts, float* __restrict__ ctx) {
  extern __shared__ char smem[];
  const uint32_t sb = smem_u32(smem);
  const int tid = threadIdx.x;
  const int wid = tid >> 5, lane = tid & 31;
  const int t0 = blockIdx.x * 64;
  const int bh = blockIdx.y;
  const int b = bh >> 4, h = bh & 15;

  float* Wf = wts + ((size_t)bh * TSEQ + t0) * TSEQ;
  const __nv_bfloat16* Vh = g_Vth + (size_t)bh * DK * TSEQ;
  const __nv_bfloat16* Vl = g_Vtl + (size_t)bh * DK * TSEQ;
  float* MS = (float*)(smem + CT_MS);

  const int wm = wid & 1;   // 32 t-rows each
  const int wn = wid >> 1;  // 16 d-cols each (0..3)
  const int l7 = lane & 7;
  const uint32_t xa = (uint32_t)(l7 << 4);
  const int rowA0 = wm * 32 + l7 + (((lane >> 3) & 1) << 3);
  const uint32_t kadd_a = (uint32_t)(((lane >> 4) & 1) << 4);
  const int rowB0 = wn * 16 + l7 + (((lane >> 4) & 1) << 3);
  const uint32_t kadd_b = (uint32_t)(((lane >> 3) & 1) << 4);

  const int wrow = tid >> 4;   // staging row group (4 rows per thread, +16 apart)
  const int wseg = tid & 15;

  float acc[2][2][4];
#pragma unroll
  for (int mt = 0; mt < 2; mt++)
#pragma unroll
    for (int nt = 0; nt < 2; nt++)
#pragma unroll
      for (int i = 0; i < 4; i++) acc[mt][nt][i] = 0.f;

  auto load_wf = [&](int kc) {
    const int k0 = kc * 64;
#pragma unroll
    for (int it = 0; it < 4; it++) {
      const int idx = tid + it * 256;
      const int row = idx >> 4, seg = idx & 15;
      cp16(sb + CT_WF + (uint32_t)(row * 256 + seg * 16),
           Wf + (size_t)row * TSEQ + k0 + seg * 4);
    }
  };
  auto load_v = [&](int kc, int buf) {
    const int k0 = kc * 64;
    const uint32_t vb = sb + CT_V + (uint32_t)(buf * 16384);
#pragma unroll
    for (int it = 0; it < 2; it++) {
      const int idx = tid + it * 256;
      const int row = idx >> 3, ch = idx & 7;
      const uint32_t sw = (uint32_t)(row * 128) + ((uint32_t)(ch * 16) ^ ((uint32_t)(row & 7) << 4));
      cp16(vb + sw, Vh + (size_t)row * TSEQ + k0 + ch * 8);
      cp16(vb + 8192 + sw, Vl + (size_t)row * TSEQ + k0 + ch * 8);
    }
  };

  load_wf(0);
  load_v(0, 0);
  cp_commit();

  // merge per-row softmax stats (4 s-tiles) -> m, 1/S
  if (tid < 64) {
    const int t = t0 + tid;
    const float2 p0 = g_stats[((size_t)bh * 4 + 0) * TSEQ + t];
    const float2 p1 = g_stats[((size_t)bh * 4 + 1) * TSEQ + t];
    const float2 p2 = g_stats[((size_t)bh * 4 + 2) * TSEQ + t];
    const float2 p3 = g_stats[((size_t)bh * 4 + 3) * TSEQ + t];
    const float m = fmaxf(fmaxf(p0.x, p1.x), fmaxf(p2.x, p3.x));
    const float S = p0.y * __expf(p0.x - m) + p1.y * __expf(p1.x - m) +
                    p2.y * __expf(p2.x - m) + p3.y * __expf(p3.x - m);
    MS[tid] = m;
    MS[64 + tid] = 1.0f / S;
  }

  for (int kc = 0; kc < 8; kc++) {
    asm volatile("cp.async.wait_group 0;" ::: "memory");
    __syncthreads();  // staging + V + stats visible; prev mma done with WH/WL

    // drain W staging into registers (short LDS), free CT_WF for prefetch
    float4 wreg[4];
#pragma unroll
    for (int it = 0; it < 4; it++) {
      const int r = wrow + it * 16;
      wreg[it] = *(const float4*)(smem + CT_WF + r * 256 + wseg * 16);
    }
    __syncthreads();  // all reads of CT_WF done

    // issue BOTH prefetches now — they overlap convert + mma below
    if (kc + 1 < 8) {
      load_wf(kc + 1);
      load_v(kc + 1, (kc + 1) & 1);
      cp_commit();
    }

    // normalize + convert W from regs -> bf16 hi/lo swizzled; write weights out
#pragma unroll
    for (int it = 0; it < 4; it++) {
      const int r = wrow + it * 16;
      float4 wv = wreg[it];
      const float mr = MS[r], is = MS[64 + r];
      wv.x = __expf(wv.x - mr) * is;
      wv.y = __expf(wv.y - mr) * is;
      wv.z = __expf(wv.z - mr) * is;
      wv.w = __expf(wv.w - mr) * is;
      *(float4*)(Wf + (size_t)r * TSEQ + kc * 64 + wseg * 4) = wv;
      const uint32_t sw = (uint32_t)(r * 128) + ((uint32_t)(wseg * 8) ^ ((uint32_t)(r & 7) << 4));
      uint2 hh, ll;
      hh.x = pack_bf2(wv.x, wv.y); hh.y = pack_bf2(wv.z, wv.w);
      ll.x = pack_bf2(bf_res(wv.x), bf_res(wv.y));
      ll.y = pack_bf2(bf_res(wv.z), bf_res(wv.w));
      *(uint2*)(smem + CT_WH + sw) = hh;
      *(uint2*)(smem + CT_WL + sw) = ll;
    }
    __syncthreads();

    const uint32_t vb = sb + CT_V + (uint32_t)((kc & 1) * 16384);
#pragma unroll
    for (int ks = 0; ks < 4; ks++) {
      const uint32_t kba = (uint32_t)(ks * 32);
      uint32_t ah[2][4], al[2][4];
#pragma unroll
      for (int mt = 0; mt < 2; mt++) {
        const uint32_t aoff = (uint32_t)((rowA0 + mt * 16) * 128) + ((kba + kadd_a) ^ xa);
        ldm4(ah[mt][0], ah[mt][1], ah[mt][2], ah[mt][3], sb + CT_WH + aoff);
        ldm4(al[mt][0], al[mt][1], al[mt][2], al[mt][3], sb + CT_WL + aoff);
      }
      const uint32_t boff = (uint32_t)(rowB0 * 128) + ((kba + kadd_b) ^ xa);
      uint32_t vhh[4], vll[4];
      ldm4(vhh[0], vhh[1], vhh[2], vhh[3], vb + boff);
      ldm4(vll[0], vll[1], vll[2], vll[3], vb + 8192 + boff);
#pragma unroll
      for (int mt = 0; mt < 2; mt++) {
        mma_bf16(acc[mt][0], ah[mt], vhh[0], vhh[1]);
        mma_bf16(acc[mt][1], ah[mt], vhh[2], vhh[3]);
        mma_bf16(acc[mt][0], ah[mt], vll[0], vll[1]);
        mma_bf16(acc[mt][1], ah[mt], vll[2], vll[3]);
        mma_bf16(acc[mt][0], al[mt], vhh[0], vhh[1]);
        mma_bf16(acc[mt][1], al[mt], vhh[2], vhh[3]);
      }
    }
  }

  const int mrow = t0 + wm * 32 + (lane >> 2);
#pragma unroll
  for (int mt = 0; mt < 2; mt++) {
#pragma unroll
    for (int half = 0; half < 2; half++) {
      const int t = mrow + mt * 16 + half * 8;
#pragma unroll
      for (int nt = 0; nt < 2; nt++) {
        const int d = wn * 16 + nt * 8 + (lane & 3) * 2;
        float2 o;
        o.x = acc[mt][nt][half * 2 + 0];
        o.y = acc[mt][nt][half * 2 + 1];
        *(float2*)(ctx + ((size_t)b * TSEQ + t) * DM + h * DK + d) = o;
      }
    }
  }
}

// ---------------------------------------------------------------------------
// Launch
// ---------------------------------------------------------------------------
extern "C" void kernel_launch(void* const* d_in, const int* in_sizes, int n_in,
                              void* d_out, int out_size) {
  const float* x     = (const float*)d_in[0];
  const float* pos   = (const float*)d_in[2];
  const float* qvk_w = (const float*)d_in[3];
  const float* qvk_b = (const float*)d_in[4];
  const float* pos_w = (const float*)d_in[5];
  const float* posu  = (const float*)d_in[6];
  const float* posv  = (const float*)d_in[7];

  float* ctx = (float*)d_out;
  float* wts = (float*)d_out + (size_t)BATCH * TSEQ * DM;

  // 0) merged prep (all bf16 hi/lo splits)
  prep_kernel<<<6400, 256>>>(x, qvk_w, pos, pos_w);

  // 1) merged projection GEMMs, tile 128x256 (QKV 768 + pos 32 tiles)
  cudaFuncSetAttribute(mma_gemm_all, cudaFuncAttributeMaxDynamicSharedMemorySize,
                       GSMEM);
  mma_gemm_all<<<800, 512, GSMEM>>>(qvk_b);

  // 2) scores (+ vtsplit + per-row partial softmax stats) -> weights region
  cudaFuncSetAttribute(scores_mma, cudaFuncAttributeMaxDynamicSharedMemorySize,
                       SC_SMEM);
  scores_mma<<<dim3(4, 8, 320), 256, SC_SMEM>>>(posu, posv, wts);

  // 3) context + softmax finalize, t-tile 64, 3 CTAs/SM
  cudaFuncSetAttribute(ctx_mma, cudaFuncAttributeMaxDynamicSharedMemorySize,
                       CT_SMEM);
  ctx_mma<<<dim3(TSEQ / 64, BATCH * NH), 256, CT_SMEM>>>(wts, ctx);
}